// round 3
// baseline (speedup 1.0000x reference)
#include <cuda_runtime.h>
#include <cuda_bf16.h>

// BiaffineAttention  B=16, S=512, H=1024, A=500 (padded to 512)
//   Th   = ReLU(X @ w1h_p^T + b1h)            [8192,512]
//   Td   = ReLU(X @ w1d_p^T + b1d)            [8192,512]
//   head = Th @ w2h_p^T + b2h                 [8192,512]
//   W'   = Wb_p @ w2d   (folded bilinear)     [512,512]
//   b'   = Wb_p @ b2d                          [512]
//   depW = Td @ W'^T + b'                      [8192,512]
//   out[b,i,j] = head[b,i,:] . depW[b,j,:] + bb  [16,512,512]
// Zero-padded weights keep all padding cols exactly 0 -> guard-free GEMMs.
// Mainloop uses packed fma.rn.f32x2 (2 fp32 FMAs / instr, bit-exact).

#define BM 128
#define BN 128
#define BK 8

#define ROWS_ 8192
#define LDP_  512

#define OFF_TH    (0LL)
#define OFF_TD    (OFF_TH   + (long long)ROWS_ * LDP_)
#define OFF_HEAD  (OFF_TD   + (long long)ROWS_ * LDP_)
#define OFF_DEPW  (OFF_HEAD + (long long)ROWS_ * LDP_)
#define OFF_W1H   (OFF_DEPW + (long long)ROWS_ * LDP_)
#define OFF_W1D   (OFF_W1H  + 512LL * 1024)
#define OFF_W2H   (OFF_W1D  + 512LL * 1024)
#define OFF_WB    (OFF_W2H  + 512LL * 512)
#define OFF_W2DT  (OFF_WB   + 512LL * 512)
#define OFF_WPRIME (OFF_W2DT + 512LL * 512)
#define OFF_BIASD (OFF_WPRIME + 512LL * 512)
#define SCRATCH_TOTAL (OFF_BIASD + 512)

__device__ float g_scratch[SCRATCH_TOTAL];

// ---------------- helpers: packed f32x2 FMA ----------------
__device__ __forceinline__ double dupf(float x) {
    double d;
    asm("mov.b64 %0, {%1, %1};" : "=d"(d) : "f"(x));
    return d;
}
__device__ __forceinline__ void fma2(double& acc, double a, double b) {
    asm("fma.rn.f32x2 %0, %1, %2, %0;" : "+d"(acc) : "d"(a), "d"(b));
}
__device__ __forceinline__ void unpack2(double d, float& lo, float& hi) {
    asm("mov.b64 {%0, %1}, %2;" : "=f"(lo), "=f"(hi) : "d"(d));
}

// ---------------- pad / pad-transpose ----------------
__global__ void pad_copy(const float* __restrict__ src, float* __restrict__ dst,
                         int R, int C, int Rp, int Cp)
{
    int idx = blockIdx.x * blockDim.x + threadIdx.x;
    if (idx >= Rp * Cp) return;
    int r = idx / Cp, c = idx - r * Cp;
    dst[idx] = (r < R && c < C) ? src[r * C + c] : 0.0f;
}
// dst[r,c] = src[c,r]  (src is [R,C], dst is [Cp,Rp] with zero pad)
__global__ void pad_copy_t(const float* __restrict__ src, float* __restrict__ dst,
                           int R, int C, int Rp, int Cp)
{
    int idx = blockIdx.x * blockDim.x + threadIdx.x;
    if (idx >= Cp * Rp) return;
    int r = idx / Rp, c = idx - r * Rp;   // dst coords: r in [0,Cp), c in [0,Rp)
    dst[idx] = (r < C && c < R) ? src[c * C + r] : 0.0f;
}

// bias' = Wp @ v   (Wp [512,512] zero-padded, v has nv valid entries)
__global__ void matvec512(const float* __restrict__ Wp, const float* __restrict__ v,
                          float* __restrict__ out, int nv)
{
    __shared__ float red[4];
    const int j = blockIdx.x;
    const int tid = threadIdx.x;          // 128 threads
    float s = 0.0f;
    for (int a = tid; a < nv; a += 128) s += Wp[j * 512 + a] * v[a];
#pragma unroll
    for (int o = 16; o > 0; o >>= 1) s += __shfl_down_sync(0xffffffffu, s, o);
    if ((tid & 31) == 0) red[tid >> 5] = s;
    __syncthreads();
    if (tid == 0) out[j] = red[0] + red[1] + red[2] + red[3];
}

// ---------------- NT GEMM, guard-free, f32x2 mainloop ----------------
// C[M,N] = A[M,K] @ B[N,K]^T (+bias)(+relu); M%128==0, N%128==0, K%8==0.
__global__ __launch_bounds__(256) void gemm128(
    const float* __restrict__ A, int lda, long long sA,
    const float* __restrict__ B, int ldb, long long sB,
    float* __restrict__ C, int ldc, long long sC,
    int K,
    const float* __restrict__ bias, int biasMode, int Nbias, int doRelu)
{
    __shared__ float As[2][BK][BM];
    __shared__ float Bs[2][BK][BN];

    const float* Ab = A + (long long)blockIdx.z * sA;
    const float* Bb = B + (long long)blockIdx.z * sB;
    float*       Cb = C + (long long)blockIdx.z * sC;

    const int tid  = threadIdx.x;
    const int row0 = blockIdx.y * BM;
    const int col0 = blockIdx.x * BN;

    const int lr = tid >> 1;
    const int lk = (tid & 1) * 4;

    const float* aPtr = Ab + (long long)(row0 + lr) * lda + lk;
    const float* bPtr = Bb + (long long)(col0 + lr) * ldb + lk;

    const int tx = tid & 15;
    const int ty = tid >> 4;
    const int mB = ty * 8;
    const int nB = tx * 8;

    double acc[8][4];
#pragma unroll
    for (int i = 0; i < 8; i++)
#pragma unroll
        for (int p = 0; p < 4; p++) acc[i][p] = 0.0;

    const int ntiles = K / BK;

    float4 aReg = *(const float4*)aPtr;
    float4 bReg = *(const float4*)bPtr;
    As[0][lk + 0][lr] = aReg.x; As[0][lk + 1][lr] = aReg.y;
    As[0][lk + 2][lr] = aReg.z; As[0][lk + 3][lr] = aReg.w;
    Bs[0][lk + 0][lr] = bReg.x; Bs[0][lk + 1][lr] = bReg.y;
    Bs[0][lk + 2][lr] = bReg.z; Bs[0][lk + 3][lr] = bReg.w;
    __syncthreads();

    for (int t = 0; t < ntiles; ++t) {
        const int buf = t & 1;

        if (t + 1 < ntiles) {
            aReg = *(const float4*)(aPtr + (t + 1) * BK);
            bReg = *(const float4*)(bPtr + (t + 1) * BK);
        }

#pragma unroll
        for (int kk = 0; kk < BK; ++kk) {
            float4 a0 = *(const float4*)&As[buf][kk][mB];
            float4 a1 = *(const float4*)&As[buf][kk][mB + 4];
            double2 bq0 = *(const double2*)&Bs[buf][kk][nB];
            double2 bq1 = *(const double2*)&Bs[buf][kk][nB + 4];
            double bp0 = bq0.x, bp1 = bq0.y, bp2 = bq1.x, bp3 = bq1.y;
            float a[8] = {a0.x, a0.y, a0.z, a0.w, a1.x, a1.y, a1.z, a1.w};
#pragma unroll
            for (int i = 0; i < 8; i++) {
                double ad = dupf(a[i]);
                fma2(acc[i][0], ad, bp0);
                fma2(acc[i][1], ad, bp1);
                fma2(acc[i][2], ad, bp2);
                fma2(acc[i][3], ad, bp3);
            }
        }

        if (t + 1 < ntiles) {
            const int nb = buf ^ 1;
            As[nb][lk + 0][lr] = aReg.x; As[nb][lk + 1][lr] = aReg.y;
            As[nb][lk + 2][lr] = aReg.z; As[nb][lk + 3][lr] = aReg.w;
            Bs[nb][lk + 0][lr] = bReg.x; Bs[nb][lk + 1][lr] = bReg.y;
            Bs[nb][lk + 2][lr] = bReg.z; Bs[nb][lk + 3][lr] = bReg.w;
            __syncthreads();
        }
    }

    // ---- epilogue ----
    float bv[8];
#pragma unroll
    for (int j = 0; j < 8; j++) {
        const int c = col0 + nB + j;
        bv[j] = 0.0f;
        if (biasMode == 1 && c < Nbias) bv[j] = bias[c];
        else if (biasMode == 2)         bv[j] = bias[0];
    }

#pragma unroll
    for (int i = 0; i < 8; i++) {
        const long long r = row0 + mB + i;
        float v[8];
#pragma unroll
        for (int p = 0; p < 4; p++) unpack2(acc[i][p], v[2 * p], v[2 * p + 1]);
#pragma unroll
        for (int j = 0; j < 8; j++) {
            float x = v[j] + bv[j];
            v[j] = doRelu ? fmaxf(x, 0.0f) : x;
        }
        *(float4*)&Cb[r * ldc + col0 + nB]     = make_float4(v[0], v[1], v[2], v[3]);
        *(float4*)&Cb[r * ldc + col0 + nB + 4] = make_float4(v[4], v[5], v[6], v[7]);
    }
}

extern "C" void kernel_launch(void* const* d_in, const int* in_sizes, int n_in,
                              void* d_out, int out_size)
{
    const float* X   = (const float*)d_in[0];
    const float* w1h = (const float*)d_in[1];
    const float* b1h = (const float*)d_in[2];
    const float* w2h = (const float*)d_in[3];
    const float* b2h = (const float*)d_in[4];
    const float* w1d = (const float*)d_in[5];
    const float* b1d = (const float*)d_in[6];
    const float* w2d = (const float*)d_in[7];
    const float* b2d = (const float*)d_in[8];
    const float* Wb  = (const float*)d_in[9];
    const float* bb  = (const float*)d_in[10];
    float* out = (float*)d_out;

    float* s = nullptr;
    cudaGetSymbolAddress((void**)&s, g_scratch);
    float* Th     = s + OFF_TH;
    float* Td     = s + OFF_TD;
    float* head   = s + OFF_HEAD;
    float* depW   = s + OFF_DEPW;
    float* w1h_p  = s + OFF_W1H;
    float* w1d_p  = s + OFF_W1D;
    float* w2h_p  = s + OFF_W2H;
    float* Wb_p   = s + OFF_WB;
    float* w2dT_p = s + OFF_W2DT;
    float* Wprime = s + OFF_WPRIME;
    float* biasd  = s + OFF_BIASD;

    // ---- pad weights ----
    {
        int t1 = 512 * 1024, t2 = 512 * 512;
        pad_copy<<<(t1 + 255) / 256, 256>>>(w1h, w1h_p, 500, 1024, 512, 1024);
        pad_copy<<<(t1 + 255) / 256, 256>>>(w1d, w1d_p, 500, 1024, 512, 1024);
        pad_copy<<<(t2 + 255) / 256, 256>>>(w2h, w2h_p, 500, 500, 512, 512);
        pad_copy<<<(t2 + 255) / 256, 256>>>(Wb,  Wb_p,  500, 500, 512, 512);
        // w2dT_p[k,a] = w2d[a,k]
        pad_copy_t<<<(t2 + 255) / 256, 256>>>(w2d, w2dT_p, 500, 500, 512, 512);
    }

    dim3 blk(256);

    // W' = Wb_p @ w2d  :  C[j,k] = sum_a Wb_p[j,a] * w2dT_p[k,a]
    dim3 gw(512 / BN, 512 / BM, 1);
    gemm128<<<gw, blk>>>(Wb_p, 512, 0, w2dT_p, 512, 0, Wprime, 512, 0,
                         512, nullptr, 0, 0, 0);
    // b' = Wb_p @ b2d
    matvec512<<<512, 128>>>(Wb_p, b2d, biasd, 500);

    dim3 g1(512 / BN, ROWS_ / BM, 1);
    // stage 1 (K=1024)
    gemm128<<<g1, blk>>>(X, 1024, 0, w1h_p, 1024, 0, Th, LDP_, 0, 1024, b1h, 1, 500, 1);
    gemm128<<<g1, blk>>>(X, 1024, 0, w1d_p, 1024, 0, Td, LDP_, 0, 1024, b1d, 1, 500, 1);

    // head = Th @ w2h_p^T + b2h ; depW = Td @ W'^T + b'
    gemm128<<<g1, blk>>>(Th, LDP_, 0, w2h_p, 512, 0, head, LDP_, 0, 512, b2h, 1, 500, 0);
    gemm128<<<g1, blk>>>(Td, LDP_, 0, Wprime, 512, 0, depW, LDP_, 0, 512, biasd, 1, 512, 0);

    // final batched: out[b] = head[b] @ depW[b]^T + bb
    dim3 gf(512 / BN, 512 / BM, 16);
    const long long sAB = 512LL * LDP_;
    const long long sC  = 512LL * 512LL;
    gemm128<<<gf, blk>>>(head, LDP_, sAB, depW, LDP_, sAB, out, 512, sC,
                         512, bb, 2, 0, 0);
}

// round 4
// speedup vs baseline: 1.0022x; 1.0022x over previous
#include <cuda_runtime.h>
#include <cuda_bf16.h>

// BiaffineAttention  B=16, S=512, H=1024, A=500 (padded to 512)
//   Th   = ReLU(X @ w1h_p^T + b1h)            [8192,512]
//   Td   = ReLU(X @ w1d_p^T + b1d)            [8192,512]
//   head = Th @ w2h_p^T + b2h                 [8192,512]
//   W'   = Wb_p @ w2d   (folded bilinear)     [512,512]
//   b'   = Wb_p @ b2d                          [512]
//   depW = Td @ W'^T + b'                      [8192,512]
//   out[b,i,j] = head[b,i,:] . depW[b,j,:] + bb  [16,512,512]
// Zero-padded weights keep all padding cols exactly 0 -> guard-free GEMMs.
// Mainloop uses packed fma.rn.f32x2 (2 fp32 FMAs / instr, bit-exact).

#define BM 128
#define BN 128
#define BK 8

#define ROWS_ 8192
#define LDP_  512

#define OFF_TH    (0LL)
#define OFF_TD    (OFF_TH   + (long long)ROWS_ * LDP_)
#define OFF_HEAD  (OFF_TD   + (long long)ROWS_ * LDP_)
#define OFF_DEPW  (OFF_HEAD + (long long)ROWS_ * LDP_)
#define OFF_W1H   (OFF_DEPW + (long long)ROWS_ * LDP_)
#define OFF_W1D   (OFF_W1H  + 512LL * 1024)
#define OFF_W2H   (OFF_W1D  + 512LL * 1024)
#define OFF_WB    (OFF_W2H  + 512LL * 512)
#define OFF_W2DT  (OFF_WB   + 512LL * 512)
#define OFF_WPRIME (OFF_W2DT + 512LL * 512)
#define OFF_BIASD (OFF_WPRIME + 512LL * 512)
#define SCRATCH_TOTAL (OFF_BIASD + 512)

__device__ float g_scratch[SCRATCH_TOTAL];

// ---------------- helpers: packed f32x2 FMA ----------------
__device__ __forceinline__ double dupf(float x) {
    double d;
    asm("mov.b64 %0, {%1, %1};" : "=d"(d) : "f"(x));
    return d;
}
__device__ __forceinline__ void fma2(double& acc, double a, double b) {
    asm("fma.rn.f32x2 %0, %1, %2, %0;" : "+d"(acc) : "d"(a), "d"(b));
}
__device__ __forceinline__ void unpack2(double d, float& lo, float& hi) {
    asm("mov.b64 {%0, %1}, %2;" : "=f"(lo), "=f"(hi) : "d"(d));
}

// ---------------- pad / pad-transpose ----------------
__global__ void pad_copy(const float* __restrict__ src, float* __restrict__ dst,
                         int R, int C, int Rp, int Cp)
{
    int idx = blockIdx.x * blockDim.x + threadIdx.x;
    if (idx >= Rp * Cp) return;
    int r = idx / Cp, c = idx - r * Cp;
    dst[idx] = (r < R && c < C) ? src[r * C + c] : 0.0f;
}
// dst[r,c] = src[c,r]  (src is [R,C], dst is [Cp,Rp] with zero pad)
__global__ void pad_copy_t(const float* __restrict__ src, float* __restrict__ dst,
                           int R, int C, int Rp, int Cp)
{
    int idx = blockIdx.x * blockDim.x + threadIdx.x;
    if (idx >= Cp * Rp) return;
    int r = idx / Rp, c = idx - r * Rp;   // dst coords: r in [0,Cp), c in [0,Rp)
    dst[idx] = (r < C && c < R) ? src[c * C + r] : 0.0f;
}

// bias' = Wp @ v   (Wp [512,512] zero-padded, v has nv valid entries)
__global__ void matvec512(const float* __restrict__ Wp, const float* __restrict__ v,
                          float* __restrict__ out, int nv)
{
    __shared__ float red[4];
    const int j = blockIdx.x;
    const int tid = threadIdx.x;          // 128 threads
    float s = 0.0f;
    for (int a = tid; a < nv; a += 128) s += Wp[j * 512 + a] * v[a];
#pragma unroll
    for (int o = 16; o > 0; o >>= 1) s += __shfl_down_sync(0xffffffffu, s, o);
    if ((tid & 31) == 0) red[tid >> 5] = s;
    __syncthreads();
    if (tid == 0) out[j] = red[0] + red[1] + red[2] + red[3];
}

// ---------------- NT GEMM, guard-free, f32x2 mainloop ----------------
// C[M,N] = A[M,K] @ B[N,K]^T (+bias)(+relu); M%128==0, N%128==0, K%8==0.
__global__ __launch_bounds__(256) void gemm128(
    const float* __restrict__ A, int lda, long long sA,
    const float* __restrict__ B, int ldb, long long sB,
    float* __restrict__ C, int ldc, long long sC,
    int K,
    const float* __restrict__ bias, int biasMode, int Nbias, int doRelu)
{
    __shared__ float As[2][BK][BM];
    __shared__ float Bs[2][BK][BN];

    const float* Ab = A + (long long)blockIdx.z * sA;
    const float* Bb = B + (long long)blockIdx.z * sB;
    float*       Cb = C + (long long)blockIdx.z * sC;

    const int tid  = threadIdx.x;
    const int row0 = blockIdx.y * BM;
    const int col0 = blockIdx.x * BN;

    const int lr = tid >> 1;
    const int lk = (tid & 1) * 4;

    const float* aPtr = Ab + (long long)(row0 + lr) * lda + lk;
    const float* bPtr = Bb + (long long)(col0 + lr) * ldb + lk;

    const int tx = tid & 15;
    const int ty = tid >> 4;
    const int mB = ty * 8;
    const int nB = tx * 8;

    double acc[8][4];
#pragma unroll
    for (int i = 0; i < 8; i++)
#pragma unroll
        for (int p = 0; p < 4; p++) acc[i][p] = 0.0;

    const int ntiles = K / BK;

    float4 aReg = *(const float4*)aPtr;
    float4 bReg = *(const float4*)bPtr;
    As[0][lk + 0][lr] = aReg.x; As[0][lk + 1][lr] = aReg.y;
    As[0][lk + 2][lr] = aReg.z; As[0][lk + 3][lr] = aReg.w;
    Bs[0][lk + 0][lr] = bReg.x; Bs[0][lk + 1][lr] = bReg.y;
    Bs[0][lk + 2][lr] = bReg.z; Bs[0][lk + 3][lr] = bReg.w;
    __syncthreads();

    for (int t = 0; t < ntiles; ++t) {
        const int buf = t & 1;

        if (t + 1 < ntiles) {
            aReg = *(const float4*)(aPtr + (t + 1) * BK);
            bReg = *(const float4*)(bPtr + (t + 1) * BK);
        }

#pragma unroll
        for (int kk = 0; kk < BK; ++kk) {
            float4 a0 = *(const float4*)&As[buf][kk][mB];
            float4 a1 = *(const float4*)&As[buf][kk][mB + 4];
            double2 bq0 = *(const double2*)&Bs[buf][kk][nB];
            double2 bq1 = *(const double2*)&Bs[buf][kk][nB + 4];
            double bp0 = bq0.x, bp1 = bq0.y, bp2 = bq1.x, bp3 = bq1.y;
            float a[8] = {a0.x, a0.y, a0.z, a0.w, a1.x, a1.y, a1.z, a1.w};
#pragma unroll
            for (int i = 0; i < 8; i++) {
                double ad = dupf(a[i]);
                fma2(acc[i][0], ad, bp0);
                fma2(acc[i][1], ad, bp1);
                fma2(acc[i][2], ad, bp2);
                fma2(acc[i][3], ad, bp3);
            }
        }

        if (t + 1 < ntiles) {
            const int nb = buf ^ 1;
            As[nb][lk + 0][lr] = aReg.x; As[nb][lk + 1][lr] = aReg.y;
            As[nb][lk + 2][lr] = aReg.z; As[nb][lk + 3][lr] = aReg.w;
            Bs[nb][lk + 0][lr] = bReg.x; Bs[nb][lk + 1][lr] = bReg.y;
            Bs[nb][lk + 2][lr] = bReg.z; Bs[nb][lk + 3][lr] = bReg.w;
            __syncthreads();
        }
    }

    // ---- epilogue ----
    float bv[8];
#pragma unroll
    for (int j = 0; j < 8; j++) {
        const int c = col0 + nB + j;
        bv[j] = 0.0f;
        if (biasMode == 1 && c < Nbias) bv[j] = bias[c];
        else if (biasMode == 2)         bv[j] = bias[0];
    }

#pragma unroll
    for (int i = 0; i < 8; i++) {
        const long long r = row0 + mB + i;
        float v[8];
#pragma unroll
        for (int p = 0; p < 4; p++) unpack2(acc[i][p], v[2 * p], v[2 * p + 1]);
#pragma unroll
        for (int j = 0; j < 8; j++) {
            float x = v[j] + bv[j];
            v[j] = doRelu ? fmaxf(x, 0.0f) : x;
        }
        *(float4*)&Cb[r * ldc + col0 + nB]     = make_float4(v[0], v[1], v[2], v[3]);
        *(float4*)&Cb[r * ldc + col0 + nB + 4] = make_float4(v[4], v[5], v[6], v[7]);
    }
}

extern "C" void kernel_launch(void* const* d_in, const int* in_sizes, int n_in,
                              void* d_out, int out_size)
{
    const float* X   = (const float*)d_in[0];
    const float* w1h = (const float*)d_in[1];
    const float* b1h = (const float*)d_in[2];
    const float* w2h = (const float*)d_in[3];
    const float* b2h = (const float*)d_in[4];
    const float* w1d = (const float*)d_in[5];
    const float* b1d = (const float*)d_in[6];
    const float* w2d = (const float*)d_in[7];
    const float* b2d = (const float*)d_in[8];
    const float* Wb  = (const float*)d_in[9];
    const float* bb  = (const float*)d_in[10];
    float* out = (float*)d_out;

    float* s = nullptr;
    cudaGetSymbolAddress((void**)&s, g_scratch);
    float* Th     = s + OFF_TH;
    float* Td     = s + OFF_TD;
    float* head   = s + OFF_HEAD;
    float* depW   = s + OFF_DEPW;
    float* w1h_p  = s + OFF_W1H;
    float* w1d_p  = s + OFF_W1D;
    float* w2h_p  = s + OFF_W2H;
    float* Wb_p   = s + OFF_WB;
    float* w2dT_p = s + OFF_W2DT;
    float* Wprime = s + OFF_WPRIME;
    float* biasd  = s + OFF_BIASD;

    // ---- pad weights ----
    {
        int t1 = 512 * 1024, t2 = 512 * 512;
        pad_copy<<<(t1 + 255) / 256, 256>>>(w1h, w1h_p, 500, 1024, 512, 1024);
        pad_copy<<<(t1 + 255) / 256, 256>>>(w1d, w1d_p, 500, 1024, 512, 1024);
        pad_copy<<<(t2 + 255) / 256, 256>>>(w2h, w2h_p, 500, 500, 512, 512);
        pad_copy<<<(t2 + 255) / 256, 256>>>(Wb,  Wb_p,  500, 500, 512, 512);
        // w2dT_p[k,a] = w2d[a,k]
        pad_copy_t<<<(t2 + 255) / 256, 256>>>(w2d, w2dT_p, 500, 500, 512, 512);
    }

    dim3 blk(256);

    // W' = Wb_p @ w2d  :  C[j,k] = sum_a Wb_p[j,a] * w2dT_p[k,a]
    dim3 gw(512 / BN, 512 / BM, 1);
    gemm128<<<gw, blk>>>(Wb_p, 512, 0, w2dT_p, 512, 0, Wprime, 512, 0,
                         512, nullptr, 0, 0, 0);
    // b' = Wb_p @ b2d
    matvec512<<<512, 128>>>(Wb_p, b2d, biasd, 500);

    dim3 g1(512 / BN, ROWS_ / BM, 1);
    // stage 1 (K=1024)
    gemm128<<<g1, blk>>>(X, 1024, 0, w1h_p, 1024, 0, Th, LDP_, 0, 1024, b1h, 1, 500, 1);
    gemm128<<<g1, blk>>>(X, 1024, 0, w1d_p, 1024, 0, Td, LDP_, 0, 1024, b1d, 1, 500, 1);

    // head = Th @ w2h_p^T + b2h ; depW = Td @ W'^T + b'
    gemm128<<<g1, blk>>>(Th, LDP_, 0, w2h_p, 512, 0, head, LDP_, 0, 512, b2h, 1, 500, 0);
    gemm128<<<g1, blk>>>(Td, LDP_, 0, Wprime, 512, 0, depW, LDP_, 0, 512, biasd, 1, 512, 0);

    // final batched: out[b] = head[b] @ depW[b]^T + bb
    dim3 gf(512 / BN, 512 / BM, 16);
    const long long sAB = 512LL * LDP_;
    const long long sC  = 512LL * 512LL;
    gemm128<<<gf, blk>>>(head, LDP_, sAB, depW, LDP_, sAB, out, 512, sC,
                         512, bb, 2, 0, 0);
}

// round 6
// speedup vs baseline: 2.0024x; 1.9981x over previous
#include <cuda_runtime.h>
#include <cuda_bf16.h>
#include <cstdint>

// BiaffineAttention  B=16, S=512, H=1024, A=500 (padded to 512)
// All GEMMs via warp-level mma.sync bf16 (m16n8k16) with 3-pass split precision:
//   x = hi + lo (bf16);  A@B^T ~= Ahi@Bhi^T + Ahi@Blo^T + Alo@Bhi^T (fp32 accum)
// Pipeline:
//   Th   = ReLU(X @ w1h^T + b1h)   -> split bf16
//   Td   = ReLU(X @ w1d^T + b1d)   -> split bf16
//   W'   = Wb @ w2d                -> split bf16 (bilinear fold kills one big GEMM)
//   b'   = Wb @ b2d
//   head = Th @ w2h^T + b2h        -> split bf16
//   depW = Td @ W'^T + b'          -> split bf16
//   out[b] = head[b] @ depW[b]^T + bb  (fp32)

// ============================ PTX helpers ============================
__device__ __forceinline__ uint32_t smem_u32(const void* p) {
    uint32_t a;
    asm("{ .reg .u64 t; cvta.to.shared.u64 t, %1; cvt.u32.u64 %0, t; }"
        : "=r"(a) : "l"(p));
    return a;
}

__device__ __forceinline__ void ldsm4(uint32_t* r, uint32_t addr) {
    asm volatile("ldmatrix.sync.aligned.m8n8.x4.shared.b16 {%0,%1,%2,%3}, [%4];"
        : "=r"(r[0]), "=r"(r[1]), "=r"(r[2]), "=r"(r[3]) : "r"(addr));
}

__device__ __forceinline__ void mma_bf16(float* c, const uint32_t* a,
                                         uint32_t b0, uint32_t b1) {
    asm volatile("mma.sync.aligned.m16n8k16.row.col.f32.bf16.bf16.f32 "
        "{%0,%1,%2,%3}, {%4,%5,%6,%7}, {%8,%9}, {%0,%1,%2,%3};"
        : "+f"(c[0]), "+f"(c[1]), "+f"(c[2]), "+f"(c[3])
        : "r"(a[0]), "r"(a[1]), "r"(a[2]), "r"(a[3]), "r"(b0), "r"(b1));
}

#define CP16(s, g) \
    asm volatile("cp.async.cg.shared.global [%0], [%1], 16;" :: "r"(s), "l"(g))
#define CP_COMMIT() asm volatile("cp.async.commit_group;" ::: "memory")
#define CP_WAIT0()  asm volatile("cp.async.wait_group 0;" ::: "memory")
#define CP_WAIT1()  asm volatile("cp.async.wait_group 1;" ::: "memory")

// ============================ scratch ============================
static constexpr long long EL_X   = 8192LL * 1024;
static constexpr long long EL_W1  = 512LL * 1024;
static constexpr long long EL_S   = 512LL * 512;
static constexpr long long EL_ACT = 8192LL * 512;

static constexpr long long O_XHI    = 0;
static constexpr long long O_XLO    = O_XHI + EL_X;
static constexpr long long O_W1H_HI = O_XLO + EL_X;
static constexpr long long O_W1H_LO = O_W1H_HI + EL_W1;
static constexpr long long O_W1D_HI = O_W1H_LO + EL_W1;
static constexpr long long O_W1D_LO = O_W1D_HI + EL_W1;
static constexpr long long O_W2H_HI = O_W1D_LO + EL_W1;
static constexpr long long O_W2H_LO = O_W2H_HI + EL_S;
static constexpr long long O_WB_HI  = O_W2H_LO + EL_S;
static constexpr long long O_WB_LO  = O_WB_HI + EL_S;
static constexpr long long O_W2DT_HI= O_WB_LO + EL_S;
static constexpr long long O_W2DT_LO= O_W2DT_HI + EL_S;
static constexpr long long O_WP_HI  = O_W2DT_LO + EL_S;
static constexpr long long O_WP_LO  = O_WP_HI + EL_S;
static constexpr long long O_TH_HI  = O_WP_LO + EL_S;
static constexpr long long O_TH_LO  = O_TH_HI + EL_ACT;
static constexpr long long O_TD_HI  = O_TH_LO + EL_ACT;
static constexpr long long O_TD_LO  = O_TD_HI + EL_ACT;
static constexpr long long O_HD_HI  = O_TD_LO + EL_ACT;
static constexpr long long O_HD_LO  = O_HD_HI + EL_ACT;
static constexpr long long O_DW_HI  = O_HD_LO + EL_ACT;
static constexpr long long O_DW_LO  = O_DW_HI + EL_ACT;
static constexpr long long BF_TOTAL = O_DW_LO + EL_ACT;

__device__ __align__(1024) __nv_bfloat16 g_bf[BF_TOTAL];
__device__ __align__(1024) float g_vec[4 * 512];

// ============================ small kernels ============================
__global__ void pad_split(const float* __restrict__ src,
                          __nv_bfloat16* __restrict__ hi, __nv_bfloat16* __restrict__ lo,
                          int R, int C, int Rp, int Cp, int transpose)
{
    long long idx = (long long)blockIdx.x * blockDim.x + threadIdx.x;
    if (idx >= (long long)Rp * Cp) return;
    int r = (int)(idx / Cp), c = (int)(idx - (long long)r * Cp);
    float v = 0.0f;
    if (!transpose) { if (r < R && c < C) v = src[(long long)r * C + c]; }
    else            { if (r < C && c < R) v = src[(long long)c * C + r]; }
    __nv_bfloat16 h = __float2bfloat16(v);
    hi[idx] = h;
    lo[idx] = __float2bfloat16(v - __bfloat162float(h));
}

__global__ void pad_vec(const float* __restrict__ src, float* __restrict__ dst, int n, int np)
{
    int i = blockIdx.x * blockDim.x + threadIdx.x;
    if (i < np) dst[i] = (i < n) ? src[i] : 0.0f;
}

__global__ void matvec_bp(const float* __restrict__ Wb, const float* __restrict__ v,
                          float* __restrict__ out)
{
    __shared__ float red[4];
    const int j = blockIdx.x;
    const int tid = threadIdx.x;
    float s = 0.0f;
    if (j < 500)
        for (int a = tid; a < 500; a += 128) s += Wb[j * 500 + a] * v[a];
#pragma unroll
    for (int o = 16; o > 0; o >>= 1) s += __shfl_down_sync(0xffffffffu, s, o);
    if ((tid & 31) == 0) red[tid >> 5] = s;
    __syncthreads();
    if (tid == 0) out[j] = (j < 500) ? (red[0] + red[1] + red[2] + red[3]) : 0.0f;
}

// ============================ main GEMM ============================
// C[M,N] = A[M,K] @ B[N,K]^T via 3-pass bf16 split, fp32 accum.
// CTA 128x128, 8 warps (4 M x 2 N), warp tile 32x64, BK=32 bf16.
// Requires M%128==0, N%128==0, K%32==0.
// smem row stride: 40 bf16 (80B) -> conflict-free ldmatrix.
#define SROW 40
#define TILEB (128 * SROW * 2)       // 10240 B per matrix tile
#define OFF_AH 0
#define OFF_AL (1 * TILEB)
#define OFF_BH (2 * TILEB)
#define OFF_BL (3 * TILEB)
#define STAGE  (4 * TILEB)           // 40960
#define SMEMSZ (2 * STAGE)           // 81920

__device__ __forceinline__ void issue_tile(
    uint32_t sbase, const char* Ah, const char* Al, const char* Bh, const char* Bl,
    int lda, int ldb, int row0, int col0, int k0, int tid)
{
#pragma unroll
    for (int i = 0; i < 2; i++) {
        const int pos = tid + i * 256;            // 0..511
        const int r = pos >> 2, ch = pos & 3;
        const uint32_t so = (uint32_t)(r * (SROW * 2) + ch * 16);
        const size_t gA = ((size_t)(row0 + r) * lda + k0 + ch * 8) * 2;
        const size_t gB = ((size_t)(col0 + r) * ldb + k0 + ch * 8) * 2;
        CP16(sbase + OFF_AH + so, Ah + gA);
        CP16(sbase + OFF_AL + so, Al + gA);
        CP16(sbase + OFF_BH + so, Bh + gB);
        CP16(sbase + OFF_BL + so, Bl + gB);
    }
}

__global__ void __launch_bounds__(256, 1) gemm_mma3(
    const __nv_bfloat16* __restrict__ Ahi, const __nv_bfloat16* __restrict__ Alo,
    int lda, long long sA,
    const __nv_bfloat16* __restrict__ Bhi, const __nv_bfloat16* __restrict__ Blo,
    int ldb, long long sB,
    void* __restrict__ Cout, void* __restrict__ Cout2,
    int ldc, long long sC,
    int K, const float* __restrict__ bias, int biasMode, int doRelu, int splitOut)
{
    extern __shared__ char smem[];
    const uint32_t sb = smem_u32(smem);
    const int tid  = threadIdx.x;
    const int lane = tid & 31;
    const int wid  = tid >> 5;
    const int wm   = wid & 3;          // 0..3 -> m offset 32*wm
    const int wn   = wid >> 2;         // 0..1 -> n offset 64*wn
    const int row0 = blockIdx.y * 128;
    const int col0 = blockIdx.x * 128;

    const char* Ah = (const char*)(Ahi + (long long)blockIdx.z * sA);
    const char* Al = (const char*)(Alo + (long long)blockIdx.z * sA);
    const char* Bh = (const char*)(Bhi + (long long)blockIdx.z * sB);
    const char* Bl = (const char*)(Blo + (long long)blockIdx.z * sB);

    float acc[2][8][4];
#pragma unroll
    for (int mt = 0; mt < 2; mt++)
#pragma unroll
        for (int nt = 0; nt < 8; nt++)
#pragma unroll
            for (int q = 0; q < 4; q++) acc[mt][nt][q] = 0.0f;

    // ldmatrix per-thread row mapping (same for A and B tiles)
    const int frow = (lane & 7) | (((lane >> 3) & 1) << 3);  // row within 16
    const int fkc  = (lane >> 4) * 8;                        // 0 or 8 (bf16 col)

    const int T = K / 32;
    issue_tile(sb, Ah, Al, Bh, Bl, lda, ldb, row0, col0, 0, tid);
    CP_COMMIT();

    for (int t = 0; t < T; ++t) {
        if (t + 1 < T) {
            issue_tile(sb + ((t + 1) & 1) * STAGE, Ah, Al, Bh, Bl,
                       lda, ldb, row0, col0, (t + 1) * 32, tid);
            CP_COMMIT();
            CP_WAIT1();
        } else {
            CP_WAIT0();
        }
        __syncthreads();

        const uint32_t st = sb + (t & 1) * STAGE;
#pragma unroll
        for (int kh = 0; kh < 2; ++kh) {
            const int kb = kh * 16 + fkc;        // bf16 col within 32
            uint32_t ah[2][4], al[2][4], bh4[4][4], bl4[4][4];
#pragma unroll
            for (int mt = 0; mt < 2; mt++) {
                const uint32_t off = (uint32_t)(((wm * 32 + mt * 16 + frow) * SROW + kb) * 2);
                ldsm4(ah[mt], st + OFF_AH + off);
                ldsm4(al[mt], st + OFF_AL + off);
            }
#pragma unroll
            for (int bt = 0; bt < 4; bt++) {
                const uint32_t off = (uint32_t)(((wn * 64 + bt * 16 + frow) * SROW + kb) * 2);
                ldsm4(bh4[bt], st + OFF_BH + off);
                ldsm4(bl4[bt], st + OFF_BL + off);
            }
#pragma unroll
            for (int mt = 0; mt < 2; mt++)
#pragma unroll
                for (int nt = 0; nt < 8; nt++) {
                    const int bt = nt >> 1, p = nt & 1;
                    // pass1: hi*hi ; pass2: hi*lo ; pass3: lo*hi
                    mma_bf16(acc[mt][nt], ah[mt], bh4[bt][p], bh4[bt][p + 2]);
                    mma_bf16(acc[mt][nt], ah[mt], bl4[bt][p], bl4[bt][p + 2]);
                    mma_bf16(acc[mt][nt], al[mt], bh4[bt][p], bh4[bt][p + 2]);
                }
        }
        __syncthreads();
    }

    // ============================ epilogue ============================
    char* Cb  = (char*)Cout + (size_t)blockIdx.z * sC * (splitOut ? 2 : 4);
    char* Cb2 = splitOut ? ((char*)Cout2 + (size_t)blockIdx.z * sC * 2) : nullptr;

#pragma unroll
    for (int mt = 0; mt < 2; mt++) {
        const long long r0 = row0 + wm * 32 + mt * 16 + (lane >> 2);
#pragma unroll
        for (int nt = 0; nt < 8; nt++) {
            const int c0 = col0 + wn * 64 + nt * 8 + (lane & 3) * 2;
            float b0 = 0.0f, b1 = 0.0f;
            if (biasMode == 1)      { b0 = bias[c0]; b1 = bias[c0 + 1]; }
            else if (biasMode == 2) { b0 = bias[0];  b1 = bias[0]; }

            float v00 = acc[mt][nt][0] + b0, v01 = acc[mt][nt][1] + b1;
            float v10 = acc[mt][nt][2] + b0, v11 = acc[mt][nt][3] + b1;
            if (doRelu) {
                v00 = fmaxf(v00, 0.0f); v01 = fmaxf(v01, 0.0f);
                v10 = fmaxf(v10, 0.0f); v11 = fmaxf(v11, 0.0f);
            }

            if (splitOut) {
                __nv_bfloat16 h00 = __float2bfloat16(v00), h01 = __float2bfloat16(v01);
                __nv_bfloat16 h10 = __float2bfloat16(v10), h11 = __float2bfloat16(v11);
                uint32_t ph0 = (uint32_t)__bfloat16_as_ushort(h00) |
                               ((uint32_t)__bfloat16_as_ushort(h01) << 16);
                uint32_t ph1 = (uint32_t)__bfloat16_as_ushort(h10) |
                               ((uint32_t)__bfloat16_as_ushort(h11) << 16);
                __nv_bfloat16 l00 = __float2bfloat16(v00 - __bfloat162float(h00));
                __nv_bfloat16 l01 = __float2bfloat16(v01 - __bfloat162float(h01));
                __nv_bfloat16 l10 = __float2bfloat16(v10 - __bfloat162float(h10));
                __nv_bfloat16 l11 = __float2bfloat16(v11 - __bfloat162float(h11));
                uint32_t pl0 = (uint32_t)__bfloat16_as_ushort(l00) |
                               ((uint32_t)__bfloat16_as_ushort(l01) << 16);
                uint32_t pl1 = (uint32_t)__bfloat16_as_ushort(l10) |
                               ((uint32_t)__bfloat16_as_ushort(l11) << 16);
                *(uint32_t*)(Cb  + (r0 * ldc + c0) * 2)       = ph0;
                *(uint32_t*)(Cb  + ((r0 + 8) * ldc + c0) * 2) = ph1;
                *(uint32_t*)(Cb2 + (r0 * ldc + c0) * 2)       = pl0;
                *(uint32_t*)(Cb2 + ((r0 + 8) * ldc + c0) * 2) = pl1;
            } else {
                *(float2*)(Cb + (r0 * ldc + c0) * 4)       = make_float2(v00, v01);
                *(float2*)(Cb + ((r0 + 8) * ldc + c0) * 4) = make_float2(v10, v11);
            }
        }
    }
}

// ============================ launch ============================
extern "C" void kernel_launch(void* const* d_in, const int* in_sizes, int n_in,
                              void* d_out, int out_size)
{
    const float* X   = (const float*)d_in[0];
    const float* w1h = (const float*)d_in[1];
    const float* b1h = (const float*)d_in[2];
    const float* w2h = (const float*)d_in[3];
    const float* b2h = (const float*)d_in[4];
    const float* w1d = (const float*)d_in[5];
    const float* b1d = (const float*)d_in[6];
    const float* w2d = (const float*)d_in[7];
    const float* b2d = (const float*)d_in[8];
    const float* Wb  = (const float*)d_in[9];
    const float* bb  = (const float*)d_in[10];
    float* out = (float*)d_out;

    __nv_bfloat16* bf = nullptr;
    cudaGetSymbolAddress((void**)&bf, g_bf);
    float* vecs = nullptr;
    cudaGetSymbolAddress((void**)&vecs, g_vec);

    __nv_bfloat16 *Xhi = bf + O_XHI,    *Xlo = bf + O_XLO;
    __nv_bfloat16 *W1Hh = bf + O_W1H_HI, *W1Hl = bf + O_W1H_LO;
    __nv_bfloat16 *W1Dh = bf + O_W1D_HI, *W1Dl = bf + O_W1D_LO;
    __nv_bfloat16 *W2Hh = bf + O_W2H_HI, *W2Hl = bf + O_W2H_LO;
    __nv_bfloat16 *WBh = bf + O_WB_HI,   *WBl = bf + O_WB_LO;
    __nv_bfloat16 *W2DTh = bf + O_W2DT_HI, *W2DTl = bf + O_W2DT_LO;
    __nv_bfloat16 *WPh = bf + O_WP_HI,   *WPl = bf + O_WP_LO;
    __nv_bfloat16 *THh = bf + O_TH_HI,   *THl = bf + O_TH_LO;
    __nv_bfloat16 *TDh = bf + O_TD_HI,   *TDl = bf + O_TD_LO;
    __nv_bfloat16 *HDh = bf + O_HD_HI,   *HDl = bf + O_HD_LO;
    __nv_bfloat16 *DWh = bf + O_DW_HI,   *DWl = bf + O_DW_LO;

    float* b1h_p = vecs + 0 * 512;
    float* b1d_p = vecs + 1 * 512;
    float* b2h_p = vecs + 2 * 512;
    float* bpr   = vecs + 3 * 512;

    cudaFuncSetAttribute(gemm_mma3, cudaFuncAttributeMaxDynamicSharedMemorySize, SMEMSZ);

    // ---- conversions / pads ----
    pad_split<<<(unsigned)((EL_X + 255) / 256), 256>>>(X,   Xhi,   Xlo,   8192, 1024, 8192, 1024, 0);
    pad_split<<<(unsigned)((EL_W1 + 255) / 256), 256>>>(w1h, W1Hh,  W1Hl,  500, 1024, 512, 1024, 0);
    pad_split<<<(unsigned)((EL_W1 + 255) / 256), 256>>>(w1d, W1Dh,  W1Dl,  500, 1024, 512, 1024, 0);
    pad_split<<<(unsigned)((EL_S + 255) / 256), 256>>>(w2h, W2Hh,  W2Hl,  500, 500, 512, 512, 0);
    pad_split<<<(unsigned)((EL_S + 255) / 256), 256>>>(Wb,  WBh,   WBl,   500, 500, 512, 512, 0);
    pad_split<<<(unsigned)((EL_S + 255) / 256), 256>>>(w2d, W2DTh, W2DTl, 500, 500, 512, 512, 1);
    pad_vec<<<2, 256>>>(b1h, b1h_p, 500, 512);
    pad_vec<<<2, 256>>>(b1d, b1d_p, 500, 512);
    pad_vec<<<2, 256>>>(b2h, b2h_p, 500, 512);
    matvec_bp<<<512, 128>>>(Wb, b2d, bpr);

    // ---- W' = Wb @ w2d ----
    {
        dim3 g(4, 4, 1);
        gemm_mma3<<<g, 256, SMEMSZ>>>(WBh, WBl, 512, 0, W2DTh, W2DTl, 512, 0,
                                      WPh, WPl, 512, 0, 512, nullptr, 0, 0, 1);
    }
    // ---- stage 1: Th, Td (K=1024, relu, split out) ----
    {
        dim3 g(4, 64, 1);
        gemm_mma3<<<g, 256, SMEMSZ>>>(Xhi, Xlo, 1024, 0, W1Hh, W1Hl, 1024, 0,
                                      THh, THl, 512, 0, 1024, b1h_p, 1, 1, 1);
        gemm_mma3<<<g, 256, SMEMSZ>>>(Xhi, Xlo, 1024, 0, W1Dh, W1Dl, 1024, 0,
                                      TDh, TDl, 512, 0, 1024, b1d_p, 1, 1, 1);
    }
    // ---- stage 2: head, depW ----
    {
        dim3 g(4, 64, 1);
        gemm_mma3<<<g, 256, SMEMSZ>>>(THh, THl, 512, 0, W2Hh, W2Hl, 512, 0,
                                      HDh, HDl, 512, 0, 512, b2h_p, 1, 0, 1);
        gemm_mma3<<<g, 256, SMEMSZ>>>(TDh, TDl, 512, 0, WPh, WPl, 512, 0,
                                      DWh, DWl, 512, 0, 512, bpr, 1, 0, 1);
    }
    // ---- final batched: out[b] = head[b] @ depW[b]^T + bb (fp32 out) ----
    {
        dim3 g(4, 4, 16);
        const long long sAB = 512LL * 512;
        gemm_mma3<<<g, 256, SMEMSZ>>>(HDh, HDl, 512, sAB, DWh, DWl, 512, sAB,
                                      out, nullptr, 512, sAB, 512, bb, 2, 0, 0);
    }
}

// round 7
// speedup vs baseline: 2.2558x; 1.1265x over previous
#include <cuda_runtime.h>
#include <cuda_bf16.h>
#include <cstdint>

// BiaffineAttention  B=16, S=512, H=1024, A=500 (padded to 512)
// GEMMs via mma.sync bf16 (m16n8k16), 3-pass split precision, fp32 accum.
//   TT   = ReLU(X @ [w1h;w1d]^T + [b1h;b1d])  [8192,1024] -> split bf16
//   W'   = Wb @ w2d ; b' = Wb @ b2d           (bilinear fold)
//   head = TT[:, :512] @ w2h^T + b2h          -> split bf16
//   depW = TT[:, 512:] @ W'^T + b'            -> split bf16
//   out[b] = head[b] @ depW[b]^T + bb         (fp32)

// ============================ PTX helpers ============================
__device__ __forceinline__ uint32_t smem_u32(const void* p) {
    uint32_t a;
    asm("{ .reg .u64 t; cvta.to.shared.u64 t, %1; cvt.u32.u64 %0, t; }"
        : "=r"(a) : "l"(p));
    return a;
}

__device__ __forceinline__ void ldsm4(uint32_t* r, uint32_t addr) {
    asm volatile("ldmatrix.sync.aligned.m8n8.x4.shared.b16 {%0,%1,%2,%3}, [%4];"
        : "=r"(r[0]), "=r"(r[1]), "=r"(r[2]), "=r"(r[3]) : "r"(addr));
}

__device__ __forceinline__ void mma_bf16(float* c, const uint32_t* a,
                                         uint32_t b0, uint32_t b1) {
    asm volatile("mma.sync.aligned.m16n8k16.row.col.f32.bf16.bf16.f32 "
        "{%0,%1,%2,%3}, {%4,%5,%6,%7}, {%8,%9}, {%0,%1,%2,%3};"
        : "+f"(c[0]), "+f"(c[1]), "+f"(c[2]), "+f"(c[3])
        : "r"(a[0]), "r"(a[1]), "r"(a[2]), "r"(a[3]), "r"(b0), "r"(b1));
}

#define CP16(s, g) \
    asm volatile("cp.async.cg.shared.global [%0], [%1], 16;" :: "r"(s), "l"(g))
#define CP_COMMIT() asm volatile("cp.async.commit_group;" ::: "memory")
#define CP_WAIT0()  asm volatile("cp.async.wait_group 0;" ::: "memory")
#define CP_WAIT1()  asm volatile("cp.async.wait_group 1;" ::: "memory")

// ============================ scratch ============================
static constexpr long long EL_X   = 8192LL * 1024;
static constexpr long long EL_W1C = 1024LL * 1024;   // [w1h;w1d] padded
static constexpr long long EL_S   = 512LL * 512;
static constexpr long long EL_TT  = 8192LL * 1024;   // [Th | Td]
static constexpr long long EL_ACT = 8192LL * 512;

static constexpr long long O_XHI    = 0;
static constexpr long long O_XLO    = O_XHI + EL_X;
static constexpr long long O_W1C_HI = O_XLO + EL_X;
static constexpr long long O_W1C_LO = O_W1C_HI + EL_W1C;
static constexpr long long O_W2H_HI = O_W1C_LO + EL_W1C;
static constexpr long long O_W2H_LO = O_W2H_HI + EL_S;
static constexpr long long O_WB_HI  = O_W2H_LO + EL_S;
static constexpr long long O_WB_LO  = O_WB_HI + EL_S;
static constexpr long long O_W2DT_HI= O_WB_LO + EL_S;
static constexpr long long O_W2DT_LO= O_W2DT_HI + EL_S;
static constexpr long long O_WP_HI  = O_W2DT_LO + EL_S;
static constexpr long long O_WP_LO  = O_WP_HI + EL_S;
static constexpr long long O_TT_HI  = O_WP_LO + EL_S;
static constexpr long long O_TT_LO  = O_TT_HI + EL_TT;
static constexpr long long O_HD_HI  = O_TT_LO + EL_TT;
static constexpr long long O_HD_LO  = O_HD_HI + EL_ACT;
static constexpr long long O_DW_HI  = O_HD_LO + EL_ACT;
static constexpr long long O_DW_LO  = O_DW_HI + EL_ACT;
static constexpr long long BF_TOTAL = O_DW_LO + EL_ACT;

__device__ __align__(1024) __nv_bfloat16 g_bf[BF_TOTAL];
__device__ __align__(1024) float g_vec[3 * 1024];    // b1c (1024), b2h_p, bprime

// ============================ small kernels ============================
__global__ void pad_split(const float* __restrict__ src,
                          __nv_bfloat16* __restrict__ hi, __nv_bfloat16* __restrict__ lo,
                          int R, int C, int Rp, int Cp, int transpose)
{
    long long idx = (long long)blockIdx.x * blockDim.x + threadIdx.x;
    if (idx >= (long long)Rp * Cp) return;
    int r = (int)(idx / Cp), c = (int)(idx - (long long)r * Cp);
    float v = 0.0f;
    if (!transpose) { if (r < R && c < C) v = src[(long long)r * C + c]; }
    else            { if (r < C && c < R) v = src[(long long)c * C + r]; }
    __nv_bfloat16 h = __float2bfloat16(v);
    hi[idx] = h;
    lo[idx] = __float2bfloat16(v - __bfloat162float(h));
}

__global__ void pad_vec(const float* __restrict__ src, float* __restrict__ dst, int n, int np)
{
    int i = blockIdx.x * blockDim.x + threadIdx.x;
    if (i < np) dst[i] = (i < n) ? src[i] : 0.0f;
}

__global__ void matvec_bp(const float* __restrict__ Wb, const float* __restrict__ v,
                          float* __restrict__ out)
{
    __shared__ float red[4];
    const int j = blockIdx.x;
    const int tid = threadIdx.x;
    float s = 0.0f;
    if (j < 500)
        for (int a = tid; a < 500; a += 128) s += Wb[j * 500 + a] * v[a];
#pragma unroll
    for (int o = 16; o > 0; o >>= 1) s += __shfl_down_sync(0xffffffffu, s, o);
    if ((tid & 31) == 0) red[tid >> 5] = s;
    __syncthreads();
    if (tid == 0) out[j] = (j < 500) ? (red[0] + red[1] + red[2] + red[3]) : 0.0f;
}

// ============================ main GEMM ============================
// C[M,N] = A[M,K] @ B[N,K]^T via 3-pass bf16 split, fp32 accum.
// CTA 128x128, 8 warps (4 M x 2 N), warp tile 32x64, BK=32 bf16, 2 CTAs/SM.
#define SROW 40
#define TILEB (128 * SROW * 2)       // 10240 B per matrix tile
#define OFF_AH 0
#define OFF_AL (1 * TILEB)
#define OFF_BH (2 * TILEB)
#define OFF_BL (3 * TILEB)
#define STAGE  (4 * TILEB)           // 40960
#define SMEMSZ (2 * STAGE)           // 81920 -> 2 CTAs/SM

__device__ __forceinline__ void issue_tile(
    uint32_t sbase, const char* Ah, const char* Al, const char* Bh, const char* Bl,
    int lda, int ldb, int row0, int col0, int k0, int tid)
{
#pragma unroll
    for (int i = 0; i < 2; i++) {
        const int pos = tid + i * 256;            // 0..511
        const int r = pos >> 2, ch = pos & 3;
        const uint32_t so = (uint32_t)(r * (SROW * 2) + ch * 16);
        const size_t gA = ((size_t)(row0 + r) * lda + k0 + ch * 8) * 2;
        const size_t gB = ((size_t)(col0 + r) * ldb + k0 + ch * 8) * 2;
        CP16(sbase + OFF_AH + so, Ah + gA);
        CP16(sbase + OFF_AL + so, Al + gA);
        CP16(sbase + OFF_BH + so, Bh + gB);
        CP16(sbase + OFF_BL + so, Bl + gB);
    }
}

__global__ void __launch_bounds__(256, 2) gemm_mma3(
    const __nv_bfloat16* __restrict__ Ahi, const __nv_bfloat16* __restrict__ Alo,
    int lda, long long sA,
    const __nv_bfloat16* __restrict__ Bhi, const __nv_bfloat16* __restrict__ Blo,
    int ldb, long long sB,
    void* __restrict__ Cout, void* __restrict__ Cout2,
    int ldc, long long sC,
    int K, const float* __restrict__ bias, int biasMode, int doRelu, int splitOut)
{
    extern __shared__ char smem[];
    const uint32_t sb = smem_u32(smem);
    const int tid  = threadIdx.x;
    const int lane = tid & 31;
    const int wid  = tid >> 5;
    const int wm   = wid & 3;
    const int wn   = wid >> 2;
    const int row0 = blockIdx.y * 128;
    const int col0 = blockIdx.x * 128;

    const char* Ah = (const char*)(Ahi + (long long)blockIdx.z * sA);
    const char* Al = (const char*)(Alo + (long long)blockIdx.z * sA);
    const char* Bh = (const char*)(Bhi + (long long)blockIdx.z * sB);
    const char* Bl = (const char*)(Blo + (long long)blockIdx.z * sB);

    float acc[2][8][4];
#pragma unroll
    for (int mt = 0; mt < 2; mt++)
#pragma unroll
        for (int nt = 0; nt < 8; nt++)
#pragma unroll
            for (int q = 0; q < 4; q++) acc[mt][nt][q] = 0.0f;

    const int frow = (lane & 7) | (((lane >> 3) & 1) << 3);
    const int fkc  = (lane >> 4) * 8;

    const int T = K / 32;
    issue_tile(sb, Ah, Al, Bh, Bl, lda, ldb, row0, col0, 0, tid);
    CP_COMMIT();

    for (int t = 0; t < T; ++t) {
        if (t + 1 < T) {
            issue_tile(sb + ((t + 1) & 1) * STAGE, Ah, Al, Bh, Bl,
                       lda, ldb, row0, col0, (t + 1) * 32, tid);
            CP_COMMIT();
            CP_WAIT1();
        } else {
            CP_WAIT0();
        }
        __syncthreads();

        const uint32_t st = sb + (t & 1) * STAGE;
#pragma unroll
        for (int kh = 0; kh < 2; ++kh) {
            const int kb = kh * 16 + fkc;
            uint32_t ah[2][4], al[2][4];
#pragma unroll
            for (int mt = 0; mt < 2; mt++) {
                const uint32_t off = (uint32_t)(((wm * 32 + mt * 16 + frow) * SROW + kb) * 2);
                ldsm4(ah[mt], st + OFF_AH + off);
                ldsm4(al[mt], st + OFF_AL + off);
            }
#pragma unroll
            for (int bt = 0; bt < 4; bt++) {
                uint32_t bh[4], bl[4];
                const uint32_t off = (uint32_t)(((wn * 64 + bt * 16 + frow) * SROW + kb) * 2);
                ldsm4(bh, st + OFF_BH + off);
                ldsm4(bl, st + OFF_BL + off);
#pragma unroll
                for (int mt = 0; mt < 2; mt++)
#pragma unroll
                    for (int p = 0; p < 2; p++) {
                        const int nt = bt * 2 + p;
                        mma_bf16(acc[mt][nt], ah[mt], bh[p], bh[p + 2]);
                        mma_bf16(acc[mt][nt], ah[mt], bl[p], bl[p + 2]);
                        mma_bf16(acc[mt][nt], al[mt], bh[p], bh[p + 2]);
                    }
            }
        }
        __syncthreads();
    }

    // ============================ epilogue ============================
    char* Cb  = (char*)Cout + (size_t)blockIdx.z * sC * (splitOut ? 2 : 4);
    char* Cb2 = splitOut ? ((char*)Cout2 + (size_t)blockIdx.z * sC * 2) : nullptr;

#pragma unroll
    for (int mt = 0; mt < 2; mt++) {
        const long long r0 = row0 + wm * 32 + mt * 16 + (lane >> 2);
#pragma unroll
        for (int nt = 0; nt < 8; nt++) {
            const int c0 = col0 + wn * 64 + nt * 8 + (lane & 3) * 2;
            float b0 = 0.0f, b1 = 0.0f;
            if (biasMode == 1)      { b0 = bias[c0]; b1 = bias[c0 + 1]; }
            else if (biasMode == 2) { b0 = bias[0];  b1 = bias[0]; }

            float v00 = acc[mt][nt][0] + b0, v01 = acc[mt][nt][1] + b1;
            float v10 = acc[mt][nt][2] + b0, v11 = acc[mt][nt][3] + b1;
            if (doRelu) {
                v00 = fmaxf(v00, 0.0f); v01 = fmaxf(v01, 0.0f);
                v10 = fmaxf(v10, 0.0f); v11 = fmaxf(v11, 0.0f);
            }

            if (splitOut) {
                __nv_bfloat16 h00 = __float2bfloat16(v00), h01 = __float2bfloat16(v01);
                __nv_bfloat16 h10 = __float2bfloat16(v10), h11 = __float2bfloat16(v11);
                uint32_t ph0 = (uint32_t)__bfloat16_as_ushort(h00) |
                               ((uint32_t)__bfloat16_as_ushort(h01) << 16);
                uint32_t ph1 = (uint32_t)__bfloat16_as_ushort(h10) |
                               ((uint32_t)__bfloat16_as_ushort(h11) << 16);
                __nv_bfloat16 l00 = __float2bfloat16(v00 - __bfloat162float(h00));
                __nv_bfloat16 l01 = __float2bfloat16(v01 - __bfloat162float(h01));
                __nv_bfloat16 l10 = __float2bfloat16(v10 - __bfloat162float(h10));
                __nv_bfloat16 l11 = __float2bfloat16(v11 - __bfloat162float(h11));
                uint32_t pl0 = (uint32_t)__bfloat16_as_ushort(l00) |
                               ((uint32_t)__bfloat16_as_ushort(l01) << 16);
                uint32_t pl1 = (uint32_t)__bfloat16_as_ushort(l10) |
                               ((uint32_t)__bfloat16_as_ushort(l11) << 16);
                *(uint32_t*)(Cb  + (r0 * ldc + c0) * 2)       = ph0;
                *(uint32_t*)(Cb  + ((r0 + 8) * ldc + c0) * 2) = ph1;
                *(uint32_t*)(Cb2 + (r0 * ldc + c0) * 2)       = pl0;
                *(uint32_t*)(Cb2 + ((r0 + 8) * ldc + c0) * 2) = pl1;
            } else {
                *(float2*)(Cb + (r0 * ldc + c0) * 4)       = make_float2(v00, v01);
                *(float2*)(Cb + ((r0 + 8) * ldc + c0) * 4) = make_float2(v10, v11);
            }
        }
    }
}

// ============================ launch ============================
extern "C" void kernel_launch(void* const* d_in, const int* in_sizes, int n_in,
                              void* d_out, int out_size)
{
    const float* X   = (const float*)d_in[0];
    const float* w1h = (const float*)d_in[1];
    const float* b1h = (const float*)d_in[2];
    const float* w2h = (const float*)d_in[3];
    const float* b2h = (const float*)d_in[4];
    const float* w1d = (const float*)d_in[5];
    const float* b1d = (const float*)d_in[6];
    const float* w2d = (const float*)d_in[7];
    const float* b2d = (const float*)d_in[8];
    const float* Wb  = (const float*)d_in[9];
    const float* bb  = (const float*)d_in[10];
    float* out = (float*)d_out;

    __nv_bfloat16* bf = nullptr;
    cudaGetSymbolAddress((void**)&bf, g_bf);
    float* vecs = nullptr;
    cudaGetSymbolAddress((void**)&vecs, g_vec);

    __nv_bfloat16 *Xhi = bf + O_XHI,     *Xlo = bf + O_XLO;
    __nv_bfloat16 *W1Ch = bf + O_W1C_HI, *W1Cl = bf + O_W1C_LO;
    __nv_bfloat16 *W2Hh = bf + O_W2H_HI, *W2Hl = bf + O_W2H_LO;
    __nv_bfloat16 *WBh = bf + O_WB_HI,   *WBl = bf + O_WB_LO;
    __nv_bfloat16 *W2DTh = bf + O_W2DT_HI, *W2DTl = bf + O_W2DT_LO;
    __nv_bfloat16 *WPh = bf + O_WP_HI,   *WPl = bf + O_WP_LO;
    __nv_bfloat16 *TTh = bf + O_TT_HI,   *TTl = bf + O_TT_LO;
    __nv_bfloat16 *HDh = bf + O_HD_HI,   *HDl = bf + O_HD_LO;
    __nv_bfloat16 *DWh = bf + O_DW_HI,   *DWl = bf + O_DW_LO;

    float* b1c   = vecs + 0 * 1024;       // [b1h_p | b1d_p]
    float* b2h_p = vecs + 1 * 1024;
    float* bpr   = vecs + 2 * 1024;

    cudaFuncSetAttribute(gemm_mma3, cudaFuncAttributeMaxDynamicSharedMemorySize, SMEMSZ);

    // ---- conversions / pads ----
    pad_split<<<(unsigned)((EL_X + 255) / 256), 256>>>(X, Xhi, Xlo, 8192, 1024, 8192, 1024, 0);
    // W1C rows 0..511 = w1h padded, rows 512..1023 = w1d padded
    pad_split<<<(unsigned)((512LL * 1024 + 255) / 256), 256>>>(
        w1h, W1Ch, W1Cl, 500, 1024, 512, 1024, 0);
    pad_split<<<(unsigned)((512LL * 1024 + 255) / 256), 256>>>(
        w1d, W1Ch + 512LL * 1024, W1Cl + 512LL * 1024, 500, 1024, 512, 1024, 0);
    pad_split<<<(unsigned)((EL_S + 255) / 256), 256>>>(w2h, W2Hh, W2Hl, 500, 500, 512, 512, 0);
    pad_split<<<(unsigned)((EL_S + 255) / 256), 256>>>(Wb,  WBh,  WBl,  500, 500, 512, 512, 0);
    pad_split<<<(unsigned)((EL_S + 255) / 256), 256>>>(w2d, W2DTh, W2DTl, 500, 500, 512, 512, 1);
    pad_vec<<<2, 256>>>(b1h, b1c,       500, 512);
    pad_vec<<<2, 256>>>(b1d, b1c + 512, 500, 512);
    pad_vec<<<2, 256>>>(b2h, b2h_p,     500, 512);
    matvec_bp<<<512, 128>>>(Wb, b2d, bpr);

    // ---- W' = Wb @ w2d ----
    {
        dim3 g(4, 4, 1);
        gemm_mma3<<<g, 256, SMEMSZ>>>(WBh, WBl, 512, 0, W2DTh, W2DTl, 512, 0,
                                      WPh, WPl, 512, 0, 512, nullptr, 0, 0, 1);
    }
    // ---- stage 1 merged: TT = ReLU(X @ W1C^T + b1c), N=1024 ----
    {
        dim3 g(8, 64, 1);
        gemm_mma3<<<g, 256, SMEMSZ>>>(Xhi, Xlo, 1024, 0, W1Ch, W1Cl, 1024, 0,
                                      TTh, TTl, 1024, 0, 1024, b1c, 1, 1, 1);
    }
    // ---- stage 2: head = TT[:, :512] @ w2h^T + b2h ; depW = TT[:, 512:] @ W'^T + b' ----
    {
        dim3 g(4, 64, 1);
        gemm_mma3<<<g, 256, SMEMSZ>>>(TTh, TTl, 1024, 0, W2Hh, W2Hl, 512, 0,
                                      HDh, HDl, 512, 0, 512, b2h_p, 1, 0, 1);
        gemm_mma3<<<g, 256, SMEMSZ>>>(TTh + 512, TTl + 512, 1024, 0, WPh, WPl, 512, 0,
                                      DWh, DWl, 512, 0, 512, bpr, 1, 0, 1);
    }
    // ---- final batched: out[b] = head[b] @ depW[b]^T + bb (fp32 out) ----
    {
        dim3 g(4, 4, 16);
        const long long sAB = 512LL * 512;
        gemm_mma3<<<g, 256, SMEMSZ>>>(HDh, HDl, 512, sAB, DWh, DWl, 512, sAB,
                                      out, nullptr, 512, sAB, 512, bb, 2, 0, 0);
    }
}

// round 8
// speedup vs baseline: 2.4116x; 1.0691x over previous
#include <cuda_runtime.h>
#include <cuda_bf16.h>
#include <cstdint>

// BiaffineAttention  B=16, S=512, H=1024, A=500 (padded to 512)
// GEMMs via mma.sync bf16 (m16n8k16), 3-pass split precision, fp32 accum.
//   TT   = ReLU(X @ [w1h;w1d]^T + [b1h;b1d])  [8192,1024] -> split bf16
//   W'   = Wb @ w2d ; b' = Wb @ b2d           (bilinear fold)
//   head = TT[:, :512] @ w2h^T + b2h          -> split bf16   (merged z=0)
//   depW = TT[:, 512:] @ W'^T + b'            -> split bf16   (merged z=1)
//   out[b] = head[b] @ depW[b]^T + bb         (fp32)

// ============================ PTX helpers ============================
__device__ __forceinline__ uint32_t smem_u32(const void* p) {
    uint32_t a;
    asm("{ .reg .u64 t; cvta.to.shared.u64 t, %1; cvt.u32.u64 %0, t; }"
        : "=r"(a) : "l"(p));
    return a;
}

__device__ __forceinline__ void ldsm4(uint32_t* r, uint32_t addr) {
    asm volatile("ldmatrix.sync.aligned.m8n8.x4.shared.b16 {%0,%1,%2,%3}, [%4];"
        : "=r"(r[0]), "=r"(r[1]), "=r"(r[2]), "=r"(r[3]) : "r"(addr));
}

__device__ __forceinline__ void mma_bf16(float* c, const uint32_t* a,
                                         uint32_t b0, uint32_t b1) {
    asm volatile("mma.sync.aligned.m16n8k16.row.col.f32.bf16.bf16.f32 "
        "{%0,%1,%2,%3}, {%4,%5,%6,%7}, {%8,%9}, {%0,%1,%2,%3};"
        : "+f"(c[0]), "+f"(c[1]), "+f"(c[2]), "+f"(c[3])
        : "r"(a[0]), "r"(a[1]), "r"(a[2]), "r"(a[3]), "r"(b0), "r"(b1));
}

#define CP16(s, g) \
    asm volatile("cp.async.cg.shared.global [%0], [%1], 16;" :: "r"(s), "l"(g))
#define CP_COMMIT() asm volatile("cp.async.commit_group;" ::: "memory")
#define CP_WAIT0()  asm volatile("cp.async.wait_group 0;" ::: "memory")
#define CP_WAIT1()  asm volatile("cp.async.wait_group 1;" ::: "memory")

// ============================ scratch ============================
static constexpr long long EL_X   = 8192LL * 1024;
static constexpr long long EL_W1C = 1024LL * 1024;
static constexpr long long EL_S   = 512LL * 512;
static constexpr long long EL_TT  = 8192LL * 1024;
static constexpr long long EL_ACT = 8192LL * 512;

static constexpr long long O_XHI    = 0;
static constexpr long long O_XLO    = O_XHI + EL_X;
static constexpr long long O_W1C_HI = O_XLO + EL_X;
static constexpr long long O_W1C_LO = O_W1C_HI + EL_W1C;
static constexpr long long O_W2H_HI = O_W1C_LO + EL_W1C;
static constexpr long long O_W2H_LO = O_W2H_HI + EL_S;
static constexpr long long O_WB_HI  = O_W2H_LO + EL_S;
static constexpr long long O_WB_LO  = O_WB_HI + EL_S;
static constexpr long long O_W2DT_HI= O_WB_LO + EL_S;
static constexpr long long O_W2DT_LO= O_W2DT_HI + EL_S;
static constexpr long long O_WP_HI  = O_W2DT_LO + EL_S;
static constexpr long long O_WP_LO  = O_WP_HI + EL_S;
static constexpr long long O_TT_HI  = O_WP_LO + EL_S;
static constexpr long long O_TT_LO  = O_TT_HI + EL_TT;
static constexpr long long O_HD_HI  = O_TT_LO + EL_TT;
static constexpr long long O_HD_LO  = O_HD_HI + EL_ACT;
static constexpr long long O_DW_HI  = O_HD_LO + EL_ACT;
static constexpr long long O_DW_LO  = O_DW_HI + EL_ACT;
static constexpr long long BF_TOTAL = O_DW_LO + EL_ACT;

__device__ __align__(1024) __nv_bfloat16 g_bf[BF_TOTAL];
__device__ __align__(1024) float g_vec[3 * 1024];    // b1c[1024], b2h_p[512], bpr[512]

// ============================ prep kernels ============================
__device__ __forceinline__ void split_store(__nv_bfloat16* hi, __nv_bfloat16* lo,
                                            long long idx, float v)
{
    __nv_bfloat16 h = __float2bfloat16(v);
    hi[idx] = h;
    lo[idx] = __float2bfloat16(v - __bfloat162float(h));
}

// X split: [8192,1024] fp32 -> hi/lo bf16 (no padding needed)
__global__ void split_x(const float* __restrict__ X,
                        __nv_bfloat16* __restrict__ hi, __nv_bfloat16* __restrict__ lo)
{
    long long idx = (long long)blockIdx.x * blockDim.x + threadIdx.x;
    float4 v = *(const float4*)(X + idx * 4);
    split_store(hi, lo, idx * 4 + 0, v.x);
    split_store(hi, lo, idx * 4 + 1, v.y);
    split_store(hi, lo, idx * 4 + 2, v.z);
    split_store(hi, lo, idx * 4 + 3, v.w);
}

// All weight pads/splits + bias pads + bpr matvec in ONE kernel.
// Block map (256 threads each):
//   [0,2048)      w1h -> W1C rows [0,512)        (512x1024)
//   [2048,4096)   w1d -> W1C rows [512,1024)
//   [4096,5120)   w2h -> W2H                     (512x512)
//   [5120,6144)   Wb  -> WB
//   [6144,7168)   w2d^T -> W2DT
//   [7168,7680)   bpr[j] = Wb[j,:] . b2d         (one block per j)
//   [7680,7686)   bias pads: b1c (1024), b2h_p (512)
__global__ void prep_weights(
    const float* __restrict__ w1h, const float* __restrict__ w1d,
    const float* __restrict__ w2h, const float* __restrict__ Wb,
    const float* __restrict__ w2d,
    const float* __restrict__ b1h, const float* __restrict__ b1d,
    const float* __restrict__ b2h, const float* __restrict__ b2d,
    __nv_bfloat16* __restrict__ W1Ch, __nv_bfloat16* __restrict__ W1Cl,
    __nv_bfloat16* __restrict__ W2Hh, __nv_bfloat16* __restrict__ W2Hl,
    __nv_bfloat16* __restrict__ WBh,  __nv_bfloat16* __restrict__ WBl,
    __nv_bfloat16* __restrict__ W2DTh,__nv_bfloat16* __restrict__ W2DTl,
    float* __restrict__ b1c, float* __restrict__ b2h_p, float* __restrict__ bpr)
{
    const int bx = blockIdx.x;
    const int tid = threadIdx.x;

    if (bx < 4096) {
        // w1h / w1d pad-split into W1C [1024,1024]
        const int half = bx >> 11;                  // 0: w1h, 1: w1d
        const long long e = ((long long)(bx & 2047)) * 256 + tid;   // < 512*1024
        const int r = (int)(e >> 10), c = (int)(e & 1023);
        const float* src = half ? w1d : w1h;
        float v = (r < 500) ? src[(long long)r * 1024 + c] : 0.0f;
        split_store(W1Ch, W1Cl, (long long)half * 512 * 1024 + e, v);
    } else if (bx < 7168) {
        const int sec = (bx - 4096) >> 10;          // 0: w2h, 1: Wb, 2: w2d^T
        const long long e = ((long long)((bx - 4096) & 1023)) * 256 + tid;  // < 512*512
        const int r = (int)(e >> 9), c = (int)(e & 511);
        float v = 0.0f;
        if (sec == 0) { if (r < 500 && c < 500) v = w2h[r * 500 + c]; split_store(W2Hh, W2Hl, e, v); }
        else if (sec == 1) { if (r < 500 && c < 500) v = Wb[r * 500 + c]; split_store(WBh, WBl, e, v); }
        else { if (r < 500 && c < 500) v = w2d[c * 500 + r]; split_store(W2DTh, W2DTl, e, v); }
    } else if (bx < 7680) {
        // bpr[j] = sum_a Wb[j,a]*b2d[a]
        const int j = bx - 7168;
        __shared__ float red[8];
        float s = 0.0f;
        if (j < 500)
            for (int a = tid; a < 500; a += 256) s += Wb[j * 500 + a] * b2d[a];
#pragma unroll
        for (int o = 16; o > 0; o >>= 1) s += __shfl_down_sync(0xffffffffu, s, o);
        if ((tid & 31) == 0) red[tid >> 5] = s;
        __syncthreads();
        if (tid == 0) {
            float t = 0.0f;
#pragma unroll
            for (int q = 0; q < 8; q++) t += red[q];
            bpr[j] = (j < 500) ? t : 0.0f;
        }
    } else {
        const int e = (bx - 7680) * 256 + tid;      // < 1536
        if (e < 1024) {
            const int c = e & 511;
            b1c[e] = (c < 500) ? ((e < 512) ? b1h[c] : b1d[c]) : 0.0f;
        } else if (e < 1536) {
            const int c = e - 1024;
            b2h_p[c] = (c < 500) ? b2h[c] : 0.0f;
        }
    }
}

// ============================ main GEMM ============================
// C[M,N] = A[M,K] @ B[N,K]^T via 3-pass bf16 split, fp32 accum.
// CTA 128x128, 8 warps (4 M x 2 N), warp tile 32x64, BK=32, 2 CTAs/SM.
// dual=1: blockIdx.z selects operand set (stage-2 merge).
#define SROW 40
#define TILEB (128 * SROW * 2)
#define OFF_AH 0
#define OFF_AL (1 * TILEB)
#define OFF_BH (2 * TILEB)
#define OFF_BL (3 * TILEB)
#define STAGE  (4 * TILEB)           // 40960
#define SMEMSZ (2 * STAGE)           // 81920 -> 2 CTAs/SM

__device__ __forceinline__ void issue_tile(
    uint32_t sbase, const char* Ah, const char* Al, const char* Bh, const char* Bl,
    int lda, int ldb, int row0, int col0, int k0, int tid)
{
#pragma unroll
    for (int i = 0; i < 2; i++) {
        const int pos = tid + i * 256;
        const int r = pos >> 2, ch = pos & 3;
        const uint32_t so = (uint32_t)(r * (SROW * 2) + ch * 16);
        const size_t gA = ((size_t)(row0 + r) * lda + k0 + ch * 8) * 2;
        const size_t gB = ((size_t)(col0 + r) * ldb + k0 + ch * 8) * 2;
        CP16(sbase + OFF_AH + so, Ah + gA);
        CP16(sbase + OFF_AL + so, Al + gA);
        CP16(sbase + OFF_BH + so, Bh + gB);
        CP16(sbase + OFF_BL + so, Bl + gB);
    }
}

__global__ void __launch_bounds__(256, 2) gemm_mma3(
    const __nv_bfloat16* __restrict__ Ahi, const __nv_bfloat16* __restrict__ Alo,
    int lda, long long sA,
    const __nv_bfloat16* __restrict__ Bhi, const __nv_bfloat16* __restrict__ Blo,
    const __nv_bfloat16* __restrict__ Bhi2, const __nv_bfloat16* __restrict__ Blo2,
    int ldb, long long sB,
    void* __restrict__ Cout, void* __restrict__ Cout2,
    void* __restrict__ CoutB, void* __restrict__ Cout2B,
    int ldc, long long sC,
    int K, const float* __restrict__ bias, const float* __restrict__ bias2,
    int biasMode, int doRelu, int splitOut, int dual)
{
    extern __shared__ char smem[];
    const uint32_t sb = smem_u32(smem);
    const int tid  = threadIdx.x;
    const int lane = tid & 31;
    const int wid  = tid >> 5;
    const int wm   = wid & 3;
    const int wn   = wid >> 2;
    const int row0 = blockIdx.y * 128;
    const int col0 = blockIdx.x * 128;

    const int z = blockIdx.z;
    const char *Ah, *Al, *Bh, *Bl;
    const float* bvp = bias;
    void *Co = Cout, *Co2 = Cout2;
    if (dual && z) {
        // second operand set: A shifted by 512 columns, B/bias/C from set 2
        Ah = (const char*)(Ahi + 512);
        Al = (const char*)(Alo + 512);
        Bh = (const char*)Bhi2;  Bl = (const char*)Blo2;
        bvp = bias2;  Co = CoutB;  Co2 = Cout2B;
    } else {
        Ah = (const char*)(Ahi + (long long)z * sA);
        Al = (const char*)(Alo + (long long)z * sA);
        Bh = (const char*)(Bhi + (long long)z * sB);
        Bl = (const char*)(Blo + (long long)z * sB);
    }

    float acc[2][8][4];
#pragma unroll
    for (int mt = 0; mt < 2; mt++)
#pragma unroll
        for (int nt = 0; nt < 8; nt++)
#pragma unroll
            for (int q = 0; q < 4; q++) acc[mt][nt][q] = 0.0f;

    const int frow = (lane & 7) | (((lane >> 3) & 1) << 3);
    const int fkc  = (lane >> 4) * 8;

    const int T = K / 32;
    issue_tile(sb, Ah, Al, Bh, Bl, lda, ldb, row0, col0, 0, tid);
    CP_COMMIT();

    for (int t = 0; t < T; ++t) {
        if (t + 1 < T) {
            issue_tile(sb + ((t + 1) & 1) * STAGE, Ah, Al, Bh, Bl,
                       lda, ldb, row0, col0, (t + 1) * 32, tid);
            CP_COMMIT();
            CP_WAIT1();
        } else {
            CP_WAIT0();
        }
        __syncthreads();

        const uint32_t st = sb + (t & 1) * STAGE;
#pragma unroll
        for (int kh = 0; kh < 2; ++kh) {
            const int kb = kh * 16 + fkc;
            uint32_t ah[2][4], al[2][4];
#pragma unroll
            for (int mt = 0; mt < 2; mt++) {
                const uint32_t off = (uint32_t)(((wm * 32 + mt * 16 + frow) * SROW + kb) * 2);
                ldsm4(ah[mt], st + OFF_AH + off);
                ldsm4(al[mt], st + OFF_AL + off);
            }
#pragma unroll
            for (int bt = 0; bt < 4; bt++) {
                uint32_t bh[4], bl[4];
                const uint32_t off = (uint32_t)(((wn * 64 + bt * 16 + frow) * SROW + kb) * 2);
                ldsm4(bh, st + OFF_BH + off);
                ldsm4(bl, st + OFF_BL + off);
                // pass-major order: all hh, then hl, then lh -> RAW distance 4
#pragma unroll
                for (int mt = 0; mt < 2; mt++)
#pragma unroll
                    for (int p = 0; p < 2; p++)
                        mma_bf16(acc[mt][bt * 2 + p], ah[mt], bh[p], bh[p + 2]);
#pragma unroll
                for (int mt = 0; mt < 2; mt++)
#pragma unroll
                    for (int p = 0; p < 2; p++)
                        mma_bf16(acc[mt][bt * 2 + p], ah[mt], bl[p], bl[p + 2]);
#pragma unroll
                for (int mt = 0; mt < 2; mt++)
#pragma unroll
                    for (int p = 0; p < 2; p++)
                        mma_bf16(acc[mt][bt * 2 + p], al[mt], bh[p], bh[p + 2]);
            }
        }
        __syncthreads();
    }

    // ============================ epilogue ============================
    char* Cb  = (char*)Co + (dual ? 0 : (size_t)z * sC * (splitOut ? 2 : 4));
    char* Cb2 = splitOut ? ((char*)Co2 + (dual ? 0 : (size_t)z * sC * 2)) : nullptr;

#pragma unroll
    for (int mt = 0; mt < 2; mt++) {
        const long long r0 = row0 + wm * 32 + mt * 16 + (lane >> 2);
#pragma unroll
        for (int nt = 0; nt < 8; nt++) {
            const int c0 = col0 + wn * 64 + nt * 8 + (lane & 3) * 2;
            float b0 = 0.0f, b1 = 0.0f;
            if (biasMode == 1)      { b0 = bvp[c0]; b1 = bvp[c0 + 1]; }
            else if (biasMode == 2) { b0 = bvp[0];  b1 = bvp[0]; }

            float v00 = acc[mt][nt][0] + b0, v01 = acc[mt][nt][1] + b1;
            float v10 = acc[mt][nt][2] + b0, v11 = acc[mt][nt][3] + b1;
            if (doRelu) {
                v00 = fmaxf(v00, 0.0f); v01 = fmaxf(v01, 0.0f);
                v10 = fmaxf(v10, 0.0f); v11 = fmaxf(v11, 0.0f);
            }

            if (splitOut) {
                __nv_bfloat16 h00 = __float2bfloat16(v00), h01 = __float2bfloat16(v01);
                __nv_bfloat16 h10 = __float2bfloat16(v10), h11 = __float2bfloat16(v11);
                uint32_t ph0 = (uint32_t)__bfloat16_as_ushort(h00) |
                               ((uint32_t)__bfloat16_as_ushort(h01) << 16);
                uint32_t ph1 = (uint32_t)__bfloat16_as_ushort(h10) |
                               ((uint32_t)__bfloat16_as_ushort(h11) << 16);
                __nv_bfloat16 l00 = __float2bfloat16(v00 - __bfloat162float(h00));
                __nv_bfloat16 l01 = __float2bfloat16(v01 - __bfloat162float(h01));
                __nv_bfloat16 l10 = __float2bfloat16(v10 - __bfloat162float(h10));
                __nv_bfloat16 l11 = __float2bfloat16(v11 - __bfloat162float(h11));
                uint32_t pl0 = (uint32_t)__bfloat16_as_ushort(l00) |
                               ((uint32_t)__bfloat16_as_ushort(l01) << 16);
                uint32_t pl1 = (uint32_t)__bfloat16_as_ushort(l10) |
                               ((uint32_t)__bfloat16_as_ushort(l11) << 16);
                *(uint32_t*)(Cb  + (r0 * ldc + c0) * 2)       = ph0;
                *(uint32_t*)(Cb  + ((r0 + 8) * ldc + c0) * 2) = ph1;
                *(uint32_t*)(Cb2 + (r0 * ldc + c0) * 2)       = pl0;
                *(uint32_t*)(Cb2 + ((r0 + 8) * ldc + c0) * 2) = pl1;
            } else {
                *(float2*)(Cb + (r0 * ldc + c0) * 4)       = make_float2(v00, v01);
                *(float2*)(Cb + ((r0 + 8) * ldc + c0) * 4) = make_float2(v10, v11);
            }
        }
    }
}

// ============================ launch ============================
extern "C" void kernel_launch(void* const* d_in, const int* in_sizes, int n_in,
                              void* d_out, int out_size)
{
    const float* X   = (const float*)d_in[0];
    const float* w1h = (const float*)d_in[1];
    const float* b1h = (const float*)d_in[2];
    const float* w2h = (const float*)d_in[3];
    const float* b2h = (const float*)d_in[4];
    const float* w1d = (const float*)d_in[5];
    const float* b1d = (const float*)d_in[6];
    const float* w2d = (const float*)d_in[7];
    const float* b2d = (const float*)d_in[8];
    const float* Wb  = (const float*)d_in[9];
    const float* bb  = (const float*)d_in[10];
    float* out = (float*)d_out;

    __nv_bfloat16* bf = nullptr;
    cudaGetSymbolAddress((void**)&bf, g_bf);
    float* vecs = nullptr;
    cudaGetSymbolAddress((void**)&vecs, g_vec);

    __nv_bfloat16 *Xhi = bf + O_XHI,     *Xlo = bf + O_XLO;
    __nv_bfloat16 *W1Ch = bf + O_W1C_HI, *W1Cl = bf + O_W1C_LO;
    __nv_bfloat16 *W2Hh = bf + O_W2H_HI, *W2Hl = bf + O_W2H_LO;
    __nv_bfloat16 *WBh = bf + O_WB_HI,   *WBl = bf + O_WB_LO;
    __nv_bfloat16 *W2DTh = bf + O_W2DT_HI, *W2DTl = bf + O_W2DT_LO;
    __nv_bfloat16 *WPh = bf + O_WP_HI,   *WPl = bf + O_WP_LO;
    __nv_bfloat16 *TTh = bf + O_TT_HI,   *TTl = bf + O_TT_LO;
    __nv_bfloat16 *HDh = bf + O_HD_HI,   *HDl = bf + O_HD_LO;
    __nv_bfloat16 *DWh = bf + O_DW_HI,   *DWl = bf + O_DW_LO;

    float* b1c   = vecs + 0 * 1024;
    float* b2h_p = vecs + 1 * 1024;
    float* bpr   = vecs + 2 * 1024;

    cudaFuncSetAttribute(gemm_mma3, cudaFuncAttributeMaxDynamicSharedMemorySize, SMEMSZ);

    // launch 0: X split
    split_x<<<(unsigned)(EL_X / 4 / 256), 256>>>(X, Xhi, Xlo);
    // launch 1: all weight/bias prep
    prep_weights<<<7686, 256>>>(w1h, w1d, w2h, Wb, w2d, b1h, b1d, b2h, b2d,
                                W1Ch, W1Cl, W2Hh, W2Hl, WBh, WBl, W2DTh, W2DTl,
                                b1c, b2h_p, bpr);

    // launch 2: W' = Wb @ w2d
    {
        dim3 g(4, 4, 1);
        gemm_mma3<<<g, 256, SMEMSZ>>>(WBh, WBl, 512, 0, W2DTh, W2DTl, nullptr, nullptr,
                                      512, 0, WPh, WPl, nullptr, nullptr, 512, 0,
                                      512, nullptr, nullptr, 0, 0, 1, 0);
    }
    // launch 3: stage 1 merged: TT = ReLU(X @ W1C^T + b1c), N=1024
    {
        dim3 g(8, 64, 1);
        gemm_mma3<<<g, 256, SMEMSZ>>>(Xhi, Xlo, 1024, 0, W1Ch, W1Cl, nullptr, nullptr,
                                      1024, 0, TTh, TTl, nullptr, nullptr, 1024, 0,
                                      1024, b1c, nullptr, 1, 1, 1, 0);
    }
    // launch 4: stage 2 merged (z=0: head, z=1: depW)
    {
        dim3 g(4, 64, 2);
        gemm_mma3<<<g, 256, SMEMSZ>>>(TTh, TTl, 1024, 0,
                                      W2Hh, W2Hl, WPh, WPl, 512, 0,
                                      HDh, HDl, DWh, DWl, 512, 0,
                                      512, b2h_p, bpr, 1, 0, 1, 1);
    }
    // launch 5: final batched: out[b] = head[b] @ depW[b]^T + bb  -> PROFILED by ncu -s 5
    {
        dim3 g(4, 4, 16);
        const long long sAB = 512LL * 512;
        gemm_mma3<<<g, 256, SMEMSZ>>>(HDh, HDl, 512, sAB, DWh, DWl, nullptr, nullptr,
                                      512, sAB, out, nullptr, nullptr, nullptr, 512, sAB,
                                      512, bb, nullptr, 2, 0, 0, 0);
    }
}

// round 9
// speedup vs baseline: 2.4124x; 1.0003x over previous
#include <cuda_runtime.h>
#include <cuda_bf16.h>
#include <cstdint>

// BiaffineAttention  B=16, S=512, H=1024, A=500 (padded to 512)
// GEMMs via mma.sync bf16 (m16n8k16), 3-pass split precision, fp32 accum.
//   TT   = ReLU(X @ [w1h;w1d]^T + [b1h;b1d])  [8192,1024] -> split bf16
//   W'   = Wb @ w2d ; b' = Wb @ b2d           (bilinear fold)
//   head = TT[:, :512] @ w2h^T + b2h          -> split bf16   (merged z=0)
//   depW = TT[:, 512:] @ W'^T + b'            -> split bf16   (merged z=1)
//   out[b] = head[b] @ depW[b]^T + bb         (fp32)

// ============================ PTX helpers ============================
__device__ __forceinline__ uint32_t smem_u32(const void* p) {
    uint32_t a;
    asm("{ .reg .u64 t; cvta.to.shared.u64 t, %1; cvt.u32.u64 %0, t; }"
        : "=r"(a) : "l"(p));
    return a;
}

__device__ __forceinline__ void ldsm4(uint32_t* r, uint32_t addr) {
    asm volatile("ldmatrix.sync.aligned.m8n8.x4.shared.b16 {%0,%1,%2,%3}, [%4];"
        : "=r"(r[0]), "=r"(r[1]), "=r"(r[2]), "=r"(r[3]) : "r"(addr));
}

__device__ __forceinline__ void mma_bf16(float* c, const uint32_t* a,
                                         uint32_t b0, uint32_t b1) {
    asm volatile("mma.sync.aligned.m16n8k16.row.col.f32.bf16.bf16.f32 "
        "{%0,%1,%2,%3}, {%4,%5,%6,%7}, {%8,%9}, {%0,%1,%2,%3};"
        : "+f"(c[0]), "+f"(c[1]), "+f"(c[2]), "+f"(c[3])
        : "r"(a[0]), "r"(a[1]), "r"(a[2]), "r"(a[3]), "r"(b0), "r"(b1));
}

#define CP16(s, g) \
    asm volatile("cp.async.cg.shared.global [%0], [%1], 16;" :: "r"(s), "l"(g))
#define CP_COMMIT() asm volatile("cp.async.commit_group;" ::: "memory")
#define CP_WAIT0()  asm volatile("cp.async.wait_group 0;" ::: "memory")
#define CP_WAIT1()  asm volatile("cp.async.wait_group 1;" ::: "memory")

// ============================ scratch ============================
static constexpr long long EL_X   = 8192LL * 1024;
static constexpr long long EL_W1C = 1024LL * 1024;
static constexpr long long EL_S   = 512LL * 512;
static constexpr long long EL_TT  = 8192LL * 1024;
static constexpr long long EL_ACT = 8192LL * 512;

static constexpr long long O_XHI    = 0;
static constexpr long long O_XLO    = O_XHI + EL_X;
static constexpr long long O_W1C_HI = O_XLO + EL_X;
static constexpr long long O_W1C_LO = O_W1C_HI + EL_W1C;
static constexpr long long O_W2H_HI = O_W1C_LO + EL_W1C;
static constexpr long long O_W2H_LO = O_W2H_HI + EL_S;
static constexpr long long O_WB_HI  = O_W2H_LO + EL_S;
static constexpr long long O_WB_LO  = O_WB_HI + EL_S;
static constexpr long long O_W2DT_HI= O_WB_LO + EL_S;
static constexpr long long O_W2DT_LO= O_W2DT_HI + EL_S;
static constexpr long long O_WP_HI  = O_W2DT_LO + EL_S;
static constexpr long long O_WP_LO  = O_WP_HI + EL_S;
static constexpr long long O_TT_HI  = O_WP_LO + EL_S;
static constexpr long long O_TT_LO  = O_TT_HI + EL_TT;
static constexpr long long O_HD_HI  = O_TT_LO + EL_TT;
static constexpr long long O_HD_LO  = O_HD_HI + EL_ACT;
static constexpr long long O_DW_HI  = O_HD_LO + EL_ACT;
static constexpr long long O_DW_LO  = O_DW_HI + EL_ACT;
static constexpr long long BF_TOTAL = O_DW_LO + EL_ACT;

__device__ __align__(1024) __nv_bfloat16 g_bf[BF_TOTAL];
__device__ __align__(1024) float g_vec[3 * 1024];    // b1c[1024], b2h_p[512], bpr[512]

// ============================ prep kernels ============================
__device__ __forceinline__ void split_store(__nv_bfloat16* hi, __nv_bfloat16* lo,
                                            long long idx, float v)
{
    __nv_bfloat16 h = __float2bfloat16(v);
    hi[idx] = h;
    lo[idx] = __float2bfloat16(v - __bfloat162float(h));
}

// X split: [8192,1024] fp32 -> hi/lo bf16 (no padding needed)
__global__ void split_x(const float* __restrict__ X,
                        __nv_bfloat16* __restrict__ hi, __nv_bfloat16* __restrict__ lo)
{
    long long idx = (long long)blockIdx.x * blockDim.x + threadIdx.x;
    float4 v = *(const float4*)(X + idx * 4);
    split_store(hi, lo, idx * 4 + 0, v.x);
    split_store(hi, lo, idx * 4 + 1, v.y);
    split_store(hi, lo, idx * 4 + 2, v.z);
    split_store(hi, lo, idx * 4 + 3, v.w);
}

// All weight pads/splits + bias pads + bpr matvec in ONE kernel.
// Block map (256 threads each):
//   [0,2048)      w1h -> W1C rows [0,512)        (512x1024)
//   [2048,4096)   w1d -> W1C rows [512,1024)
//   [4096,5120)   w2h -> W2H                     (512x512)
//   [5120,6144)   Wb  -> WB
//   [6144,7168)   w2d^T -> W2DT
//   [7168,7680)   bpr[j] = Wb[j,:] . b2d         (one block per j)
//   [7680,7686)   bias pads: b1c (1024), b2h_p (512)
__global__ void prep_weights(
    const float* __restrict__ w1h, const float* __restrict__ w1d,
    const float* __restrict__ w2h, const float* __restrict__ Wb,
    const float* __restrict__ w2d,
    const float* __restrict__ b1h, const float* __restrict__ b1d,
    const float* __restrict__ b2h, const float* __restrict__ b2d,
    __nv_bfloat16* __restrict__ W1Ch, __nv_bfloat16* __restrict__ W1Cl,
    __nv_bfloat16* __restrict__ W2Hh, __nv_bfloat16* __restrict__ W2Hl,
    __nv_bfloat16* __restrict__ WBh,  __nv_bfloat16* __restrict__ WBl,
    __nv_bfloat16* __restrict__ W2DTh,__nv_bfloat16* __restrict__ W2DTl,
    float* __restrict__ b1c, float* __restrict__ b2h_p, float* __restrict__ bpr)
{
    const int bx = blockIdx.x;
    const int tid = threadIdx.x;

    if (bx < 4096) {
        // w1h / w1d pad-split into W1C [1024,1024]
        const int half = bx >> 11;                  // 0: w1h, 1: w1d
        const long long e = ((long long)(bx & 2047)) * 256 + tid;   // < 512*1024
        const int r = (int)(e >> 10), c = (int)(e & 1023);
        const float* src = half ? w1d : w1h;
        float v = (r < 500) ? src[(long long)r * 1024 + c] : 0.0f;
        split_store(W1Ch, W1Cl, (long long)half * 512 * 1024 + e, v);
    } else if (bx < 7168) {
        const int sec = (bx - 4096) >> 10;          // 0: w2h, 1: Wb, 2: w2d^T
        const long long e = ((long long)((bx - 4096) & 1023)) * 256 + tid;  // < 512*512
        const int r = (int)(e >> 9), c = (int)(e & 511);
        float v = 0.0f;
        if (sec == 0) { if (r < 500 && c < 500) v = w2h[r * 500 + c]; split_store(W2Hh, W2Hl, e, v); }
        else if (sec == 1) { if (r < 500 && c < 500) v = Wb[r * 500 + c]; split_store(WBh, WBl, e, v); }
        else { if (r < 500 && c < 500) v = w2d[c * 500 + r]; split_store(W2DTh, W2DTl, e, v); }
    } else if (bx < 7680) {
        // bpr[j] = sum_a Wb[j,a]*b2d[a]
        const int j = bx - 7168;
        __shared__ float red[8];
        float s = 0.0f;
        if (j < 500)
            for (int a = tid; a < 500; a += 256) s += Wb[j * 500 + a] * b2d[a];
#pragma unroll
        for (int o = 16; o > 0; o >>= 1) s += __shfl_down_sync(0xffffffffu, s, o);
        if ((tid & 31) == 0) red[tid >> 5] = s;
        __syncthreads();
        if (tid == 0) {
            float t = 0.0f;
#pragma unroll
            for (int q = 0; q < 8; q++) t += red[q];
            bpr[j] = (j < 500) ? t : 0.0f;
        }
    } else {
        const int e = (bx - 7680) * 256 + tid;      // < 1536
        if (e < 1024) {
            const int c = e & 511;
            b1c[e] = (c < 500) ? ((e < 512) ? b1h[c] : b1d[c]) : 0.0f;
        } else if (e < 1536) {
            const int c = e - 1024;
            b2h_p[c] = (c < 500) ? b2h[c] : 0.0f;
        }
    }
}

// ============================ main GEMM ============================
// C[M,N] = A[M,K] @ B[N,K]^T via 3-pass bf16 split, fp32 accum.
// CTA 128x128, 8 warps (4 M x 2 N), warp tile 32x64, BK=32, 2 CTAs/SM.
// dual=1: blockIdx.z selects operand set (stage-2 merge).
#define SROW 40
#define TILEB (128 * SROW * 2)
#define OFF_AH 0
#define OFF_AL (1 * TILEB)
#define OFF_BH (2 * TILEB)
#define OFF_BL (3 * TILEB)
#define STAGE  (4 * TILEB)           // 40960
#define SMEMSZ (2 * STAGE)           // 81920 -> 2 CTAs/SM

__device__ __forceinline__ void issue_tile(
    uint32_t sbase, const char* Ah, const char* Al, const char* Bh, const char* Bl,
    int lda, int ldb, int row0, int col0, int k0, int tid)
{
#pragma unroll
    for (int i = 0; i < 2; i++) {
        const int pos = tid + i * 256;
        const int r = pos >> 2, ch = pos & 3;
        const uint32_t so = (uint32_t)(r * (SROW * 2) + ch * 16);
        const size_t gA = ((size_t)(row0 + r) * lda + k0 + ch * 8) * 2;
        const size_t gB = ((size_t)(col0 + r) * ldb + k0 + ch * 8) * 2;
        CP16(sbase + OFF_AH + so, Ah + gA);
        CP16(sbase + OFF_AL + so, Al + gA);
        CP16(sbase + OFF_BH + so, Bh + gB);
        CP16(sbase + OFF_BL + so, Bl + gB);
    }
}

__global__ void __launch_bounds__(256, 2) gemm_mma3(
    const __nv_bfloat16* __restrict__ Ahi, const __nv_bfloat16* __restrict__ Alo,
    int lda, long long sA,
    const __nv_bfloat16* __restrict__ Bhi, const __nv_bfloat16* __restrict__ Blo,
    const __nv_bfloat16* __restrict__ Bhi2, const __nv_bfloat16* __restrict__ Blo2,
    int ldb, long long sB,
    void* __restrict__ Cout, void* __restrict__ Cout2,
    void* __restrict__ CoutB, void* __restrict__ Cout2B,
    int ldc, long long sC,
    int K, const float* __restrict__ bias, const float* __restrict__ bias2,
    int biasMode, int doRelu, int splitOut, int dual)
{
    extern __shared__ char smem[];
    const uint32_t sb = smem_u32(smem);
    const int tid  = threadIdx.x;
    const int lane = tid & 31;
    const int wid  = tid >> 5;
    const int wm   = wid & 3;
    const int wn   = wid >> 2;
    const int row0 = blockIdx.y * 128;
    const int col0 = blockIdx.x * 128;

    const int z = blockIdx.z;
    const char *Ah, *Al, *Bh, *Bl;
    const float* bvp = bias;
    void *Co = Cout, *Co2 = Cout2;
    if (dual && z) {
        // second operand set: A shifted by 512 columns, B/bias/C from set 2
        Ah = (const char*)(Ahi + 512);
        Al = (const char*)(Alo + 512);
        Bh = (const char*)Bhi2;  Bl = (const char*)Blo2;
        bvp = bias2;  Co = CoutB;  Co2 = Cout2B;
    } else {
        Ah = (const char*)(Ahi + (long long)z * sA);
        Al = (const char*)(Alo + (long long)z * sA);
        Bh = (const char*)(Bhi + (long long)z * sB);
        Bl = (const char*)(Blo + (long long)z * sB);
    }

    float acc[2][8][4];
#pragma unroll
    for (int mt = 0; mt < 2; mt++)
#pragma unroll
        for (int nt = 0; nt < 8; nt++)
#pragma unroll
            for (int q = 0; q < 4; q++) acc[mt][nt][q] = 0.0f;

    const int frow = (lane & 7) | (((lane >> 3) & 1) << 3);
    const int fkc  = (lane >> 4) * 8;

    const int T = K / 32;
    issue_tile(sb, Ah, Al, Bh, Bl, lda, ldb, row0, col0, 0, tid);
    CP_COMMIT();

    for (int t = 0; t < T; ++t) {
        if (t + 1 < T) {
            issue_tile(sb + ((t + 1) & 1) * STAGE, Ah, Al, Bh, Bl,
                       lda, ldb, row0, col0, (t + 1) * 32, tid);
            CP_COMMIT();
            CP_WAIT1();
        } else {
            CP_WAIT0();
        }
        __syncthreads();

        const uint32_t st = sb + (t & 1) * STAGE;
#pragma unroll
        for (int kh = 0; kh < 2; ++kh) {
            const int kb = kh * 16 + fkc;
            uint32_t ah[2][4], al[2][4];
#pragma unroll
            for (int mt = 0; mt < 2; mt++) {
                const uint32_t off = (uint32_t)(((wm * 32 + mt * 16 + frow) * SROW + kb) * 2);
                ldsm4(ah[mt], st + OFF_AH + off);
                ldsm4(al[mt], st + OFF_AL + off);
            }
#pragma unroll
            for (int bt = 0; bt < 4; bt++) {
                uint32_t bh[4], bl[4];
                const uint32_t off = (uint32_t)(((wn * 64 + bt * 16 + frow) * SROW + kb) * 2);
                ldsm4(bh, st + OFF_BH + off);
                ldsm4(bl, st + OFF_BL + off);
                // pass-major order: all hh, then hl, then lh -> RAW distance 4
#pragma unroll
                for (int mt = 0; mt < 2; mt++)
#pragma unroll
                    for (int p = 0; p < 2; p++)
                        mma_bf16(acc[mt][bt * 2 + p], ah[mt], bh[p], bh[p + 2]);
#pragma unroll
                for (int mt = 0; mt < 2; mt++)
#pragma unroll
                    for (int p = 0; p < 2; p++)
                        mma_bf16(acc[mt][bt * 2 + p], ah[mt], bl[p], bl[p + 2]);
#pragma unroll
                for (int mt = 0; mt < 2; mt++)
#pragma unroll
                    for (int p = 0; p < 2; p++)
                        mma_bf16(acc[mt][bt * 2 + p], al[mt], bh[p], bh[p + 2]);
            }
        }
        __syncthreads();
    }

    // ============================ epilogue ============================
    char* Cb  = (char*)Co + (dual ? 0 : (size_t)z * sC * (splitOut ? 2 : 4));
    char* Cb2 = splitOut ? ((char*)Co2 + (dual ? 0 : (size_t)z * sC * 2)) : nullptr;

#pragma unroll
    for (int mt = 0; mt < 2; mt++) {
        const long long r0 = row0 + wm * 32 + mt * 16 + (lane >> 2);
#pragma unroll
        for (int nt = 0; nt < 8; nt++) {
            const int c0 = col0 + wn * 64 + nt * 8 + (lane & 3) * 2;
            float b0 = 0.0f, b1 = 0.0f;
            if (biasMode == 1)      { b0 = bvp[c0]; b1 = bvp[c0 + 1]; }
            else if (biasMode == 2) { b0 = bvp[0];  b1 = bvp[0]; }

            float v00 = acc[mt][nt][0] + b0, v01 = acc[mt][nt][1] + b1;
            float v10 = acc[mt][nt][2] + b0, v11 = acc[mt][nt][3] + b1;
            if (doRelu) {
                v00 = fmaxf(v00, 0.0f); v01 = fmaxf(v01, 0.0f);
                v10 = fmaxf(v10, 0.0f); v11 = fmaxf(v11, 0.0f);
            }

            if (splitOut) {
                __nv_bfloat16 h00 = __float2bfloat16(v00), h01 = __float2bfloat16(v01);
                __nv_bfloat16 h10 = __float2bfloat16(v10), h11 = __float2bfloat16(v11);
                uint32_t ph0 = (uint32_t)__bfloat16_as_ushort(h00) |
                               ((uint32_t)__bfloat16_as_ushort(h01) << 16);
                uint32_t ph1 = (uint32_t)__bfloat16_as_ushort(h10) |
                               ((uint32_t)__bfloat16_as_ushort(h11) << 16);
                __nv_bfloat16 l00 = __float2bfloat16(v00 - __bfloat162float(h00));
                __nv_bfloat16 l01 = __float2bfloat16(v01 - __bfloat162float(h01));
                __nv_bfloat16 l10 = __float2bfloat16(v10 - __bfloat162float(h10));
                __nv_bfloat16 l11 = __float2bfloat16(v11 - __bfloat162float(h11));
                uint32_t pl0 = (uint32_t)__bfloat16_as_ushort(l00) |
                               ((uint32_t)__bfloat16_as_ushort(l01) << 16);
                uint32_t pl1 = (uint32_t)__bfloat16_as_ushort(l10) |
                               ((uint32_t)__bfloat16_as_ushort(l11) << 16);
                *(uint32_t*)(Cb  + (r0 * ldc + c0) * 2)       = ph0;
                *(uint32_t*)(Cb  + ((r0 + 8) * ldc + c0) * 2) = ph1;
                *(uint32_t*)(Cb2 + (r0 * ldc + c0) * 2)       = pl0;
                *(uint32_t*)(Cb2 + ((r0 + 8) * ldc + c0) * 2) = pl1;
            } else {
                *(float2*)(Cb + (r0 * ldc + c0) * 4)       = make_float2(v00, v01);
                *(float2*)(Cb + ((r0 + 8) * ldc + c0) * 4) = make_float2(v10, v11);
            }
        }
    }
}

// ============================ launch ============================
extern "C" void kernel_launch(void* const* d_in, const int* in_sizes, int n_in,
                              void* d_out, int out_size)
{
    const float* X   = (const float*)d_in[0];
    const float* w1h = (const float*)d_in[1];
    const float* b1h = (const float*)d_in[2];
    const float* w2h = (const float*)d_in[3];
    const float* b2h = (const float*)d_in[4];
    const float* w1d = (const float*)d_in[5];
    const float* b1d = (const float*)d_in[6];
    const float* w2d = (const float*)d_in[7];
    const float* b2d = (const float*)d_in[8];
    const float* Wb  = (const float*)d_in[9];
    const float* bb  = (const float*)d_in[10];
    float* out = (float*)d_out;

    __nv_bfloat16* bf = nullptr;
    cudaGetSymbolAddress((void**)&bf, g_bf);
    float* vecs = nullptr;
    cudaGetSymbolAddress((void**)&vecs, g_vec);

    __nv_bfloat16 *Xhi = bf + O_XHI,     *Xlo = bf + O_XLO;
    __nv_bfloat16 *W1Ch = bf + O_W1C_HI, *W1Cl = bf + O_W1C_LO;
    __nv_bfloat16 *W2Hh = bf + O_W2H_HI, *W2Hl = bf + O_W2H_LO;
    __nv_bfloat16 *WBh = bf + O_WB_HI,   *WBl = bf + O_WB_LO;
    __nv_bfloat16 *W2DTh = bf + O_W2DT_HI, *W2DTl = bf + O_W2DT_LO;
    __nv_bfloat16 *WPh = bf + O_WP_HI,   *WPl = bf + O_WP_LO;
    __nv_bfloat16 *TTh = bf + O_TT_HI,   *TTl = bf + O_TT_LO;
    __nv_bfloat16 *HDh = bf + O_HD_HI,   *HDl = bf + O_HD_LO;
    __nv_bfloat16 *DWh = bf + O_DW_HI,   *DWl = bf + O_DW_LO;

    float* b1c   = vecs + 0 * 1024;
    float* b2h_p = vecs + 1 * 1024;
    float* bpr   = vecs + 2 * 1024;

    cudaFuncSetAttribute(gemm_mma3, cudaFuncAttributeMaxDynamicSharedMemorySize, SMEMSZ);

    // launch 0: X split
    split_x<<<(unsigned)(EL_X / 4 / 256), 256>>>(X, Xhi, Xlo);
    // launch 1: all weight/bias prep
    prep_weights<<<7686, 256>>>(w1h, w1d, w2h, Wb, w2d, b1h, b1d, b2h, b2d,
                                W1Ch, W1Cl, W2Hh, W2Hl, WBh, WBl, W2DTh, W2DTl,
                                b1c, b2h_p, bpr);

    // launch 2: W' = Wb @ w2d
    {
        dim3 g(4, 4, 1);
        gemm_mma3<<<g, 256, SMEMSZ>>>(WBh, WBl, 512, 0, W2DTh, W2DTl, nullptr, nullptr,
                                      512, 0, WPh, WPl, nullptr, nullptr, 512, 0,
                                      512, nullptr, nullptr, 0, 0, 1, 0);
    }
    // launch 3: stage 1 merged: TT = ReLU(X @ W1C^T + b1c), N=1024
    {
        dim3 g(8, 64, 1);
        gemm_mma3<<<g, 256, SMEMSZ>>>(Xhi, Xlo, 1024, 0, W1Ch, W1Cl, nullptr, nullptr,
                                      1024, 0, TTh, TTl, nullptr, nullptr, 1024, 0,
                                      1024, b1c, nullptr, 1, 1, 1, 0);
    }
    // launch 4: stage 2 merged (z=0: head, z=1: depW)
    {
        dim3 g(4, 64, 2);
        gemm_mma3<<<g, 256, SMEMSZ>>>(TTh, TTl, 1024, 0,
                                      W2Hh, W2Hl, WPh, WPl, 512, 0,
                                      HDh, HDl, DWh, DWl, 512, 0,
                                      512, b2h_p, bpr, 1, 0, 1, 1);
    }
    // launch 5: final batched: out[b] = head[b] @ depW[b]^T + bb  -> PROFILED by ncu -s 5
    {
        dim3 g(4, 4, 16);
        const long long sAB = 512LL * 512;
        gemm_mma3<<<g, 256, SMEMSZ>>>(HDh, HDl, 512, sAB, DWh, DWl, nullptr, nullptr,
                                      512, sAB, out, nullptr, nullptr, nullptr, 512, sAB,
                                      512, bb, nullptr, 2, 0, 0, 0);
    }
}

// round 10
// speedup vs baseline: 3.2413x; 1.3436x over previous
#include <cuda_runtime.h>
#include <cuda_fp16.h>
#include <cstdint>

// BiaffineAttention  B=16, S=512, H=1024, A=500 (padded to 512)
// GEMMs via mma.sync fp16 (m16n8k16), split precision, fp32 accum.
// Weights pre-scaled by 32 (keeps fp16-lo limbs out of subnormal range),
// descale via cScale in epilogue.
//   TT   = ReLU(X @ [w1h;w1d]^T + b1c)   2-pass (A-lo dropped)  -> fp16 hi only
//   W'   = Wb @ w2d (3-pass) ; b' = Wb @ b2d
//   head = TT[:, :512] @ w2h^T + b2h     2-pass -> fp16 hi+lo   (merged z=0)
//   depW = TT[:, 512:] @ W'^T + b'       2-pass -> fp16 hi+lo   (merged z=1)
//   out[b] = head[b] @ depW[b]^T + bb    3-pass (fp32 out)

// ============================ PTX helpers ============================
__device__ __forceinline__ uint32_t smem_u32(const void* p) {
    uint32_t a;
    asm("{ .reg .u64 t; cvta.to.shared.u64 t, %1; cvt.u32.u64 %0, t; }"
        : "=r"(a) : "l"(p));
    return a;
}

__device__ __forceinline__ void ldsm4(uint32_t* r, uint32_t addr) {
    asm volatile("ldmatrix.sync.aligned.m8n8.x4.shared.b16 {%0,%1,%2,%3}, [%4];"
        : "=r"(r[0]), "=r"(r[1]), "=r"(r[2]), "=r"(r[3]) : "r"(addr));
}

__device__ __forceinline__ void mma_f16(float* c, const uint32_t* a,
                                        uint32_t b0, uint32_t b1) {
    asm volatile("mma.sync.aligned.m16n8k16.row.col.f32.f16.f16.f32 "
        "{%0,%1,%2,%3}, {%4,%5,%6,%7}, {%8,%9}, {%0,%1,%2,%3};"
        : "+f"(c[0]), "+f"(c[1]), "+f"(c[2]), "+f"(c[3])
        : "r"(a[0]), "r"(a[1]), "r"(a[2]), "r"(a[3]), "r"(b0), "r"(b1));
}

#define CP16(s, g) \
    asm volatile("cp.async.cg.shared.global [%0], [%1], 16;" :: "r"(s), "l"(g))
#define CP_COMMIT() asm volatile("cp.async.commit_group;" ::: "memory")
#define CP_WAIT0()  asm volatile("cp.async.wait_group 0;" ::: "memory")
#define CP_WAIT1()  asm volatile("cp.async.wait_group 1;" ::: "memory")

// ============================ scratch ============================
static constexpr long long EL_X   = 8192LL * 1024;
static constexpr long long EL_W1C = 1024LL * 1024;
static constexpr long long EL_S   = 512LL * 512;
static constexpr long long EL_TT  = 8192LL * 1024;
static constexpr long long EL_ACT = 8192LL * 512;

static constexpr long long O_XH     = 0;
static constexpr long long O_W1C_H  = O_XH + EL_X;
static constexpr long long O_W1C_L  = O_W1C_H + EL_W1C;
static constexpr long long O_W2H_H  = O_W1C_L + EL_W1C;
static constexpr long long O_W2H_L  = O_W2H_H + EL_S;
static constexpr long long O_WB_H   = O_W2H_L + EL_S;
static constexpr long long O_WB_L   = O_WB_H + EL_S;
static constexpr long long O_W2DT_H = O_WB_L + EL_S;
static constexpr long long O_W2DT_L = O_W2DT_H + EL_S;
static constexpr long long O_WP_H   = O_W2DT_L + EL_S;
static constexpr long long O_WP_L   = O_WP_H + EL_S;
static constexpr long long O_TT_H   = O_WP_L + EL_S;
static constexpr long long O_HD_H   = O_TT_H + EL_TT;
static constexpr long long O_HD_L   = O_HD_H + EL_ACT;
static constexpr long long O_DW_H   = O_HD_L + EL_ACT;
static constexpr long long O_DW_L   = O_DW_H + EL_ACT;
static constexpr long long H_TOTAL  = O_DW_L + EL_ACT;

__device__ __align__(1024) __half g_h[H_TOTAL];
__device__ __align__(1024) float g_vec[3 * 1024];   // b1c[1024], b2h_p[512], bpr[512]

// ============================ prep kernels ============================
__device__ __forceinline__ void split_h(__half* hi, __half* lo, long long i, float v)
{
    __half h = __float2half_rn(v);
    hi[i] = h;
    lo[i] = __float2half_rn(v - __half2float(h));
}

// X -> fp16 (hi only; A-lo unused in 2-pass stages)
__global__ void conv_x(const float* __restrict__ X, __half* __restrict__ Xh)
{
    long long idx = ((long long)blockIdx.x * blockDim.x + threadIdx.x) * 4;
    float4 v = *(const float4*)(X + idx);
    __half h[4] = {__float2half_rn(v.x), __float2half_rn(v.y),
                   __float2half_rn(v.z), __float2half_rn(v.w)};
    *(uint2*)(Xh + idx) = *(uint2*)h;
}

#define WSCALE 32.0f
#define CDESC  0.03125f

// all weight pads/splits (scaled by 32) + bias pads + bpr matvec
__global__ void prep_weights(
    const float* __restrict__ w1h, const float* __restrict__ w1d,
    const float* __restrict__ w2h, const float* __restrict__ Wb,
    const float* __restrict__ w2d,
    const float* __restrict__ b1h, const float* __restrict__ b1d,
    const float* __restrict__ b2h, const float* __restrict__ b2d,
    __half* __restrict__ W1Ch, __half* __restrict__ W1Cl,
    __half* __restrict__ W2Hh, __half* __restrict__ W2Hl,
    __half* __restrict__ WBh,  __half* __restrict__ WBl,
    __half* __restrict__ W2DTh,__half* __restrict__ W2DTl,
    float* __restrict__ b1c, float* __restrict__ b2h_p, float* __restrict__ bpr)
{
    const int bx = blockIdx.x;
    const int tid = threadIdx.x;

    if (bx < 4096) {
        const int half_ = bx >> 11;
        const long long e = ((long long)(bx & 2047)) * 256 + tid;
        const int r = (int)(e >> 10);
        const float* src = half_ ? w1d : w1h;
        float v = (r < 500) ? WSCALE * src[(long long)r * 1024 + (e & 1023)] : 0.0f;
        split_h(W1Ch, W1Cl, (long long)half_ * 512 * 1024 + e, v);
    } else if (bx < 7168) {
        const int sec = (bx - 4096) >> 10;
        const long long e = ((long long)((bx - 4096) & 1023)) * 256 + tid;
        const int r = (int)(e >> 9), c = (int)(e & 511);
        float v = 0.0f;
        if (sec == 0) { if (r < 500 && c < 500) v = WSCALE * w2h[r * 500 + c]; split_h(W2Hh, W2Hl, e, v); }
        else if (sec == 1) { if (r < 500 && c < 500) v = WSCALE * Wb[r * 500 + c]; split_h(WBh, WBl, e, v); }
        else { if (r < 500 && c < 500) v = WSCALE * w2d[c * 500 + r]; split_h(W2DTh, W2DTl, e, v); }
    } else if (bx < 7680) {
        const int j = bx - 7168;
        __shared__ float red[8];
        float s = 0.0f;
        if (j < 500)
            for (int a = tid; a < 500; a += 256) s += Wb[j * 500 + a] * b2d[a];
#pragma unroll
        for (int o = 16; o > 0; o >>= 1) s += __shfl_down_sync(0xffffffffu, s, o);
        if ((tid & 31) == 0) red[tid >> 5] = s;
        __syncthreads();
        if (tid == 0) {
            float t = 0.0f;
#pragma unroll
            for (int q = 0; q < 8; q++) t += red[q];
            bpr[j] = (j < 500) ? t : 0.0f;
        }
    } else {
        const int e = (bx - 7680) * 256 + tid;
        if (e < 1024) {
            const int c = e & 511;
            b1c[e] = (c < 500) ? ((e < 512) ? b1h[c] : b1d[c]) : 0.0f;
        } else if (e < 1536) {
            const int c = e - 1024;
            b2h_p[c] = (c < 500) ? b2h[c] : 0.0f;
        }
    }
}

// ============================ main GEMM ============================
// C[M,N] = A[M,K] @ B[N,K]^T, PASSES=2: Ahi@(Bhi+Blo); PASSES=3: + Alo@Bhi.
// CTA 128x128, 8 warps (4Mx2N), warp 32x64, BK=32, 2 CTAs/SM.
#define SROW 40
#define TILEB (128 * SROW * 2)
#define OFF_AH 0
#define OFF_AL (1 * TILEB)
#define OFF_BH (2 * TILEB)
#define OFF_BL (3 * TILEB)
#define STAGE  (4 * TILEB)
#define SMEMSZ (2 * STAGE)

template<int PASSES>
__device__ __forceinline__ void issue_tile(
    uint32_t sbase, const char* Ah, const char* Al, const char* Bh, const char* Bl,
    int lda, int ldb, int row0, int col0, int k0, int tid)
{
#pragma unroll
    for (int i = 0; i < 2; i++) {
        const int pos = tid + i * 256;
        const int r = pos >> 2, ch = pos & 3;
        const uint32_t so = (uint32_t)(r * (SROW * 2) + ch * 16);
        const size_t gA = ((size_t)(row0 + r) * lda + k0 + ch * 8) * 2;
        const size_t gB = ((size_t)(col0 + r) * ldb + k0 + ch * 8) * 2;
        CP16(sbase + OFF_AH + so, Ah + gA);
        if (PASSES == 3) CP16(sbase + OFF_AL + so, Al + gA);
        CP16(sbase + OFF_BH + so, Bh + gB);
        CP16(sbase + OFF_BL + so, Bl + gB);
    }
}

template<int PASSES>
__global__ void __launch_bounds__(256, 2) gemm_mma(
    const __half* __restrict__ Ahi, const __half* __restrict__ Alo,
    int lda, long long sA,
    const __half* __restrict__ Bhi, const __half* __restrict__ Blo,
    const __half* __restrict__ Bhi2, const __half* __restrict__ Blo2,
    int ldb, long long sB,
    void* __restrict__ Cout, void* __restrict__ Cout2,
    void* __restrict__ CoutB, void* __restrict__ Cout2B,
    int ldc, long long sC,
    int K, const float* __restrict__ bias, const float* __restrict__ bias2,
    int biasMode, float cScale, int doRelu, int splitOut, int dual)
{
    extern __shared__ char smem[];
    const uint32_t sb = smem_u32(smem);
    const int tid  = threadIdx.x;
    const int lane = tid & 31;
    const int wid  = tid >> 5;
    const int wm   = wid & 3;
    const int wn   = wid >> 2;
    const int row0 = blockIdx.y * 128;
    const int col0 = blockIdx.x * 128;

    const int z = blockIdx.z;
    const char *Ah, *Al, *Bh, *Bl;
    const float* bvp = bias;
    void *Co = Cout, *Co2 = Cout2;
    if (dual && z) {
        Ah = (const char*)(Ahi + 512);
        Al = (const char*)(Alo ? Alo + 512 : nullptr);
        Bh = (const char*)Bhi2;  Bl = (const char*)Blo2;
        bvp = bias2;  Co = CoutB;  Co2 = Cout2B;
    } else {
        Ah = (const char*)(Ahi + (long long)z * sA);
        Al = (const char*)(Alo ? Alo + (long long)z * sA : nullptr);
        Bh = (const char*)(Bhi + (long long)z * sB);
        Bl = (const char*)(Blo + (long long)z * sB);
    }

    float acc[2][8][4];
#pragma unroll
    for (int mt = 0; mt < 2; mt++)
#pragma unroll
        for (int nt = 0; nt < 8; nt++)
#pragma unroll
            for (int q = 0; q < 4; q++) acc[mt][nt][q] = 0.0f;

    const int frow = (lane & 7) | (((lane >> 3) & 1) << 3);
    const int fkc  = (lane >> 4) * 8;

    const int T = K / 32;
    issue_tile<PASSES>(sb, Ah, Al, Bh, Bl, lda, ldb, row0, col0, 0, tid);
    CP_COMMIT();

    for (int t = 0; t < T; ++t) {
        if (t + 1 < T) {
            issue_tile<PASSES>(sb + ((t + 1) & 1) * STAGE, Ah, Al, Bh, Bl,
                               lda, ldb, row0, col0, (t + 1) * 32, tid);
            CP_COMMIT();
            CP_WAIT1();
        } else {
            CP_WAIT0();
        }
        __syncthreads();

        const uint32_t st = sb + (t & 1) * STAGE;
#pragma unroll
        for (int kh = 0; kh < 2; ++kh) {
            const int kb = kh * 16 + fkc;
            uint32_t ah[2][4], al[2][4];
#pragma unroll
            for (int mt = 0; mt < 2; mt++) {
                const uint32_t off = (uint32_t)(((wm * 32 + mt * 16 + frow) * SROW + kb) * 2);
                ldsm4(ah[mt], st + OFF_AH + off);
                if (PASSES == 3) ldsm4(al[mt], st + OFF_AL + off);
            }
#pragma unroll
            for (int bt = 0; bt < 4; bt++) {
                uint32_t bh[4], bl[4];
                const uint32_t off = (uint32_t)(((wn * 64 + bt * 16 + frow) * SROW + kb) * 2);
                ldsm4(bh, st + OFF_BH + off);
                ldsm4(bl, st + OFF_BL + off);
#pragma unroll
                for (int mt = 0; mt < 2; mt++)
#pragma unroll
                    for (int p = 0; p < 2; p++)
                        mma_f16(acc[mt][bt * 2 + p], ah[mt], bh[p], bh[p + 2]);
#pragma unroll
                for (int mt = 0; mt < 2; mt++)
#pragma unroll
                    for (int p = 0; p < 2; p++)
                        mma_f16(acc[mt][bt * 2 + p], ah[mt], bl[p], bl[p + 2]);
                if (PASSES == 3) {
#pragma unroll
                    for (int mt = 0; mt < 2; mt++)
#pragma unroll
                        for (int p = 0; p < 2; p++)
                            mma_f16(acc[mt][bt * 2 + p], al[mt], bh[p], bh[p + 2]);
                }
            }
        }
        __syncthreads();
    }

    // ============================ epilogue ============================
    const int cbytes = (splitOut == 0) ? 4 : 2;
    char* Cb  = (char*)Co + (dual ? 0 : (size_t)z * sC * cbytes);
    char* Cb2 = (splitOut == 1) ? ((char*)Co2 + (dual ? 0 : (size_t)z * sC * 2)) : nullptr;

#pragma unroll
    for (int mt = 0; mt < 2; mt++) {
        const long long r0 = row0 + wm * 32 + mt * 16 + (lane >> 2);
#pragma unroll
        for (int nt = 0; nt < 8; nt++) {
            const int c0 = col0 + wn * 64 + nt * 8 + (lane & 3) * 2;
            float b0 = 0.0f, b1 = 0.0f;
            if (biasMode == 1)      { b0 = bvp[c0]; b1 = bvp[c0 + 1]; }
            else if (biasMode == 2) { b0 = bvp[0];  b1 = bvp[0]; }

            float v00 = fmaf(acc[mt][nt][0], cScale, b0);
            float v01 = fmaf(acc[mt][nt][1], cScale, b1);
            float v10 = fmaf(acc[mt][nt][2], cScale, b0);
            float v11 = fmaf(acc[mt][nt][3], cScale, b1);
            if (doRelu) {
                v00 = fmaxf(v00, 0.0f); v01 = fmaxf(v01, 0.0f);
                v10 = fmaxf(v10, 0.0f); v11 = fmaxf(v11, 0.0f);
            }

            if (splitOut == 0) {
                *(float2*)(Cb + (r0 * ldc + c0) * 4)       = make_float2(v00, v01);
                *(float2*)(Cb + ((r0 + 8) * ldc + c0) * 4) = make_float2(v10, v11);
            } else {
                __half h00 = __float2half_rn(v00), h01 = __float2half_rn(v01);
                __half h10 = __float2half_rn(v10), h11 = __float2half_rn(v11);
                uint32_t ph0 = (uint32_t)__half_as_ushort(h00) |
                               ((uint32_t)__half_as_ushort(h01) << 16);
                uint32_t ph1 = (uint32_t)__half_as_ushort(h10) |
                               ((uint32_t)__half_as_ushort(h11) << 16);
                *(uint32_t*)(Cb + (r0 * ldc + c0) * 2)       = ph0;
                *(uint32_t*)(Cb + ((r0 + 8) * ldc + c0) * 2) = ph1;
                if (splitOut == 1) {
                    __half l00 = __float2half_rn(v00 - __half2float(h00));
                    __half l01 = __float2half_rn(v01 - __half2float(h01));
                    __half l10 = __float2half_rn(v10 - __half2float(h10));
                    __half l11 = __float2half_rn(v11 - __half2float(h11));
                    uint32_t pl0 = (uint32_t)__half_as_ushort(l00) |
                                   ((uint32_t)__half_as_ushort(l01) << 16);
                    uint32_t pl1 = (uint32_t)__half_as_ushort(l10) |
                                   ((uint32_t)__half_as_ushort(l11) << 16);
                    *(uint32_t*)(Cb2 + (r0 * ldc + c0) * 2)       = pl0;
                    *(uint32_t*)(Cb2 + ((r0 + 8) * ldc + c0) * 2) = pl1;
                }
            }
        }
    }
}

// ============================ launch ============================
extern "C" void kernel_launch(void* const* d_in, const int* in_sizes, int n_in,
                              void* d_out, int out_size)
{
    const float* X   = (const float*)d_in[0];
    const float* w1h = (const float*)d_in[1];
    const float* b1h = (const float*)d_in[2];
    const float* w2h = (const float*)d_in[3];
    const float* b2h = (const float*)d_in[4];
    const float* w1d = (const float*)d_in[5];
    const float* b1d = (const float*)d_in[6];
    const float* w2d = (const float*)d_in[7];
    const float* b2d = (const float*)d_in[8];
    const float* Wb  = (const float*)d_in[9];
    const float* bb  = (const float*)d_in[10];
    float* out = (float*)d_out;

    __half* hb = nullptr;
    cudaGetSymbolAddress((void**)&hb, g_h);
    float* vecs = nullptr;
    cudaGetSymbolAddress((void**)&vecs, g_vec);

    __half *Xh    = hb + O_XH;
    __half *W1Ch  = hb + O_W1C_H,  *W1Cl  = hb + O_W1C_L;
    __half *W2Hh  = hb + O_W2H_H,  *W2Hl  = hb + O_W2H_L;
    __half *WBh   = hb + O_WB_H,   *WBl   = hb + O_WB_L;
    __half *W2DTh = hb + O_W2DT_H, *W2DTl = hb + O_W2DT_L;
    __half *WPh   = hb + O_WP_H,   *WPl   = hb + O_WP_L;
    __half *TTh   = hb + O_TT_H;
    __half *HDh   = hb + O_HD_H,   *HDl   = hb + O_HD_L;
    __half *DWh   = hb + O_DW_H,   *DWl   = hb + O_DW_L;

    float* b1c   = vecs + 0 * 1024;
    float* b2h_p = vecs + 1 * 1024;
    float* bpr   = vecs + 2 * 1024;

    cudaFuncSetAttribute(gemm_mma<2>, cudaFuncAttributeMaxDynamicSharedMemorySize, SMEMSZ);
    cudaFuncSetAttribute(gemm_mma<3>, cudaFuncAttributeMaxDynamicSharedMemorySize, SMEMSZ);

    // launch 0: X -> fp16
    conv_x<<<(unsigned)(EL_X / 4 / 256), 256>>>(X, Xh);
    // launch 1: weight prep (scaled x32) + biases
    prep_weights<<<7686, 256>>>(w1h, w1d, w2h, Wb, w2d, b1h, b1d, b2h, b2d,
                                W1Ch, W1Cl, W2Hh, W2Hl, WBh, WBl, W2DTh, W2DTl,
                                b1c, b2h_p, bpr);

    // launch 2: W' = Wb @ w2d (3-pass; operands scaled 32 each -> cScale stores 32*W')
    {
        dim3 g(4, 4, 1);
        gemm_mma<3><<<g, 256, SMEMSZ>>>(WBh, WBl, 512, 0, W2DTh, W2DTl, nullptr, nullptr,
                                        512, 0, WPh, WPl, nullptr, nullptr, 512, 0,
                                        512, nullptr, nullptr, 0, CDESC, 0, 1, 0);
    }
    // launch 3: stage 1: TT = ReLU(X @ W1C^T /32 + b1c), 2-pass, hi-only out
    {
        dim3 g(8, 64, 1);
        gemm_mma<2><<<g, 256, SMEMSZ>>>(Xh, nullptr, 1024, 0, W1Ch, W1Cl, nullptr, nullptr,
                                        1024, 0, TTh, nullptr, nullptr, nullptr, 1024, 0,
                                        1024, b1c, nullptr, 1, CDESC, 1, 2, 0);
    }
    // launch 4: stage 2 merged (z=0: head, z=1: depW), 2-pass, hi+lo out
    {
        dim3 g(4, 64, 2);
        gemm_mma<2><<<g, 256, SMEMSZ>>>(TTh, nullptr, 1024, 0,
                                        W2Hh, W2Hl, WPh, WPl, 512, 0,
                                        HDh, HDl, DWh, DWl, 512, 0,
                                        512, b2h_p, bpr, 1, CDESC, 0, 1, 1);
    }
    // launch 5: final batched: out[b] = head[b] @ depW[b]^T + bb, 3-pass, fp32 out
    {
        dim3 g(4, 4, 16);
        const long long sAB = 512LL * 512;
        gemm_mma<3><<<g, 256, SMEMSZ>>>(HDh, HDl, 512, sAB, DWh, DWl, nullptr, nullptr,
                                        512, sAB, out, nullptr, nullptr, nullptr, 512, sAB,
                                        512, bb, nullptr, 2, 1.0f, 0, 0, 0);
    }
}

// round 11
// speedup vs baseline: 3.2456x; 1.0013x over previous
#include <cuda_runtime.h>
#include <cuda_fp16.h>
#include <cstdint>

// BiaffineAttention  B=16, S=512, H=1024, A=500 (padded to 512)
// GEMMs via mma.sync fp16 (m16n8k16), split precision, fp32 accum.
// Weights pre-scaled by 32 (keeps fp16-lo limbs out of subnormal range),
// descale via cScale in epilogue.
//   TT   = ReLU(X @ [w1h;w1d]^T + b1c)   2-pass (A-lo dropped)  -> fp16 hi only
//   W'   = Wb @ w2d (3-pass) ; b' = Wb @ b2d
//   head = TT[:, :512] @ w2h^T + b2h     2-pass -> fp16 hi+lo   (merged z=0)
//   depW = TT[:, 512:] @ W'^T + b'       2-pass -> fp16 hi+lo   (merged z=1)
//   out[b] = head[b] @ depW[b]^T + bb    3-pass (fp32 out)

// ============================ PTX helpers ============================
__device__ __forceinline__ uint32_t smem_u32(const void* p) {
    uint32_t a;
    asm("{ .reg .u64 t; cvta.to.shared.u64 t, %1; cvt.u32.u64 %0, t; }"
        : "=r"(a) : "l"(p));
    return a;
}

__device__ __forceinline__ void ldsm4(uint32_t* r, uint32_t addr) {
    asm volatile("ldmatrix.sync.aligned.m8n8.x4.shared.b16 {%0,%1,%2,%3}, [%4];"
        : "=r"(r[0]), "=r"(r[1]), "=r"(r[2]), "=r"(r[3]) : "r"(addr));
}

__device__ __forceinline__ void mma_f16(float* c, const uint32_t* a,
                                        uint32_t b0, uint32_t b1) {
    asm volatile("mma.sync.aligned.m16n8k16.row.col.f32.f16.f16.f32 "
        "{%0,%1,%2,%3}, {%4,%5,%6,%7}, {%8,%9}, {%0,%1,%2,%3};"
        : "+f"(c[0]), "+f"(c[1]), "+f"(c[2]), "+f"(c[3])
        : "r"(a[0]), "r"(a[1]), "r"(a[2]), "r"(a[3]), "r"(b0), "r"(b1));
}

#define CP16(s, g) \
    asm volatile("cp.async.cg.shared.global [%0], [%1], 16;" :: "r"(s), "l"(g))
#define CP_COMMIT() asm volatile("cp.async.commit_group;" ::: "memory")
#define CP_WAIT0()  asm volatile("cp.async.wait_group 0;" ::: "memory")
#define CP_WAIT1()  asm volatile("cp.async.wait_group 1;" ::: "memory")

// ============================ scratch ============================
static constexpr long long EL_X   = 8192LL * 1024;
static constexpr long long EL_W1C = 1024LL * 1024;
static constexpr long long EL_S   = 512LL * 512;
static constexpr long long EL_TT  = 8192LL * 1024;
static constexpr long long EL_ACT = 8192LL * 512;

static constexpr long long O_XH     = 0;
static constexpr long long O_W1C_H  = O_XH + EL_X;
static constexpr long long O_W1C_L  = O_W1C_H + EL_W1C;
static constexpr long long O_W2H_H  = O_W1C_L + EL_W1C;
static constexpr long long O_W2H_L  = O_W2H_H + EL_S;
static constexpr long long O_WB_H   = O_W2H_L + EL_S;
static constexpr long long O_WB_L   = O_WB_H + EL_S;
static constexpr long long O_W2DT_H = O_WB_L + EL_S;
static constexpr long long O_W2DT_L = O_W2DT_H + EL_S;
static constexpr long long O_WP_H   = O_W2DT_L + EL_S;
static constexpr long long O_WP_L   = O_WP_H + EL_S;
static constexpr long long O_TT_H   = O_WP_L + EL_S;
static constexpr long long O_HD_H   = O_TT_H + EL_TT;
static constexpr long long O_HD_L   = O_HD_H + EL_ACT;
static constexpr long long O_DW_H   = O_HD_L + EL_ACT;
static constexpr long long O_DW_L   = O_DW_H + EL_ACT;
static constexpr long long H_TOTAL  = O_DW_L + EL_ACT;

__device__ __align__(1024) __half g_h[H_TOTAL];
__device__ __align__(1024) float g_vec[3 * 1024];   // b1c[1024], b2h_p[512], bpr[512]

// ============================ prep kernels ============================
__device__ __forceinline__ void split_h(__half* hi, __half* lo, long long i, float v)
{
    __half h = __float2half_rn(v);
    hi[i] = h;
    lo[i] = __float2half_rn(v - __half2float(h));
}

// X -> fp16 (hi only; A-lo unused in 2-pass stages)
__global__ void conv_x(const float* __restrict__ X, __half* __restrict__ Xh)
{
    long long idx = ((long long)blockIdx.x * blockDim.x + threadIdx.x) * 4;
    float4 v = *(const float4*)(X + idx);
    __half h[4] = {__float2half_rn(v.x), __float2half_rn(v.y),
                   __float2half_rn(v.z), __float2half_rn(v.w)};
    *(uint2*)(Xh + idx) = *(uint2*)h;
}

#define WSCALE 32.0f
#define CDESC  0.03125f

// all weight pads/splits (scaled by 32) + bias pads + bpr matvec
__global__ void prep_weights(
    const float* __restrict__ w1h, const float* __restrict__ w1d,
    const float* __restrict__ w2h, const float* __restrict__ Wb,
    const float* __restrict__ w2d,
    const float* __restrict__ b1h, const float* __restrict__ b1d,
    const float* __restrict__ b2h, const float* __restrict__ b2d,
    __half* __restrict__ W1Ch, __half* __restrict__ W1Cl,
    __half* __restrict__ W2Hh, __half* __restrict__ W2Hl,
    __half* __restrict__ WBh,  __half* __restrict__ WBl,
    __half* __restrict__ W2DTh,__half* __restrict__ W2DTl,
    float* __restrict__ b1c, float* __restrict__ b2h_p, float* __restrict__ bpr)
{
    const int bx = blockIdx.x;
    const int tid = threadIdx.x;

    if (bx < 4096) {
        const int half_ = bx >> 11;
        const long long e = ((long long)(bx & 2047)) * 256 + tid;
        const int r = (int)(e >> 10);
        const float* src = half_ ? w1d : w1h;
        float v = (r < 500) ? WSCALE * src[(long long)r * 1024 + (e & 1023)] : 0.0f;
        split_h(W1Ch, W1Cl, (long long)half_ * 512 * 1024 + e, v);
    } else if (bx < 7168) {
        const int sec = (bx - 4096) >> 10;
        const long long e = ((long long)((bx - 4096) & 1023)) * 256 + tid;
        const int r = (int)(e >> 9), c = (int)(e & 511);
        float v = 0.0f;
        if (sec == 0) { if (r < 500 && c < 500) v = WSCALE * w2h[r * 500 + c]; split_h(W2Hh, W2Hl, e, v); }
        else if (sec == 1) { if (r < 500 && c < 500) v = WSCALE * Wb[r * 500 + c]; split_h(WBh, WBl, e, v); }
        else { if (r < 500 && c < 500) v = WSCALE * w2d[c * 500 + r]; split_h(W2DTh, W2DTl, e, v); }
    } else if (bx < 7680) {
        const int j = bx - 7168;
        __shared__ float red[8];
        float s = 0.0f;
        if (j < 500)
            for (int a = tid; a < 500; a += 256) s += Wb[j * 500 + a] * b2d[a];
#pragma unroll
        for (int o = 16; o > 0; o >>= 1) s += __shfl_down_sync(0xffffffffu, s, o);
        if ((tid & 31) == 0) red[tid >> 5] = s;
        __syncthreads();
        if (tid == 0) {
            float t = 0.0f;
#pragma unroll
            for (int q = 0; q < 8; q++) t += red[q];
            bpr[j] = (j < 500) ? t : 0.0f;
        }
    } else {
        const int e = (bx - 7680) * 256 + tid;
        if (e < 1024) {
            const int c = e & 511;
            b1c[e] = (c < 500) ? ((e < 512) ? b1h[c] : b1d[c]) : 0.0f;
        } else if (e < 1536) {
            const int c = e - 1024;
            b2h_p[c] = (c < 500) ? b2h[c] : 0.0f;
        }
    }
}

// ============================ main GEMM ============================
// C[M,N] = A[M,K] @ B[N,K]^T, PASSES=2: Ahi@(Bhi+Blo); PASSES=3: + Alo@Bhi.
// CTA 128x128, 8 warps (4Mx2N), warp 32x64, BK=32, 2 CTAs/SM.
#define SROW 40
#define TILEB (128 * SROW * 2)
#define OFF_AH 0
#define OFF_AL (1 * TILEB)
#define OFF_BH (2 * TILEB)
#define OFF_BL (3 * TILEB)
#define STAGE  (4 * TILEB)
#define SMEMSZ (2 * STAGE)

template<int PASSES>
__device__ __forceinline__ void issue_tile(
    uint32_t sbase, const char* Ah, const char* Al, const char* Bh, const char* Bl,
    int lda, int ldb, int row0, int col0, int k0, int tid)
{
#pragma unroll
    for (int i = 0; i < 2; i++) {
        const int pos = tid + i * 256;
        const int r = pos >> 2, ch = pos & 3;
        const uint32_t so = (uint32_t)(r * (SROW * 2) + ch * 16);
        const size_t gA = ((size_t)(row0 + r) * lda + k0 + ch * 8) * 2;
        const size_t gB = ((size_t)(col0 + r) * ldb + k0 + ch * 8) * 2;
        CP16(sbase + OFF_AH + so, Ah + gA);
        if (PASSES == 3) CP16(sbase + OFF_AL + so, Al + gA);
        CP16(sbase + OFF_BH + so, Bh + gB);
        CP16(sbase + OFF_BL + so, Bl + gB);
    }
}

template<int PASSES>
__global__ void __launch_bounds__(256, 2) gemm_mma(
    const __half* __restrict__ Ahi, const __half* __restrict__ Alo,
    int lda, long long sA,
    const __half* __restrict__ Bhi, const __half* __restrict__ Blo,
    const __half* __restrict__ Bhi2, const __half* __restrict__ Blo2,
    int ldb, long long sB,
    void* __restrict__ Cout, void* __restrict__ Cout2,
    void* __restrict__ CoutB, void* __restrict__ Cout2B,
    int ldc, long long sC,
    int K, const float* __restrict__ bias, const float* __restrict__ bias2,
    int biasMode, float cScale, int doRelu, int splitOut, int dual)
{
    extern __shared__ char smem[];
    const uint32_t sb = smem_u32(smem);
    const int tid  = threadIdx.x;
    const int lane = tid & 31;
    const int wid  = tid >> 5;
    const int wm   = wid & 3;
    const int wn   = wid >> 2;
    const int row0 = blockIdx.y * 128;
    const int col0 = blockIdx.x * 128;

    const int z = blockIdx.z;
    const char *Ah, *Al, *Bh, *Bl;
    const float* bvp = bias;
    void *Co = Cout, *Co2 = Cout2;
    if (dual && z) {
        Ah = (const char*)(Ahi + 512);
        Al = (const char*)(Alo ? Alo + 512 : nullptr);
        Bh = (const char*)Bhi2;  Bl = (const char*)Blo2;
        bvp = bias2;  Co = CoutB;  Co2 = Cout2B;
    } else {
        Ah = (const char*)(Ahi + (long long)z * sA);
        Al = (const char*)(Alo ? Alo + (long long)z * sA : nullptr);
        Bh = (const char*)(Bhi + (long long)z * sB);
        Bl = (const char*)(Blo + (long long)z * sB);
    }

    float acc[2][8][4];
#pragma unroll
    for (int mt = 0; mt < 2; mt++)
#pragma unroll
        for (int nt = 0; nt < 8; nt++)
#pragma unroll
            for (int q = 0; q < 4; q++) acc[mt][nt][q] = 0.0f;

    const int frow = (lane & 7) | (((lane >> 3) & 1) << 3);
    const int fkc  = (lane >> 4) * 8;

    const int T = K / 32;
    issue_tile<PASSES>(sb, Ah, Al, Bh, Bl, lda, ldb, row0, col0, 0, tid);
    CP_COMMIT();

    for (int t = 0; t < T; ++t) {
        if (t + 1 < T) {
            issue_tile<PASSES>(sb + ((t + 1) & 1) * STAGE, Ah, Al, Bh, Bl,
                               lda, ldb, row0, col0, (t + 1) * 32, tid);
            CP_COMMIT();
            CP_WAIT1();
        } else {
            CP_WAIT0();
        }
        __syncthreads();

        const uint32_t st = sb + (t & 1) * STAGE;
#pragma unroll
        for (int kh = 0; kh < 2; ++kh) {
            const int kb = kh * 16 + fkc;
            uint32_t ah[2][4], al[2][4];
#pragma unroll
            for (int mt = 0; mt < 2; mt++) {
                const uint32_t off = (uint32_t)(((wm * 32 + mt * 16 + frow) * SROW + kb) * 2);
                ldsm4(ah[mt], st + OFF_AH + off);
                if (PASSES == 3) ldsm4(al[mt], st + OFF_AL + off);
            }
#pragma unroll
            for (int bt = 0; bt < 4; bt++) {
                uint32_t bh[4], bl[4];
                const uint32_t off = (uint32_t)(((wn * 64 + bt * 16 + frow) * SROW + kb) * 2);
                ldsm4(bh, st + OFF_BH + off);
                ldsm4(bl, st + OFF_BL + off);
#pragma unroll
                for (int mt = 0; mt < 2; mt++)
#pragma unroll
                    for (int p = 0; p < 2; p++)
                        mma_f16(acc[mt][bt * 2 + p], ah[mt], bh[p], bh[p + 2]);
#pragma unroll
                for (int mt = 0; mt < 2; mt++)
#pragma unroll
                    for (int p = 0; p < 2; p++)
                        mma_f16(acc[mt][bt * 2 + p], ah[mt], bl[p], bl[p + 2]);
                if (PASSES == 3) {
#pragma unroll
                    for (int mt = 0; mt < 2; mt++)
#pragma unroll
                        for (int p = 0; p < 2; p++)
                            mma_f16(acc[mt][bt * 2 + p], al[mt], bh[p], bh[p + 2]);
                }
            }
        }
        __syncthreads();
    }

    // ============================ epilogue ============================
    const int cbytes = (splitOut == 0) ? 4 : 2;
    char* Cb  = (char*)Co + (dual ? 0 : (size_t)z * sC * cbytes);
    char* Cb2 = (splitOut == 1) ? ((char*)Co2 + (dual ? 0 : (size_t)z * sC * 2)) : nullptr;

#pragma unroll
    for (int mt = 0; mt < 2; mt++) {
        const long long r0 = row0 + wm * 32 + mt * 16 + (lane >> 2);
#pragma unroll
        for (int nt = 0; nt < 8; nt++) {
            const int c0 = col0 + wn * 64 + nt * 8 + (lane & 3) * 2;
            float b0 = 0.0f, b1 = 0.0f;
            if (biasMode == 1)      { b0 = bvp[c0]; b1 = bvp[c0 + 1]; }
            else if (biasMode == 2) { b0 = bvp[0];  b1 = bvp[0]; }

            float v00 = fmaf(acc[mt][nt][0], cScale, b0);
            float v01 = fmaf(acc[mt][nt][1], cScale, b1);
            float v10 = fmaf(acc[mt][nt][2], cScale, b0);
            float v11 = fmaf(acc[mt][nt][3], cScale, b1);
            if (doRelu) {
                v00 = fmaxf(v00, 0.0f); v01 = fmaxf(v01, 0.0f);
                v10 = fmaxf(v10, 0.0f); v11 = fmaxf(v11, 0.0f);
            }

            if (splitOut == 0) {
                *(float2*)(Cb + (r0 * ldc + c0) * 4)       = make_float2(v00, v01);
                *(float2*)(Cb + ((r0 + 8) * ldc + c0) * 4) = make_float2(v10, v11);
            } else {
                __half h00 = __float2half_rn(v00), h01 = __float2half_rn(v01);
                __half h10 = __float2half_rn(v10), h11 = __float2half_rn(v11);
                uint32_t ph0 = (uint32_t)__half_as_ushort(h00) |
                               ((uint32_t)__half_as_ushort(h01) << 16);
                uint32_t ph1 = (uint32_t)__half_as_ushort(h10) |
                               ((uint32_t)__half_as_ushort(h11) << 16);
                *(uint32_t*)(Cb + (r0 * ldc + c0) * 2)       = ph0;
                *(uint32_t*)(Cb + ((r0 + 8) * ldc + c0) * 2) = ph1;
                if (splitOut == 1) {
                    __half l00 = __float2half_rn(v00 - __half2float(h00));
                    __half l01 = __float2half_rn(v01 - __half2float(h01));
                    __half l10 = __float2half_rn(v10 - __half2float(h10));
                    __half l11 = __float2half_rn(v11 - __half2float(h11));
                    uint32_t pl0 = (uint32_t)__half_as_ushort(l00) |
                                   ((uint32_t)__half_as_ushort(l01) << 16);
                    uint32_t pl1 = (uint32_t)__half_as_ushort(l10) |
                                   ((uint32_t)__half_as_ushort(l11) << 16);
                    *(uint32_t*)(Cb2 + (r0 * ldc + c0) * 2)       = pl0;
                    *(uint32_t*)(Cb2 + ((r0 + 8) * ldc + c0) * 2) = pl1;
                }
            }
        }
    }
}

// ============================ launch ============================
extern "C" void kernel_launch(void* const* d_in, const int* in_sizes, int n_in,
                              void* d_out, int out_size)
{
    const float* X   = (const float*)d_in[0];
    const float* w1h = (const float*)d_in[1];
    const float* b1h = (const float*)d_in[2];
    const float* w2h = (const float*)d_in[3];
    const float* b2h = (const float*)d_in[4];
    const float* w1d = (const float*)d_in[5];
    const float* b1d = (const float*)d_in[6];
    const float* w2d = (const float*)d_in[7];
    const float* b2d = (const float*)d_in[8];
    const float* Wb  = (const float*)d_in[9];
    const float* bb  = (const float*)d_in[10];
    float* out = (float*)d_out;

    __half* hb = nullptr;
    cudaGetSymbolAddress((void**)&hb, g_h);
    float* vecs = nullptr;
    cudaGetSymbolAddress((void**)&vecs, g_vec);

    __half *Xh    = hb + O_XH;
    __half *W1Ch  = hb + O_W1C_H,  *W1Cl  = hb + O_W1C_L;
    __half *W2Hh  = hb + O_W2H_H,  *W2Hl  = hb + O_W2H_L;
    __half *WBh   = hb + O_WB_H,   *WBl   = hb + O_WB_L;
    __half *W2DTh = hb + O_W2DT_H, *W2DTl = hb + O_W2DT_L;
    __half *WPh   = hb + O_WP_H,   *WPl   = hb + O_WP_L;
    __half *TTh   = hb + O_TT_H;
    __half *HDh   = hb + O_HD_H,   *HDl   = hb + O_HD_L;
    __half *DWh   = hb + O_DW_H,   *DWl   = hb + O_DW_L;

    float* b1c   = vecs + 0 * 1024;
    float* b2h_p = vecs + 1 * 1024;
    float* bpr   = vecs + 2 * 1024;

    cudaFuncSetAttribute(gemm_mma<2>, cudaFuncAttributeMaxDynamicSharedMemorySize, SMEMSZ);
    cudaFuncSetAttribute(gemm_mma<3>, cudaFuncAttributeMaxDynamicSharedMemorySize, SMEMSZ);

    // launch 0: X -> fp16
    conv_x<<<(unsigned)(EL_X / 4 / 256), 256>>>(X, Xh);
    // launch 1: weight prep (scaled x32) + biases
    prep_weights<<<7686, 256>>>(w1h, w1d, w2h, Wb, w2d, b1h, b1d, b2h, b2d,
                                W1Ch, W1Cl, W2Hh, W2Hl, WBh, WBl, W2DTh, W2DTl,
                                b1c, b2h_p, bpr);

    // launch 2: W' = Wb @ w2d (3-pass; operands scaled 32 each -> cScale stores 32*W')
    {
        dim3 g(4, 4, 1);
        gemm_mma<3><<<g, 256, SMEMSZ>>>(WBh, WBl, 512, 0, W2DTh, W2DTl, nullptr, nullptr,
                                        512, 0, WPh, WPl, nullptr, nullptr, 512, 0,
                                        512, nullptr, nullptr, 0, CDESC, 0, 1, 0);
    }
    // launch 3: stage 1: TT = ReLU(X @ W1C^T /32 + b1c), 2-pass, hi-only out
    {
        dim3 g(8, 64, 1);
        gemm_mma<2><<<g, 256, SMEMSZ>>>(Xh, nullptr, 1024, 0, W1Ch, W1Cl, nullptr, nullptr,
                                        1024, 0, TTh, nullptr, nullptr, nullptr, 1024, 0,
                                        1024, b1c, nullptr, 1, CDESC, 1, 2, 0);
    }
    // launch 4: stage 2 merged (z=0: head, z=1: depW), 2-pass, hi+lo out
    {
        dim3 g(4, 64, 2);
        gemm_mma<2><<<g, 256, SMEMSZ>>>(TTh, nullptr, 1024, 0,
                                        W2Hh, W2Hl, WPh, WPl, 512, 0,
                                        HDh, HDl, DWh, DWl, 512, 0,
                                        512, b2h_p, bpr, 1, CDESC, 0, 1, 1);
    }
    // launch 5: final batched: out[b] = head[b] @ depW[b]^T + bb, 3-pass, fp32 out
    {
        dim3 g(4, 4, 16);
        const long long sAB = 512LL * 512;
        gemm_mma<3><<<g, 256, SMEMSZ>>>(HDh, HDl, 512, sAB, DWh, DWl, nullptr, nullptr,
                                        512, sAB, out, nullptr, nullptr, nullptr, 512, sAB,
                                        512, bb, nullptr, 2, 1.0f, 0, 0, 0);
    }
}

// round 12
// speedup vs baseline: 3.7477x; 1.1547x over previous
#include <cuda_runtime.h>
#include <cuda_fp16.h>
#include <cstdint>

// BiaffineAttention  B=16, S=512, H=1024, A=500 (padded to 512)
// GEMMs via mma.sync fp16 (m16n8k16), split precision, fp32 accum.
// Weights pre-scaled by 32 (fp16-lo limbs stay normal), descaled in epilogue.
//   TT   = ReLU(X @ [w1h;w1d]^T + b1c)   2-pass              -> fp16 hi
//   W'   = Wb @ w2d (3-pass, hi store) ; b' = Wb @ b2d
//   head = TT[:, :512] @ w2h^T + b2h     1-pass -> fp16 hi        (z=0)
//   depW = TT[:, 512:] @ W'^T + b'       1-pass -> fp16 hi+lo     (z=1)
//   out[b] = head[b] @ depW[b]^T + bb    2-pass (fp32 out)

// ============================ PTX helpers ============================
__device__ __forceinline__ uint32_t smem_u32(const void* p) {
    uint32_t a;
    asm("{ .reg .u64 t; cvta.to.shared.u64 t, %1; cvt.u32.u64 %0, t; }"
        : "=r"(a) : "l"(p));
    return a;
}

__device__ __forceinline__ void ldsm4(uint32_t* r, uint32_t addr) {
    asm volatile("ldmatrix.sync.aligned.m8n8.x4.shared.b16 {%0,%1,%2,%3}, [%4];"
        : "=r"(r[0]), "=r"(r[1]), "=r"(r[2]), "=r"(r[3]) : "r"(addr));
}

__device__ __forceinline__ void mma_f16(float* c, const uint32_t* a,
                                        uint32_t b0, uint32_t b1) {
    asm volatile("mma.sync.aligned.m16n8k16.row.col.f32.f16.f16.f32 "
        "{%0,%1,%2,%3}, {%4,%5,%6,%7}, {%8,%9}, {%0,%1,%2,%3};"
        : "+f"(c[0]), "+f"(c[1]), "+f"(c[2]), "+f"(c[3])
        : "r"(a[0]), "r"(a[1]), "r"(a[2]), "r"(a[3]), "r"(b0), "r"(b1));
}

#define CP16(s, g) \
    asm volatile("cp.async.cg.shared.global [%0], [%1], 16;" :: "r"(s), "l"(g))
#define CP_COMMIT() asm volatile("cp.async.commit_group;" ::: "memory")
#define CP_WAIT0()  asm volatile("cp.async.wait_group 0;" ::: "memory")
#define CP_WAIT1()  asm volatile("cp.async.wait_group 1;" ::: "memory")

// ============================ scratch ============================
static constexpr long long EL_X   = 8192LL * 1024;
static constexpr long long EL_W1C = 1024LL * 1024;
static constexpr long long EL_S   = 512LL * 512;
static constexpr long long EL_TT  = 8192LL * 1024;
static constexpr long long EL_ACT = 8192LL * 512;

static constexpr long long O_XH     = 0;
static constexpr long long O_W1C_H  = O_XH + EL_X;
static constexpr long long O_W1C_L  = O_W1C_H + EL_W1C;
static constexpr long long O_W2H_H  = O_W1C_L + EL_W1C;
static constexpr long long O_WB_H   = O_W2H_H + EL_S;
static constexpr long long O_WB_L   = O_WB_H + EL_S;
static constexpr long long O_W2DT_H = O_WB_L + EL_S;
static constexpr long long O_W2DT_L = O_W2DT_H + EL_S;
static constexpr long long O_WP_H   = O_W2DT_L + EL_S;
static constexpr long long O_TT_H   = O_WP_H + EL_S;
static constexpr long long O_HD_H   = O_TT_H + EL_TT;
static constexpr long long O_DW_H   = O_HD_H + EL_ACT;
static constexpr long long O_DW_L   = O_DW_H + EL_ACT;
static constexpr long long H_TOTAL  = O_DW_L + EL_ACT;

__device__ __align__(1024) __half g_h[H_TOTAL];
__device__ __align__(1024) float g_vec[3 * 1024];   // b1c[1024], b2h_p[512], bpr[512]

// ============================ prep kernels ============================
__device__ __forceinline__ void split_h(__half* hi, __half* lo, long long i, float v)
{
    __half h = __float2half_rn(v);
    hi[i] = h;
    lo[i] = __float2half_rn(v - __half2float(h));
}

__global__ void conv_x(const float* __restrict__ X, __half* __restrict__ Xh)
{
    long long idx = ((long long)blockIdx.x * blockDim.x + threadIdx.x) * 4;
    float4 v = *(const float4*)(X + idx);
    __half h[4] = {__float2half_rn(v.x), __float2half_rn(v.y),
                   __float2half_rn(v.z), __float2half_rn(v.w)};
    *(uint2*)(Xh + idx) = *(uint2*)h;
}

#define WSCALE 32.0f
#define CDESC  0.03125f

__global__ void prep_weights(
    const float* __restrict__ w1h, const float* __restrict__ w1d,
    const float* __restrict__ w2h, const float* __restrict__ Wb,
    const float* __restrict__ w2d,
    const float* __restrict__ b1h, const float* __restrict__ b1d,
    const float* __restrict__ b2h, const float* __restrict__ b2d,
    __half* __restrict__ W1Ch, __half* __restrict__ W1Cl,
    __half* __restrict__ W2Hh,
    __half* __restrict__ WBh,  __half* __restrict__ WBl,
    __half* __restrict__ W2DTh,__half* __restrict__ W2DTl,
    float* __restrict__ b1c, float* __restrict__ b2h_p, float* __restrict__ bpr)
{
    const int bx = blockIdx.x;
    const int tid = threadIdx.x;

    if (bx < 4096) {
        const int half_ = bx >> 11;
        const long long e = ((long long)(bx & 2047)) * 256 + tid;
        const int r = (int)(e >> 10);
        const float* src = half_ ? w1d : w1h;
        float v = (r < 500) ? WSCALE * src[(long long)r * 1024 + (e & 1023)] : 0.0f;
        split_h(W1Ch, W1Cl, (long long)half_ * 512 * 1024 + e, v);
    } else if (bx < 7168) {
        const int sec = (bx - 4096) >> 10;
        const long long e = ((long long)((bx - 4096) & 1023)) * 256 + tid;
        const int r = (int)(e >> 9), c = (int)(e & 511);
        float v = 0.0f;
        if (sec == 0) {
            if (r < 500 && c < 500) v = WSCALE * w2h[r * 500 + c];
            W2Hh[e] = __float2half_rn(v);                 // hi only (1-pass consumer)
        } else if (sec == 1) {
            if (r < 500 && c < 500) v = WSCALE * Wb[r * 500 + c];
            split_h(WBh, WBl, e, v);
        } else {
            if (r < 500 && c < 500) v = WSCALE * w2d[c * 500 + r];
            split_h(W2DTh, W2DTl, e, v);
        }
    } else if (bx < 7680) {
        const int j = bx - 7168;
        __shared__ float red[8];
        float s = 0.0f;
        if (j < 500)
            for (int a = tid; a < 500; a += 256) s += Wb[j * 500 + a] * b2d[a];
#pragma unroll
        for (int o = 16; o > 0; o >>= 1) s += __shfl_down_sync(0xffffffffu, s, o);
        if ((tid & 31) == 0) red[tid >> 5] = s;
        __syncthreads();
        if (tid == 0) {
            float t = 0.0f;
#pragma unroll
            for (int q = 0; q < 8; q++) t += red[q];
            bpr[j] = (j < 500) ? t : 0.0f;
        }
    } else {
        const int e = (bx - 7680) * 256 + tid;
        if (e < 1024) {
            const int c = e & 511;
            b1c[e] = (c < 500) ? ((e < 512) ? b1h[c] : b1d[c]) : 0.0f;
        } else if (e < 1536) {
            const int c = e - 1024;
            b2h_p[c] = (c < 500) ? b2h[c] : 0.0f;
        }
    }
}

// ============================ main GEMM ============================
// C[M,N] = A[M,K] @ B[N,K]^T.
// PASSES=1: Ahi@Bhi.  PASSES=2: + Ahi@Blo.  PASSES=3: + Alo@Bhi.
// CTA 128x128, 8 warps (4Mx2N), warp 32x64, BK=32, 2 CTAs/SM.
// splitOut: 0=fp32, 1=fp16 hi+lo, 2=fp16 hi only. dual: z picks operand set
// (z=1 uses A+512 cols, B2/bias2/C-B outputs, splitOutB).
#define SROW 40
#define TILEB (128 * SROW * 2)
#define OFF_AH 0
#define OFF_AL (1 * TILEB)
#define OFF_BH (2 * TILEB)
#define OFF_BL (3 * TILEB)
#define STAGE  (4 * TILEB)
#define SMEMSZ (2 * STAGE)

template<int PASSES>
__device__ __forceinline__ void issue_tile(
    uint32_t sbase, const char* Ah, const char* Al, const char* Bh, const char* Bl,
    int lda, int ldb, int row0, int col0, int k0, int tid)
{
#pragma unroll
    for (int i = 0; i < 2; i++) {
        const int pos = tid + i * 256;
        const int r = pos >> 2, ch = pos & 3;
        const uint32_t so = (uint32_t)(r * (SROW * 2) + ch * 16);
        const size_t gA = ((size_t)(row0 + r) * lda + k0 + ch * 8) * 2;
        const size_t gB = ((size_t)(col0 + r) * ldb + k0 + ch * 8) * 2;
        CP16(sbase + OFF_AH + so, Ah + gA);
        if (PASSES == 3) CP16(sbase + OFF_AL + so, Al + gA);
        CP16(sbase + OFF_BH + so, Bh + gB);
        if (PASSES >= 2) CP16(sbase + OFF_BL + so, Bl + gB);
    }
}

template<int PASSES>
__global__ void __launch_bounds__(256, 2) gemm_mma(
    const __half* __restrict__ Ahi, const __half* __restrict__ Alo,
    int lda, long long sA,
    const __half* __restrict__ Bhi, const __half* __restrict__ Blo,
    const __half* __restrict__ Bhi2, const __half* __restrict__ Blo2,
    int ldb, long long sB,
    void* __restrict__ Cout, void* __restrict__ Cout2,
    void* __restrict__ CoutB, void* __restrict__ Cout2B,
    int ldc, long long sC,
    int K, const float* __restrict__ bias, const float* __restrict__ bias2,
    int biasMode, float cScale, int doRelu, int splitOut, int splitOutB, int dual)
{
    extern __shared__ char smem[];
    const uint32_t sb = smem_u32(smem);
    const int tid  = threadIdx.x;
    const int lane = tid & 31;
    const int wid  = tid >> 5;
    const int wm   = wid & 3;
    const int wn   = wid >> 2;
    const int row0 = blockIdx.y * 128;
    const int col0 = blockIdx.x * 128;

    const int z = blockIdx.z;
    const char *Ah, *Al, *Bh, *Bl;
    const float* bvp = bias;
    void *Co = Cout, *Co2 = Cout2;
    int sOut = splitOut;
    if (dual && z) {
        Ah = (const char*)(Ahi + 512);
        Al = (const char*)(Alo ? Alo + 512 : nullptr);
        Bh = (const char*)Bhi2;  Bl = (const char*)Blo2;
        bvp = bias2;  Co = CoutB;  Co2 = Cout2B;  sOut = splitOutB;
    } else {
        Ah = (const char*)(Ahi + (long long)z * sA);
        Al = (const char*)(Alo ? Alo + (long long)z * sA : nullptr);
        Bh = (const char*)(Bhi + (long long)z * sB);
        Bl = (const char*)(Blo ? Blo + (long long)z * sB : nullptr);
    }

    float acc[2][8][4];
#pragma unroll
    for (int mt = 0; mt < 2; mt++)
#pragma unroll
        for (int nt = 0; nt < 8; nt++)
#pragma unroll
            for (int q = 0; q < 4; q++) acc[mt][nt][q] = 0.0f;

    const int frow = (lane & 7) | (((lane >> 3) & 1) << 3);
    const int fkc  = (lane >> 4) * 8;

    const int T = K / 32;
    issue_tile<PASSES>(sb, Ah, Al, Bh, Bl, lda, ldb, row0, col0, 0, tid);
    CP_COMMIT();

    for (int t = 0; t < T; ++t) {
        if (t + 1 < T) {
            issue_tile<PASSES>(sb + ((t + 1) & 1) * STAGE, Ah, Al, Bh, Bl,
                               lda, ldb, row0, col0, (t + 1) * 32, tid);
            CP_COMMIT();
            CP_WAIT1();
        } else {
            CP_WAIT0();
        }
        __syncthreads();

        const uint32_t st = sb + (t & 1) * STAGE;
#pragma unroll
        for (int kh = 0; kh < 2; ++kh) {
            const int kb = kh * 16 + fkc;
            uint32_t ah[2][4], al[2][4];
#pragma unroll
            for (int mt = 0; mt < 2; mt++) {
                const uint32_t off = (uint32_t)(((wm * 32 + mt * 16 + frow) * SROW + kb) * 2);
                ldsm4(ah[mt], st + OFF_AH + off);
                if (PASSES == 3) ldsm4(al[mt], st + OFF_AL + off);
            }
#pragma unroll
            for (int bt = 0; bt < 4; bt++) {
                uint32_t bh[4], bl[4];
                const uint32_t off = (uint32_t)(((wn * 64 + bt * 16 + frow) * SROW + kb) * 2);
                ldsm4(bh, st + OFF_BH + off);
                if (PASSES >= 2) ldsm4(bl, st + OFF_BL + off);
#pragma unroll
                for (int mt = 0; mt < 2; mt++)
#pragma unroll
                    for (int p = 0; p < 2; p++)
                        mma_f16(acc[mt][bt * 2 + p], ah[mt], bh[p], bh[p + 2]);
                if (PASSES >= 2) {
#pragma unroll
                    for (int mt = 0; mt < 2; mt++)
#pragma unroll
                        for (int p = 0; p < 2; p++)
                            mma_f16(acc[mt][bt * 2 + p], ah[mt], bl[p], bl[p + 2]);
                }
                if (PASSES == 3) {
#pragma unroll
                    for (int mt = 0; mt < 2; mt++)
#pragma unroll
                        for (int p = 0; p < 2; p++)
                            mma_f16(acc[mt][bt * 2 + p], al[mt], bh[p], bh[p + 2]);
                }
            }
        }
        __syncthreads();
    }

    // ============================ epilogue ============================
    const int cbytes = (sOut == 0) ? 4 : 2;
    char* Cb  = (char*)Co + (dual ? 0 : (size_t)z * sC * cbytes);
    char* Cb2 = (sOut == 1) ? ((char*)Co2 + (dual ? 0 : (size_t)z * sC * 2)) : nullptr;

#pragma unroll
    for (int mt = 0; mt < 2; mt++) {
        const long long r0 = row0 + wm * 32 + mt * 16 + (lane >> 2);
#pragma unroll
        for (int nt = 0; nt < 8; nt++) {
            const int c0 = col0 + wn * 64 + nt * 8 + (lane & 3) * 2;
            float b0 = 0.0f, b1 = 0.0f;
            if (biasMode == 1)      { b0 = bvp[c0]; b1 = bvp[c0 + 1]; }
            else if (biasMode == 2) { b0 = bvp[0];  b1 = bvp[0]; }

            float v00 = fmaf(acc[mt][nt][0], cScale, b0);
            float v01 = fmaf(acc[mt][nt][1], cScale, b1);
            float v10 = fmaf(acc[mt][nt][2], cScale, b0);
            float v11 = fmaf(acc[mt][nt][3], cScale, b1);
            if (doRelu) {
                v00 = fmaxf(v00, 0.0f); v01 = fmaxf(v01, 0.0f);
                v10 = fmaxf(v10, 0.0f); v11 = fmaxf(v11, 0.0f);
            }

            if (sOut == 0) {
                *(float2*)(Cb + (r0 * ldc + c0) * 4)       = make_float2(v00, v01);
                *(float2*)(Cb + ((r0 + 8) * ldc + c0) * 4) = make_float2(v10, v11);
            } else {
                __half h00 = __float2half_rn(v00), h01 = __float2half_rn(v01);
                __half h10 = __float2half_rn(v10), h11 = __float2half_rn(v11);
                uint32_t ph0 = (uint32_t)__half_as_ushort(h00) |
                               ((uint32_t)__half_as_ushort(h01) << 16);
                uint32_t ph1 = (uint32_t)__half_as_ushort(h10) |
                               ((uint32_t)__half_as_ushort(h11) << 16);
                *(uint32_t*)(Cb + (r0 * ldc + c0) * 2)       = ph0;
                *(uint32_t*)(Cb + ((r0 + 8) * ldc + c0) * 2) = ph1;
                if (sOut == 1) {
                    __half l00 = __float2half_rn(v00 - __half2float(h00));
                    __half l01 = __float2half_rn(v01 - __half2float(h01));
                    __half l10 = __float2half_rn(v10 - __half2float(h10));
                    __half l11 = __float2half_rn(v11 - __half2float(h11));
                    uint32_t pl0 = (uint32_t)__half_as_ushort(l00) |
                                   ((uint32_t)__half_as_ushort(l01) << 16);
                    uint32_t pl1 = (uint32_t)__half_as_ushort(l10) |
                                   ((uint32_t)__half_as_ushort(l11) << 16);
                    *(uint32_t*)(Cb2 + (r0 * ldc + c0) * 2)       = pl0;
                    *(uint32_t*)(Cb2 + ((r0 + 8) * ldc + c0) * 2) = pl1;
                }
            }
        }
    }
}

// ============================ launch ============================
extern "C" void kernel_launch(void* const* d_in, const int* in_sizes, int n_in,
                              void* d_out, int out_size)
{
    const float* X   = (const float*)d_in[0];
    const float* w1h = (const float*)d_in[1];
    const float* b1h = (const float*)d_in[2];
    const float* w2h = (const float*)d_in[3];
    const float* b2h = (const float*)d_in[4];
    const float* w1d = (const float*)d_in[5];
    const float* b1d = (const float*)d_in[6];
    const float* w2d = (const float*)d_in[7];
    const float* b2d = (const float*)d_in[8];
    const float* Wb  = (const float*)d_in[9];
    const float* bb  = (const float*)d_in[10];
    float* out = (float*)d_out;

    __half* hb = nullptr;
    cudaGetSymbolAddress((void**)&hb, g_h);
    float* vecs = nullptr;
    cudaGetSymbolAddress((void**)&vecs, g_vec);

    __half *Xh    = hb + O_XH;
    __half *W1Ch  = hb + O_W1C_H,  *W1Cl  = hb + O_W1C_L;
    __half *W2Hh  = hb + O_W2H_H;
    __half *WBh   = hb + O_WB_H,   *WBl   = hb + O_WB_L;
    __half *W2DTh = hb + O_W2DT_H, *W2DTl = hb + O_W2DT_L;
    __half *WPh   = hb + O_WP_H;
    __half *TTh   = hb + O_TT_H;
    __half *HDh   = hb + O_HD_H;
    __half *DWh   = hb + O_DW_H,   *DWl   = hb + O_DW_L;

    float* b1c   = vecs + 0 * 1024;
    float* b2h_p = vecs + 1 * 1024;
    float* bpr   = vecs + 2 * 1024;

    cudaFuncSetAttribute(gemm_mma<1>, cudaFuncAttributeMaxDynamicSharedMemorySize, SMEMSZ);
    cudaFuncSetAttribute(gemm_mma<2>, cudaFuncAttributeMaxDynamicSharedMemorySize, SMEMSZ);
    cudaFuncSetAttribute(gemm_mma<3>, cudaFuncAttributeMaxDynamicSharedMemorySize, SMEMSZ);

    // launch 0: X -> fp16
    conv_x<<<(unsigned)(EL_X / 4 / 256), 256>>>(X, Xh);
    // launch 1: weight prep (scaled x32) + biases
    prep_weights<<<7686, 256>>>(w1h, w1d, w2h, Wb, w2d, b1h, b1d, b2h, b2d,
                                W1Ch, W1Cl, W2Hh, WBh, WBl, W2DTh, W2DTl,
                                b1c, b2h_p, bpr);

    // launch 2: W' = Wb @ w2d (3-pass, hi-only store of 32*W')
    {
        dim3 g(4, 4, 1);
        gemm_mma<3><<<g, 256, SMEMSZ>>>(WBh, WBl, 512, 0, W2DTh, W2DTl, nullptr, nullptr,
                                        512, 0, WPh, nullptr, nullptr, nullptr, 512, 0,
                                        512, nullptr, nullptr, 0, CDESC, 0, 2, 0, 0);
    }
    // launch 3: stage 1: TT = ReLU(X @ W1C^T /32 + b1c), 2-pass, hi-only out
    {
        dim3 g(8, 64, 1);
        gemm_mma<2><<<g, 256, SMEMSZ>>>(Xh, nullptr, 1024, 0, W1Ch, W1Cl, nullptr, nullptr,
                                        1024, 0, TTh, nullptr, nullptr, nullptr, 1024, 0,
                                        1024, b1c, nullptr, 1, CDESC, 1, 2, 0, 0);
    }
    // launch 4: stage 2 merged, 1-pass (z=0: head -> hi only; z=1: depW -> hi+lo)
    {
        dim3 g(4, 64, 2);
        gemm_mma<1><<<g, 256, SMEMSZ>>>(TTh, nullptr, 1024, 0,
                                        W2Hh, nullptr, WPh, nullptr, 512, 0,
                                        HDh, nullptr, DWh, DWl, 512, 0,
                                        512, b2h_p, bpr, 1, CDESC, 0, 2, 1, 1);
    }
    // launch 5: final batched, 2-pass: out[b] = headh[b] @ (DWh+DWl)[b]^T + bb
    {
        dim3 g(4, 4, 16);
        const long long sAB = 512LL * 512;
        gemm_mma<2><<<g, 256, SMEMSZ>>>(HDh, nullptr, 512, sAB, DWh, DWl, nullptr, nullptr,
                                        512, sAB, out, nullptr, nullptr, nullptr, 512, sAB,
                                        512, bb, nullptr, 2, 1.0f, 0, 0, 0, 0);
    }
}

// round 13
// speedup vs baseline: 4.5967x; 1.2265x over previous
#include <cuda_runtime.h>
#include <cuda_fp16.h>
#include <cstdint>

// BiaffineAttention  B=16, S=512, H=1024, A=500 (padded to 512)
// GEMMs via mma.sync fp16 (m16n8k16), split precision, fp32 accum.
// Weights pre-scaled by 32 (fp16-lo limbs stay normal), descaled in epilogue.
//   TT   = ReLU(X @ [w1h;w1d]^T + b1c)   1-pass              -> fp16 hi
//   W'   = Wb @ w2d (3-pass, hi store) ; b' = Wb @ b2d
//   head = TT[:, :512] @ w2h^T + b2h     1-pass -> fp16 hi        (z=0)
//   depW = TT[:, 512:] @ W'^T + b'       1-pass -> fp16 hi+lo     (z=1)
//   out[b] = head[b] @ depW[b]^T + bb    2-pass (fp32 out)

// ============================ PTX helpers ============================
__device__ __forceinline__ uint32_t smem_u32(const void* p) {
    uint32_t a;
    asm("{ .reg .u64 t; cvta.to.shared.u64 t, %1; cvt.u32.u64 %0, t; }"
        : "=r"(a) : "l"(p));
    return a;
}

__device__ __forceinline__ void ldsm4(uint32_t* r, uint32_t addr) {
    asm volatile("ldmatrix.sync.aligned.m8n8.x4.shared.b16 {%0,%1,%2,%3}, [%4];"
        : "=r"(r[0]), "=r"(r[1]), "=r"(r[2]), "=r"(r[3]) : "r"(addr));
}

__device__ __forceinline__ void mma_f16(float* c, const uint32_t* a,
                                        uint32_t b0, uint32_t b1) {
    asm volatile("mma.sync.aligned.m16n8k16.row.col.f32.f16.f16.f32 "
        "{%0,%1,%2,%3}, {%4,%5,%6,%7}, {%8,%9}, {%0,%1,%2,%3};"
        : "+f"(c[0]), "+f"(c[1]), "+f"(c[2]), "+f"(c[3])
        : "r"(a[0]), "r"(a[1]), "r"(a[2]), "r"(a[3]), "r"(b0), "r"(b1));
}

#define CP16(s, g) \
    asm volatile("cp.async.cg.shared.global [%0], [%1], 16;" :: "r"(s), "l"(g))
#define CP_COMMIT() asm volatile("cp.async.commit_group;" ::: "memory")
#define CP_WAIT0()  asm volatile("cp.async.wait_group 0;" ::: "memory")
#define CP_WAIT1()  asm volatile("cp.async.wait_group 1;" ::: "memory")

// ============================ scratch ============================
static constexpr long long EL_X   = 8192LL * 1024;
static constexpr long long EL_W1C = 1024LL * 1024;
static constexpr long long EL_S   = 512LL * 512;
static constexpr long long EL_TT  = 8192LL * 1024;
static constexpr long long EL_ACT = 8192LL * 512;

static constexpr long long O_XH     = 0;
static constexpr long long O_W1C_H  = O_XH + EL_X;
static constexpr long long O_W2H_H  = O_W1C_H + EL_W1C;
static constexpr long long O_WB_H   = O_W2H_H + EL_S;
static constexpr long long O_WB_L   = O_WB_H + EL_S;
static constexpr long long O_W2DT_H = O_WB_L + EL_S;
static constexpr long long O_W2DT_L = O_W2DT_H + EL_S;
static constexpr long long O_WP_H   = O_W2DT_L + EL_S;
static constexpr long long O_TT_H   = O_WP_H + EL_S;
static constexpr long long O_HD_H   = O_TT_H + EL_TT;
static constexpr long long O_DW_H   = O_HD_H + EL_ACT;
static constexpr long long O_DW_L   = O_DW_H + EL_ACT;
static constexpr long long H_TOTAL  = O_DW_L + EL_ACT;

__device__ __align__(1024) __half g_h[H_TOTAL];
__device__ __align__(1024) float g_vec[3 * 1024];   // b1c[1024], b2h_p[512], bpr[512]

// ============================ prep kernels ============================
__device__ __forceinline__ void split_h(__half* hi, __half* lo, long long i, float v)
{
    __half h = __float2half_rn(v);
    hi[i] = h;
    lo[i] = __float2half_rn(v - __half2float(h));
}

__global__ void conv_x(const float* __restrict__ X, __half* __restrict__ Xh)
{
    long long idx = ((long long)blockIdx.x * blockDim.x + threadIdx.x) * 4;
    float4 v = *(const float4*)(X + idx);
    __half h[4] = {__float2half_rn(v.x), __float2half_rn(v.y),
                   __float2half_rn(v.z), __float2half_rn(v.w)};
    *(uint2*)(Xh + idx) = *(uint2*)h;
}

#define WSCALE 32.0f
#define CDESC  0.03125f

__global__ void prep_weights(
    const float* __restrict__ w1h, const float* __restrict__ w1d,
    const float* __restrict__ w2h, const float* __restrict__ Wb,
    const float* __restrict__ w2d,
    const float* __restrict__ b1h, const float* __restrict__ b1d,
    const float* __restrict__ b2h, const float* __restrict__ b2d,
    __half* __restrict__ W1Ch,
    __half* __restrict__ W2Hh,
    __half* __restrict__ WBh,  __half* __restrict__ WBl,
    __half* __restrict__ W2DTh,__half* __restrict__ W2DTl,
    float* __restrict__ b1c, float* __restrict__ b2h_p, float* __restrict__ bpr)
{
    const int bx = blockIdx.x;
    const int tid = threadIdx.x;

    if (bx < 4096) {
        const int half_ = bx >> 11;
        const long long e = ((long long)(bx & 2047)) * 256 + tid;
        const int r = (int)(e >> 10);
        const float* src = half_ ? w1d : w1h;
        float v = (r < 500) ? WSCALE * src[(long long)r * 1024 + (e & 1023)] : 0.0f;
        W1Ch[(long long)half_ * 512 * 1024 + e] = __float2half_rn(v);  // hi only
    } else if (bx < 7168) {
        const int sec = (bx - 4096) >> 10;
        const long long e = ((long long)((bx - 4096) & 1023)) * 256 + tid;
        const int r = (int)(e >> 9), c = (int)(e & 511);
        float v = 0.0f;
        if (sec == 0) {
            if (r < 500 && c < 500) v = WSCALE * w2h[r * 500 + c];
            W2Hh[e] = __float2half_rn(v);                 // hi only (1-pass consumer)
        } else if (sec == 1) {
            if (r < 500 && c < 500) v = WSCALE * Wb[r * 500 + c];
            split_h(WBh, WBl, e, v);
        } else {
            if (r < 500 && c < 500) v = WSCALE * w2d[c * 500 + r];
            split_h(W2DTh, W2DTl, e, v);
        }
    } else if (bx < 7680) {
        const int j = bx - 7168;
        __shared__ float red[8];
        float s = 0.0f;
        if (j < 500)
            for (int a = tid; a < 500; a += 256) s += Wb[j * 500 + a] * b2d[a];
#pragma unroll
        for (int o = 16; o > 0; o >>= 1) s += __shfl_down_sync(0xffffffffu, s, o);
        if ((tid & 31) == 0) red[tid >> 5] = s;
        __syncthreads();
        if (tid == 0) {
            float t = 0.0f;
#pragma unroll
            for (int q = 0; q < 8; q++) t += red[q];
            bpr[j] = (j < 500) ? t : 0.0f;
        }
    } else {
        const int e = (bx - 7680) * 256 + tid;
        if (e < 1024) {
            const int c = e & 511;
            b1c[e] = (c < 500) ? ((e < 512) ? b1h[c] : b1d[c]) : 0.0f;
        } else if (e < 1536) {
            const int c = e - 1024;
            b2h_p[c] = (c < 500) ? b2h[c] : 0.0f;
        }
    }
}

// ============================ main GEMM ============================
// C[M,N] = A[M,K] @ B[N,K]^T.
// PASSES=1: Ahi@Bhi.  PASSES=2: + Ahi@Blo.  PASSES=3: + Alo@Bhi.
// CTA 128x128, 8 warps (4Mx2N), warp 32x64, BK=32, 2 CTAs/SM.
// splitOut: 0=fp32, 1=fp16 hi+lo, 2=fp16 hi only. dual: z picks operand set.
#define SROW 40
#define TILEB (128 * SROW * 2)
#define OFF_AH 0
#define OFF_AL (1 * TILEB)
#define OFF_BH (2 * TILEB)
#define OFF_BL (3 * TILEB)
#define STAGE  (4 * TILEB)
#define SMEMSZ (2 * STAGE)

template<int PASSES>
__device__ __forceinline__ void issue_tile(
    uint32_t sbase, const char* Ah, const char* Al, const char* Bh, const char* Bl,
    int lda, int ldb, int row0, int col0, int k0, int tid)
{
#pragma unroll
    for (int i = 0; i < 2; i++) {
        const int pos = tid + i * 256;
        const int r = pos >> 2, ch = pos & 3;
        const uint32_t so = (uint32_t)(r * (SROW * 2) + ch * 16);
        const size_t gA = ((size_t)(row0 + r) * lda + k0 + ch * 8) * 2;
        const size_t gB = ((size_t)(col0 + r) * ldb + k0 + ch * 8) * 2;
        CP16(sbase + OFF_AH + so, Ah + gA);
        if (PASSES == 3) CP16(sbase + OFF_AL + so, Al + gA);
        CP16(sbase + OFF_BH + so, Bh + gB);
        if (PASSES >= 2) CP16(sbase + OFF_BL + so, Bl + gB);
    }
}

template<int PASSES>
__global__ void __launch_bounds__(256, 2) gemm_mma(
    const __half* __restrict__ Ahi, const __half* __restrict__ Alo,
    int lda, long long sA,
    const __half* __restrict__ Bhi, const __half* __restrict__ Blo,
    const __half* __restrict__ Bhi2, const __half* __restrict__ Blo2,
    int ldb, long long sB,
    void* __restrict__ Cout, void* __restrict__ Cout2,
    void* __restrict__ CoutB, void* __restrict__ Cout2B,
    int ldc, long long sC,
    int K, const float* __restrict__ bias, const float* __restrict__ bias2,
    int biasMode, float cScale, int doRelu, int splitOut, int splitOutB, int dual)
{
    extern __shared__ char smem[];
    const uint32_t sb = smem_u32(smem);
    const int tid  = threadIdx.x;
    const int lane = tid & 31;
    const int wid  = tid >> 5;
    const int wm   = wid & 3;
    const int wn   = wid >> 2;
    const int row0 = blockIdx.y * 128;
    const int col0 = blockIdx.x * 128;

    const int z = blockIdx.z;
    const char *Ah, *Al, *Bh, *Bl;
    const float* bvp = bias;
    void *Co = Cout, *Co2 = Cout2;
    int sOut = splitOut;
    if (dual && z) {
        Ah = (const char*)(Ahi + 512);
        Al = (const char*)(Alo ? Alo + 512 : nullptr);
        Bh = (const char*)Bhi2;  Bl = (const char*)Blo2;
        bvp = bias2;  Co = CoutB;  Co2 = Cout2B;  sOut = splitOutB;
    } else {
        Ah = (const char*)(Ahi + (long long)z * sA);
        Al = (const char*)(Alo ? Alo + (long long)z * sA : nullptr);
        Bh = (const char*)(Bhi + (long long)z * sB);
        Bl = (const char*)(Blo ? Blo + (long long)z * sB : nullptr);
    }

    float acc[2][8][4];
#pragma unroll
    for (int mt = 0; mt < 2; mt++)
#pragma unroll
        for (int nt = 0; nt < 8; nt++)
#pragma unroll
            for (int q = 0; q < 4; q++) acc[mt][nt][q] = 0.0f;

    const int frow = (lane & 7) | (((lane >> 3) & 1) << 3);
    const int fkc  = (lane >> 4) * 8;

    const int T = K / 32;
    issue_tile<PASSES>(sb, Ah, Al, Bh, Bl, lda, ldb, row0, col0, 0, tid);
    CP_COMMIT();

    for (int t = 0; t < T; ++t) {
        if (t + 1 < T) {
            issue_tile<PASSES>(sb + ((t + 1) & 1) * STAGE, Ah, Al, Bh, Bl,
                               lda, ldb, row0, col0, (t + 1) * 32, tid);
            CP_COMMIT();
            CP_WAIT1();
        } else {
            CP_WAIT0();
        }
        __syncthreads();

        const uint32_t st = sb + (t & 1) * STAGE;
#pragma unroll
        for (int kh = 0; kh < 2; ++kh) {
            const int kb = kh * 16 + fkc;
            uint32_t ah[2][4], al[2][4];
#pragma unroll
            for (int mt = 0; mt < 2; mt++) {
                const uint32_t off = (uint32_t)(((wm * 32 + mt * 16 + frow) * SROW + kb) * 2);
                ldsm4(ah[mt], st + OFF_AH + off);
                if (PASSES == 3) ldsm4(al[mt], st + OFF_AL + off);
            }
#pragma unroll
            for (int bt = 0; bt < 4; bt++) {
                uint32_t bh[4], bl[4];
                const uint32_t off = (uint32_t)(((wn * 64 + bt * 16 + frow) * SROW + kb) * 2);
                ldsm4(bh, st + OFF_BH + off);
                if (PASSES >= 2) ldsm4(bl, st + OFF_BL + off);
#pragma unroll
                for (int mt = 0; mt < 2; mt++)
#pragma unroll
                    for (int p = 0; p < 2; p++)
                        mma_f16(acc[mt][bt * 2 + p], ah[mt], bh[p], bh[p + 2]);
                if (PASSES >= 2) {
#pragma unroll
                    for (int mt = 0; mt < 2; mt++)
#pragma unroll
                        for (int p = 0; p < 2; p++)
                            mma_f16(acc[mt][bt * 2 + p], ah[mt], bl[p], bl[p + 2]);
                }
                if (PASSES == 3) {
#pragma unroll
                    for (int mt = 0; mt < 2; mt++)
#pragma unroll
                        for (int p = 0; p < 2; p++)
                            mma_f16(acc[mt][bt * 2 + p], al[mt], bh[p], bh[p + 2]);
                }
            }
        }
        __syncthreads();
    }

    // ============================ epilogue ============================
    const int cbytes = (sOut == 0) ? 4 : 2;
    char* Cb  = (char*)Co + (dual ? 0 : (size_t)z * sC * cbytes);
    char* Cb2 = (sOut == 1) ? ((char*)Co2 + (dual ? 0 : (size_t)z * sC * 2)) : nullptr;

#pragma unroll
    for (int mt = 0; mt < 2; mt++) {
        const long long r0 = row0 + wm * 32 + mt * 16 + (lane >> 2);
#pragma unroll
        for (int nt = 0; nt < 8; nt++) {
            const int c0 = col0 + wn * 64 + nt * 8 + (lane & 3) * 2;
            float b0 = 0.0f, b1 = 0.0f;
            if (biasMode == 1)      { b0 = bvp[c0]; b1 = bvp[c0 + 1]; }
            else if (biasMode == 2) { b0 = bvp[0];  b1 = bvp[0]; }

            float v00 = fmaf(acc[mt][nt][0], cScale, b0);
            float v01 = fmaf(acc[mt][nt][1], cScale, b1);
            float v10 = fmaf(acc[mt][nt][2], cScale, b0);
            float v11 = fmaf(acc[mt][nt][3], cScale, b1);
            if (doRelu) {
                v00 = fmaxf(v00, 0.0f); v01 = fmaxf(v01, 0.0f);
                v10 = fmaxf(v10, 0.0f); v11 = fmaxf(v11, 0.0f);
            }

            if (sOut == 0) {
                *(float2*)(Cb + (r0 * ldc + c0) * 4)       = make_float2(v00, v01);
                *(float2*)(Cb + ((r0 + 8) * ldc + c0) * 4) = make_float2(v10, v11);
            } else {
                __half h00 = __float2half_rn(v00), h01 = __float2half_rn(v01);
                __half h10 = __float2half_rn(v10), h11 = __float2half_rn(v11);
                uint32_t ph0 = (uint32_t)__half_as_ushort(h00) |
                               ((uint32_t)__half_as_ushort(h01) << 16);
                uint32_t ph1 = (uint32_t)__half_as_ushort(h10) |
                               ((uint32_t)__half_as_ushort(h11) << 16);
                *(uint32_t*)(Cb + (r0 * ldc + c0) * 2)       = ph0;
                *(uint32_t*)(Cb + ((r0 + 8) * ldc + c0) * 2) = ph1;
                if (sOut == 1) {
                    __half l00 = __float2half_rn(v00 - __half2float(h00));
                    __half l01 = __float2half_rn(v01 - __half2float(h01));
                    __half l10 = __float2half_rn(v10 - __half2float(h10));
                    __half l11 = __float2half_rn(v11 - __half2float(h11));
                    uint32_t pl0 = (uint32_t)__half_as_ushort(l00) |
                                   ((uint32_t)__half_as_ushort(l01) << 16);
                    uint32_t pl1 = (uint32_t)__half_as_ushort(l10) |
                                   ((uint32_t)__half_as_ushort(l11) << 16);
                    *(uint32_t*)(Cb2 + (r0 * ldc + c0) * 2)       = pl0;
                    *(uint32_t*)(Cb2 + ((r0 + 8) * ldc + c0) * 2) = pl1;
                }
            }
        }
    }
}

// ============================ launch ============================
extern "C" void kernel_launch(void* const* d_in, const int* in_sizes, int n_in,
                              void* d_out, int out_size)
{
    const float* X   = (const float*)d_in[0];
    const float* w1h = (const float*)d_in[1];
    const float* b1h = (const float*)d_in[2];
    const float* w2h = (const float*)d_in[3];
    const float* b2h = (const float*)d_in[4];
    const float* w1d = (const float*)d_in[5];
    const float* b1d = (const float*)d_in[6];
    const float* w2d = (const float*)d_in[7];
    const float* b2d = (const float*)d_in[8];
    const float* Wb  = (const float*)d_in[9];
    const float* bb  = (const float*)d_in[10];
    float* out = (float*)d_out;

    __half* hb = nullptr;
    cudaGetSymbolAddress((void**)&hb, g_h);
    float* vecs = nullptr;
    cudaGetSymbolAddress((void**)&vecs, g_vec);

    __half *Xh    = hb + O_XH;
    __half *W1Ch  = hb + O_W1C_H;
    __half *W2Hh  = hb + O_W2H_H;
    __half *WBh   = hb + O_WB_H,   *WBl   = hb + O_WB_L;
    __half *W2DTh = hb + O_W2DT_H, *W2DTl = hb + O_W2DT_L;
    __half *WPh   = hb + O_WP_H;
    __half *TTh   = hb + O_TT_H;
    __half *HDh   = hb + O_HD_H;
    __half *DWh   = hb + O_DW_H,   *DWl   = hb + O_DW_L;

    float* b1c   = vecs + 0 * 1024;
    float* b2h_p = vecs + 1 * 1024;
    float* bpr   = vecs + 2 * 1024;

    cudaFuncSetAttribute(gemm_mma<1>, cudaFuncAttributeMaxDynamicSharedMemorySize, SMEMSZ);
    cudaFuncSetAttribute(gemm_mma<2>, cudaFuncAttributeMaxDynamicSharedMemorySize, SMEMSZ);
    cudaFuncSetAttribute(gemm_mma<3>, cudaFuncAttributeMaxDynamicSharedMemorySize, SMEMSZ);

    // launch 0: X -> fp16
    conv_x<<<(unsigned)(EL_X / 4 / 256), 256>>>(X, Xh);
    // launch 1: weight prep (scaled x32) + biases
    prep_weights<<<7686, 256>>>(w1h, w1d, w2h, Wb, w2d, b1h, b1d, b2h, b2d,
                                W1Ch, W2Hh, WBh, WBl, W2DTh, W2DTl,
                                b1c, b2h_p, bpr);

    // launch 2: W' = Wb @ w2d (3-pass, hi-only store of 32*W')
    {
        dim3 g(4, 4, 1);
        gemm_mma<3><<<g, 256, SMEMSZ>>>(WBh, WBl, 512, 0, W2DTh, W2DTl, nullptr, nullptr,
                                        512, 0, WPh, nullptr, nullptr, nullptr, 512, 0,
                                        512, nullptr, nullptr, 0, CDESC, 0, 2, 0, 0);
    }
    // launch 3: stage 1: TT = ReLU(X @ W1C^T /32 + b1c), 1-pass, hi-only out
    {
        dim3 g(8, 64, 1);
        gemm_mma<1><<<g, 256, SMEMSZ>>>(Xh, nullptr, 1024, 0, W1Ch, nullptr, nullptr, nullptr,
                                        1024, 0, TTh, nullptr, nullptr, nullptr, 1024, 0,
                                        1024, b1c, nullptr, 1, CDESC, 1, 2, 0, 0);
    }
    // launch 4: stage 2 merged, 1-pass (z=0: head -> hi only; z=1: depW -> hi+lo)
    {
        dim3 g(4, 64, 2);
        gemm_mma<1><<<g, 256, SMEMSZ>>>(TTh, nullptr, 1024, 0,
                                        W2Hh, nullptr, WPh, nullptr, 512, 0,
                                        HDh, nullptr, DWh, DWl, 512, 0,
                                        512, b2h_p, bpr, 1, CDESC, 0, 2, 1, 1);
    }
    // launch 5: final batched, 2-pass: out[b] = headh[b] @ (DWh+DWl)[b]^T + bb
    {
        dim3 g(4, 4, 16);
        const long long sAB = 512LL * 512;
        gemm_mma<2><<<g, 256, SMEMSZ>>>(HDh, nullptr, 512, sAB, DWh, DWl, nullptr, nullptr,
                                        512, sAB, out, nullptr, nullptr, nullptr, 512, sAB,
                                        512, bb, nullptr, 2, 1.0f, 0, 0, 0, 0);
    }
}

// round 14
// speedup vs baseline: 5.1611x; 1.1228x over previous
#include <cuda_runtime.h>
#include <cuda_fp16.h>
#include <cstdint>

// BiaffineAttention  B=16, S=512, H=1024, A=500 (padded to 512)
// GEMMs via mma.sync fp16 (m16n8k16), fp32 accum, 3-stage cp.async pipeline.
// Weights pre-scaled by 32, descaled in epilogue (fp16-lo limbs stay normal).
//   TT   = ReLU(X @ [w1h;w1d]^T + b1c)   1-pass -> fp16 hi
//   W'   = Wb @ w2d (3-pass, hi store) ; b' = Wb @ b2d
//   head = TT[:, :512] @ w2h^T + b2h     1-pass -> fp16 hi   (z=0)
//   depW = TT[:, 512:] @ W'^T + b'       1-pass -> fp16 hi   (z=1)
//   out[b] = head[b] @ depW[b]^T + bb    1-pass (fp32 out)

// ============================ PTX helpers ============================
__device__ __forceinline__ uint32_t smem_u32(const void* p) {
    uint32_t a;
    asm("{ .reg .u64 t; cvta.to.shared.u64 t, %1; cvt.u32.u64 %0, t; }"
        : "=r"(a) : "l"(p));
    return a;
}

__device__ __forceinline__ void ldsm4(uint32_t* r, uint32_t addr) {
    asm volatile("ldmatrix.sync.aligned.m8n8.x4.shared.b16 {%0,%1,%2,%3}, [%4];"
        : "=r"(r[0]), "=r"(r[1]), "=r"(r[2]), "=r"(r[3]) : "r"(addr));
}

__device__ __forceinline__ void mma_f16(float* c, const uint32_t* a,
                                        uint32_t b0, uint32_t b1) {
    asm volatile("mma.sync.aligned.m16n8k16.row.col.f32.f16.f16.f32 "
        "{%0,%1,%2,%3}, {%4,%5,%6,%7}, {%8,%9}, {%0,%1,%2,%3};"
        : "+f"(c[0]), "+f"(c[1]), "+f"(c[2]), "+f"(c[3])
        : "r"(a[0]), "r"(a[1]), "r"(a[2]), "r"(a[3]), "r"(b0), "r"(b1));
}

#define CP16(s, g) \
    asm volatile("cp.async.cg.shared.global [%0], [%1], 16;" :: "r"(s), "l"(g))
#define CP_COMMIT() asm volatile("cp.async.commit_group;" ::: "memory")
#define CP_WAIT0()  asm volatile("cp.async.wait_group 0;" ::: "memory")
#define CP_WAIT1()  asm volatile("cp.async.wait_group 1;" ::: "memory")

// ============================ scratch ============================
static constexpr long long EL_X   = 8192LL * 1024;
static constexpr long long EL_W1C = 1024LL * 1024;
static constexpr long long EL_S   = 512LL * 512;
static constexpr long long EL_TT  = 8192LL * 1024;
static constexpr long long EL_ACT = 8192LL * 512;

static constexpr long long O_XH     = 0;
static constexpr long long O_W1C_H  = O_XH + EL_X;
static constexpr long long O_W2H_H  = O_W1C_H + EL_W1C;
static constexpr long long O_WB_H   = O_W2H_H + EL_S;
static constexpr long long O_WB_L   = O_WB_H + EL_S;
static constexpr long long O_W2DT_H = O_WB_L + EL_S;
static constexpr long long O_W2DT_L = O_W2DT_H + EL_S;
static constexpr long long O_WP_H   = O_W2DT_L + EL_S;
static constexpr long long O_TT_H   = O_WP_H + EL_S;
static constexpr long long O_HD_H   = O_TT_H + EL_TT;
static constexpr long long O_DW_H   = O_HD_H + EL_ACT;
static constexpr long long H_TOTAL  = O_DW_H + EL_ACT;

__device__ __align__(1024) __half g_h[H_TOTAL];
__device__ __align__(1024) float g_vec[3 * 1024];   // b1c[1024], b2h_p[512], bpr[512]

// ============================ prep kernels ============================
__device__ __forceinline__ void split_h(__half* hi, __half* lo, long long i, float v)
{
    __half h = __float2half_rn(v);
    hi[i] = h;
    lo[i] = __float2half_rn(v - __half2float(h));
}

__global__ void conv_x(const float* __restrict__ X, __half* __restrict__ Xh)
{
    long long idx = ((long long)blockIdx.x * blockDim.x + threadIdx.x) * 4;
    float4 v = *(const float4*)(X + idx);
    __half h[4] = {__float2half_rn(v.x), __float2half_rn(v.y),
                   __float2half_rn(v.z), __float2half_rn(v.w)};
    *(uint2*)(Xh + idx) = *(uint2*)h;
}

#define WSCALE 32.0f
#define CDESC  0.03125f

__global__ void prep_weights(
    const float* __restrict__ w1h, const float* __restrict__ w1d,
    const float* __restrict__ w2h, const float* __restrict__ Wb,
    const float* __restrict__ w2d,
    const float* __restrict__ b1h, const float* __restrict__ b1d,
    const float* __restrict__ b2h, const float* __restrict__ b2d,
    __half* __restrict__ W1Ch,
    __half* __restrict__ W2Hh,
    __half* __restrict__ WBh,  __half* __restrict__ WBl,
    __half* __restrict__ W2DTh,__half* __restrict__ W2DTl,
    float* __restrict__ b1c, float* __restrict__ b2h_p, float* __restrict__ bpr)
{
    const int bx = blockIdx.x;
    const int tid = threadIdx.x;

    if (bx < 4096) {
        const int half_ = bx >> 11;
        const long long e = ((long long)(bx & 2047)) * 256 + tid;
        const int r = (int)(e >> 10);
        const float* src = half_ ? w1d : w1h;
        float v = (r < 500) ? WSCALE * src[(long long)r * 1024 + (e & 1023)] : 0.0f;
        W1Ch[(long long)half_ * 512 * 1024 + e] = __float2half_rn(v);
    } else if (bx < 7168) {
        const int sec = (bx - 4096) >> 10;
        const long long e = ((long long)((bx - 4096) & 1023)) * 256 + tid;
        const int r = (int)(e >> 9), c = (int)(e & 511);
        float v = 0.0f;
        if (sec == 0) {
            if (r < 500 && c < 500) v = WSCALE * w2h[r * 500 + c];
            W2Hh[e] = __float2half_rn(v);
        } else if (sec == 1) {
            if (r < 500 && c < 500) v = WSCALE * Wb[r * 500 + c];
            split_h(WBh, WBl, e, v);
        } else {
            if (r < 500 && c < 500) v = WSCALE * w2d[c * 500 + r];
            split_h(W2DTh, W2DTl, e, v);
        }
    } else if (bx < 7680) {
        const int j = bx - 7168;
        __shared__ float red[8];
        float s = 0.0f;
        if (j < 500)
            for (int a = tid; a < 500; a += 256) s += Wb[j * 500 + a] * b2d[a];
#pragma unroll
        for (int o = 16; o > 0; o >>= 1) s += __shfl_down_sync(0xffffffffu, s, o);
        if ((tid & 31) == 0) red[tid >> 5] = s;
        __syncthreads();
        if (tid == 0) {
            float t = 0.0f;
#pragma unroll
            for (int q = 0; q < 8; q++) t += red[q];
            bpr[j] = (j < 500) ? t : 0.0f;
        }
    } else {
        const int e = (bx - 7680) * 256 + tid;
        if (e < 1024) {
            const int c = e & 511;
            b1c[e] = (c < 500) ? ((e < 512) ? b1h[c] : b1d[c]) : 0.0f;
        } else if (e < 1536) {
            const int c = e - 1024;
            b2h_p[c] = (c < 500) ? b2h[c] : 0.0f;
        }
    }
}

// ============================ main GEMM ============================
// C[M,N] = A[M,K] @ B[N,K]^T.
// PASSES=1: Ahi@Bhi.  PASSES=2: + Ahi@Blo.  PASSES=3: + Alo@Bhi.
// CTA 128x128, 8 warps (4Mx2N), warp 32x64, BK=32, 3-stage cp.async ring,
// ONE __syncthreads per k-iter.
// splitOut: 0=fp32, 2=fp16 hi only. dual: z picks operand set.
#define SROW 40
#define TILEB (128 * SROW * 2)   // 10240 B per matrix tile

template<int PASSES>
struct Lay {
    static constexpr int NT = (PASSES == 1) ? 2 : (PASSES == 2) ? 3 : 4;
    static constexpr int STAGEB = NT * TILEB;
    static constexpr int AH = 0;
    static constexpr int AL = (PASSES == 3) ? TILEB : 0;
    static constexpr int BH = (PASSES == 3) ? 2 * TILEB : TILEB;
    static constexpr int BL = (PASSES == 2) ? 2 * TILEB : 3 * TILEB;
    static constexpr int SMEM = 3 * STAGEB;
};

template<int PASSES>
__device__ __forceinline__ void issue_tile(
    uint32_t sbase, const char* Ah, const char* Al, const char* Bh, const char* Bl,
    int lda, int ldb, int row0, int col0, int k0, int tid)
{
    using L = Lay<PASSES>;
#pragma unroll
    for (int i = 0; i < 2; i++) {
        const int pos = tid + i * 256;
        const int r = pos >> 2, ch = pos & 3;
        const uint32_t so = (uint32_t)(r * (SROW * 2) + ch * 16);
        const size_t gA = ((size_t)(row0 + r) * lda + k0 + ch * 8) * 2;
        const size_t gB = ((size_t)(col0 + r) * ldb + k0 + ch * 8) * 2;
        CP16(sbase + L::AH + so, Ah + gA);
        if (PASSES == 3) CP16(sbase + L::AL + so, Al + gA);
        CP16(sbase + L::BH + so, Bh + gB);
        if (PASSES >= 2) CP16(sbase + L::BL + so, Bl + gB);
    }
}

template<int PASSES>
__global__ void __launch_bounds__(256, 2) gemm_mma(
    const __half* __restrict__ Ahi, const __half* __restrict__ Alo,
    int lda, long long sA,
    const __half* __restrict__ Bhi, const __half* __restrict__ Blo,
    const __half* __restrict__ Bhi2, int ldb, long long sB,
    void* __restrict__ Cout, void* __restrict__ CoutB,
    int ldc, long long sC,
    int K, const float* __restrict__ bias, const float* __restrict__ bias2,
    int biasMode, float cScale, int doRelu, int splitOut, int dual)
{
    using L = Lay<PASSES>;
    extern __shared__ char smem[];
    const uint32_t sb = smem_u32(smem);
    const int tid  = threadIdx.x;
    const int lane = tid & 31;
    const int wid  = tid >> 5;
    const int wm   = wid & 3;
    const int wn   = wid >> 2;
    const int row0 = blockIdx.y * 128;
    const int col0 = blockIdx.x * 128;

    const int z = blockIdx.z;
    const char *Ah, *Al, *Bh, *Bl;
    const float* bvp = bias;
    void *Co = Cout;
    if (dual && z) {
        Ah = (const char*)(Ahi + 512);
        Al = nullptr;
        Bh = (const char*)Bhi2;  Bl = nullptr;
        bvp = bias2;  Co = CoutB;
    } else {
        Ah = (const char*)(Ahi + (long long)z * sA);
        Al = (const char*)(Alo ? Alo + (long long)z * sA : nullptr);
        Bh = (const char*)(Bhi + (long long)z * sB);
        Bl = (const char*)(Blo ? Blo + (long long)z * sB : nullptr);
    }

    float acc[2][8][4];
#pragma unroll
    for (int mt = 0; mt < 2; mt++)
#pragma unroll
        for (int nt = 0; nt < 8; nt++)
#pragma unroll
            for (int q = 0; q < 4; q++) acc[mt][nt][q] = 0.0f;

    const int frow = (lane & 7) | (((lane >> 3) & 1) << 3);
    const int fkc  = (lane >> 4) * 8;

    const int T = K / 32;   // >= 16 always
    issue_tile<PASSES>(sb + 0 * L::STAGEB, Ah, Al, Bh, Bl, lda, ldb, row0, col0, 0, tid);
    CP_COMMIT();
    issue_tile<PASSES>(sb + 1 * L::STAGEB, Ah, Al, Bh, Bl, lda, ldb, row0, col0, 32, tid);
    CP_COMMIT();

    int sidx = 0;
    for (int t = 0; t < T; ++t) {
        if (t + 1 < T) { CP_WAIT1(); } else { CP_WAIT0(); }
        __syncthreads();

        const uint32_t st = sb + sidx * L::STAGEB;
#pragma unroll
        for (int kh = 0; kh < 2; ++kh) {
            const int kb = kh * 16 + fkc;
            if (PASSES == 1) {
                // fragment burst: all operands loaded, then 16 independent MMAs
                uint32_t ah[2][4], bh4[4][4];
#pragma unroll
                for (int mt = 0; mt < 2; mt++)
                    ldsm4(ah[mt], st + L::AH +
                          (uint32_t)(((wm * 32 + mt * 16 + frow) * SROW + kb) * 2));
#pragma unroll
                for (int bt = 0; bt < 4; bt++)
                    ldsm4(bh4[bt], st + L::BH +
                          (uint32_t)(((wn * 64 + bt * 16 + frow) * SROW + kb) * 2));
#pragma unroll
                for (int bt = 0; bt < 4; bt++)
#pragma unroll
                    for (int p = 0; p < 2; p++)
#pragma unroll
                        for (int mt = 0; mt < 2; mt++)
                            mma_f16(acc[mt][bt * 2 + p], ah[mt],
                                    bh4[bt][p], bh4[bt][p + 2]);
            } else {
                uint32_t ah[2][4], al[2][4];
#pragma unroll
                for (int mt = 0; mt < 2; mt++) {
                    const uint32_t off =
                        (uint32_t)(((wm * 32 + mt * 16 + frow) * SROW + kb) * 2);
                    ldsm4(ah[mt], st + L::AH + off);
                    if (PASSES == 3) ldsm4(al[mt], st + L::AL + off);
                }
#pragma unroll
                for (int bt = 0; bt < 4; bt++) {
                    uint32_t bh[4], bl[4];
                    const uint32_t off =
                        (uint32_t)(((wn * 64 + bt * 16 + frow) * SROW + kb) * 2);
                    ldsm4(bh, st + L::BH + off);
                    ldsm4(bl, st + L::BL + off);
#pragma unroll
                    for (int mt = 0; mt < 2; mt++)
#pragma unroll
                        for (int p = 0; p < 2; p++)
                            mma_f16(acc[mt][bt * 2 + p], ah[mt], bh[p], bh[p + 2]);
#pragma unroll
                    for (int mt = 0; mt < 2; mt++)
#pragma unroll
                        for (int p = 0; p < 2; p++)
                            mma_f16(acc[mt][bt * 2 + p], ah[mt], bl[p], bl[p + 2]);
                    if (PASSES == 3) {
#pragma unroll
                        for (int mt = 0; mt < 2; mt++)
#pragma unroll
                            for (int p = 0; p < 2; p++)
                                mma_f16(acc[mt][bt * 2 + p], al[mt], bh[p], bh[p + 2]);
                    }
                }
            }
        }

        if (t + 2 < T) {
            int widx = sidx + 2; if (widx >= 3) widx -= 3;
            issue_tile<PASSES>(sb + widx * L::STAGEB, Ah, Al, Bh, Bl,
                               lda, ldb, row0, col0, (t + 2) * 32, tid);
            CP_COMMIT();
        }
        sidx = (sidx + 1 == 3) ? 0 : sidx + 1;
    }

    // ============================ epilogue ============================
    const int cbytes = (splitOut == 0) ? 4 : 2;
    char* Cb = (char*)Co + (dual ? 0 : (size_t)z * sC * cbytes);

#pragma unroll
    for (int mt = 0; mt < 2; mt++) {
        const long long r0 = row0 + wm * 32 + mt * 16 + (lane >> 2);
#pragma unroll
        for (int nt = 0; nt < 8; nt++) {
            const int c0 = col0 + wn * 64 + nt * 8 + (lane & 3) * 2;
            float b0 = 0.0f, b1 = 0.0f;
            if (biasMode == 1)      { b0 = bvp[c0]; b1 = bvp[c0 + 1]; }
            else if (biasMode == 2) { b0 = bvp[0];  b1 = bvp[0]; }

            float v00 = fmaf(acc[mt][nt][0], cScale, b0);
            float v01 = fmaf(acc[mt][nt][1], cScale, b1);
            float v10 = fmaf(acc[mt][nt][2], cScale, b0);
            float v11 = fmaf(acc[mt][nt][3], cScale, b1);
            if (doRelu) {
                v00 = fmaxf(v00, 0.0f); v01 = fmaxf(v01, 0.0f);
                v10 = fmaxf(v10, 0.0f); v11 = fmaxf(v11, 0.0f);
            }

            if (splitOut == 0) {
                *(float2*)(Cb + (r0 * ldc + c0) * 4)       = make_float2(v00, v01);
                *(float2*)(Cb + ((r0 + 8) * ldc + c0) * 4) = make_float2(v10, v11);
            } else {
                __half h00 = __float2half_rn(v00), h01 = __float2half_rn(v01);
                __half h10 = __float2half_rn(v10), h11 = __float2half_rn(v11);
                uint32_t ph0 = (uint32_t)__half_as_ushort(h00) |
                               ((uint32_t)__half_as_ushort(h01) << 16);
                uint32_t ph1 = (uint32_t)__half_as_ushort(h10) |
                               ((uint32_t)__half_as_ushort(h11) << 16);
                *(uint32_t*)(Cb + (r0 * ldc + c0) * 2)       = ph0;
                *(uint32_t*)(Cb + ((r0 + 8) * ldc + c0) * 2) = ph1;
            }
        }
    }
}

// ============================ launch ============================
extern "C" void kernel_launch(void* const* d_in, const int* in_sizes, int n_in,
                              void* d_out, int out_size)
{
    const float* X   = (const float*)d_in[0];
    const float* w1h = (const float*)d_in[1];
    const float* b1h = (const float*)d_in[2];
    const float* w2h = (const float*)d_in[3];
    const float* b2h = (const float*)d_in[4];
    const float* w1d = (const float*)d_in[5];
    const float* b1d = (const float*)d_in[6];
    const float* w2d = (const float*)d_in[7];
    const float* b2d = (const float*)d_in[8];
    const float* Wb  = (const float*)d_in[9];
    const float* bb  = (const float*)d_in[10];
    float* out = (float*)d_out;

    __half* hb = nullptr;
    cudaGetSymbolAddress((void**)&hb, g_h);
    float* vecs = nullptr;
    cudaGetSymbolAddress((void**)&vecs, g_vec);

    __half *Xh    = hb + O_XH;
    __half *W1Ch  = hb + O_W1C_H;
    __half *W2Hh  = hb + O_W2H_H;
    __half *WBh   = hb + O_WB_H,   *WBl   = hb + O_WB_L;
    __half *W2DTh = hb + O_W2DT_H, *W2DTl = hb + O_W2DT_L;
    __half *WPh   = hb + O_WP_H;
    __half *TTh   = hb + O_TT_H;
    __half *HDh   = hb + O_HD_H;
    __half *DWh   = hb + O_DW_H;

    float* b1c   = vecs + 0 * 1024;
    float* b2h_p = vecs + 1 * 1024;
    float* bpr   = vecs + 2 * 1024;

    cudaFuncSetAttribute(gemm_mma<1>, cudaFuncAttributeMaxDynamicSharedMemorySize,
                         Lay<1>::SMEM);
    cudaFuncSetAttribute(gemm_mma<3>, cudaFuncAttributeMaxDynamicSharedMemorySize,
                         Lay<3>::SMEM);

    // launch 0: X -> fp16
    conv_x<<<(unsigned)(EL_X / 4 / 256), 256>>>(X, Xh);
    // launch 1: weight prep (scaled x32) + biases
    prep_weights<<<7686, 256>>>(w1h, w1d, w2h, Wb, w2d, b1h, b1d, b2h, b2d,
                                W1Ch, W2Hh, WBh, WBl, W2DTh, W2DTl,
                                b1c, b2h_p, bpr);

    // launch 2: W' = Wb @ w2d (3-pass, hi-only store of 32*W')
    {
        dim3 g(4, 4, 1);
        gemm_mma<3><<<g, 256, Lay<3>::SMEM>>>(
            WBh, WBl, 512, 0, W2DTh, W2DTl, nullptr, 512, 0,
            WPh, nullptr, 512, 0, 512, nullptr, nullptr, 0, CDESC, 0, 2, 0);
    }
    // launch 3: stage 1: TT = ReLU(X @ W1C^T /32 + b1c), 1-pass, hi out
    {
        dim3 g(8, 64, 1);
        gemm_mma<1><<<g, 256, Lay<1>::SMEM>>>(
            Xh, nullptr, 1024, 0, W1Ch, nullptr, nullptr, 1024, 0,
            TTh, nullptr, 1024, 0, 1024, b1c, nullptr, 1, CDESC, 1, 2, 0);
    }
    // launch 4: stage 2 merged, 1-pass (z=0: head -> hi; z=1: depW -> hi)
    {
        dim3 g(4, 64, 2);
        gemm_mma<1><<<g, 256, Lay<1>::SMEM>>>(
            TTh, nullptr, 1024, 0, W2Hh, nullptr, WPh, 512, 0,
            HDh, DWh, 512, 0, 512, b2h_p, bpr, 1, CDESC, 0, 2, 1);
    }
    // launch 5: final batched, 1-pass: out[b] = head[b] @ depW[b]^T + bb (fp32)
    {
        dim3 g(4, 4, 16);
        const long long sAB = 512LL * 512;
        gemm_mma<1><<<g, 256, Lay<1>::SMEM>>>(
            HDh, nullptr, 512, sAB, DWh, nullptr, nullptr, 512, sAB,
            out, nullptr, 512, sAB, 512, bb, nullptr, 2, 1.0f, 0, 0, 0);
    }
}